// round 1
// baseline (speedup 1.0000x reference)
#include <cuda_runtime.h>
#include <math.h>

// Problem constants
#define B_SZ   1024
#define NF_    128
#define D_     64
#define H_     8
#define MCOLS  4096
#define LN_EPS 1e-5f

// Scratch (static device allocations are the sanctioned workaround)
__device__ float g_Fi[(size_t)B_SZ * NF_ * D_];   // [b][f][d]  post-LN features, 33.5 MB
__device__ float g_qt[(size_t)B_SZ * H_ * D_];    // [b][h][d'] = wk_h @ Q_bh,     2 MB

__device__ __forceinline__ float gelu_exact(float x) {
    return 0.5f * x * (1.0f + erff(x * 0.70710678118654752f));
}

// ---------------------------------------------------------------------------
// Kernel Q: Q = command @ wq  ([1024,128]@[128,512]), then
//           qt[b,h,d'] = sum_d wk[d', h*64+d] * Q[b, h*64+d]
// ---------------------------------------------------------------------------
__global__ __launch_bounds__(128) void q_kernel(
    const float* __restrict__ command,
    const float* __restrict__ wq,
    const float* __restrict__ wk)
{
    __shared__ float cs[128];
    __shared__ float Qs[512];
    __shared__ float Wb[64][68];   // wk block for one h, padded

    const int tid = threadIdx.x;
    const int b   = blockIdx.x;

    cs[tid] = command[(size_t)b * 128 + tid];
    __syncthreads();

    #pragma unroll
    for (int o = 0; o < 4; o++) {
        const int j = tid + o * 128;
        float s = 0.f;
        #pragma unroll 8
        for (int e = 0; e < 128; e++)
            s = fmaf(cs[e], wq[(size_t)e * 512 + j], s);
        Qs[j] = s;
    }
    __syncthreads();

    for (int h = 0; h < 8; h++) {
        // load wk[:, h*64 : h*64+64] -> Wb[64][64]
        const int dp = tid >> 1, half = tid & 1;
        const float* src = wk + (size_t)dp * 512 + h * 64 + half * 32;
        #pragma unroll
        for (int v = 0; v < 8; v++) {
            float4 w = *(const float4*)(src + v * 4);
            *(float4*)&Wb[dp][half * 32 + v * 4] = w;
        }
        __syncthreads();
        if (tid < 64) {
            float s = 0.f;
            #pragma unroll 8
            for (int d = 0; d < 64; d++)
                s = fmaf(Wb[tid][d], Qs[h * 64 + d], s);
            g_qt[((size_t)b * 8 + h) * 64 + tid] = s;
        }
        __syncthreads();
    }
}

// ---------------------------------------------------------------------------
// Kernel A: C = gelu(Afeat @ W) for a 128x64 tile, then LayerNorm over the
// 64-wide column chunk (which is exactly one f-group of Fi), write to g_Fi.
//   grid.x = 64 (column chunk == f index within half), grid.y = 8 (row tiles)
//   fbase = 0 for feature@wz half, 64 for hidden@wh half
// ---------------------------------------------------------------------------
__global__ __launch_bounds__(256) void proj_gelu_ln_kernel(
    const float* __restrict__ A,
    const float* __restrict__ W,
    const float* __restrict__ gamma,
    const float* __restrict__ beta,
    int Kdim, int fbase)
{
    __shared__ float As[16][132];   // A tile transposed: As[k][i]
    __shared__ float Bs[16][64];    // W tile: Bs[k][j]

    const int tid   = threadIdx.x;
    const int chunk = blockIdx.x;        // 0..63
    const int bm    = blockIdx.y * 128;
    const int cn    = chunk * 64;

    const int ty  = tid >> 4;            // 0..15 -> 8-row group
    const int txx = tid & 15;            // 0..15 -> 4-col group

    float acc[8][4];
    #pragma unroll
    for (int r = 0; r < 8; r++)
        #pragma unroll
        for (int c = 0; c < 4; c++) acc[r][c] = 0.f;

    const int arow = tid >> 2;   // 0..63
    const int avec = tid & 3;    // 0..3
    const int brow = tid >> 4;   // 0..15
    const int bvec = tid & 15;   // 0..15

    for (int kt = 0; kt < Kdim; kt += 16) {
        // A tile 128x16, transposed into smem
        #pragma unroll
        for (int it = 0; it < 2; it++) {
            const int i = arow + it * 64;
            float4 a = *(const float4*)(A + (size_t)(bm + i) * Kdim + kt + avec * 4);
            As[avec * 4 + 0][i] = a.x;
            As[avec * 4 + 1][i] = a.y;
            As[avec * 4 + 2][i] = a.z;
            As[avec * 4 + 3][i] = a.w;
        }
        // W tile 16x64
        {
            float4 bv = *(const float4*)(W + (size_t)(kt + brow) * MCOLS + cn + bvec * 4);
            *(float4*)&Bs[brow][bvec * 4] = bv;
        }
        __syncthreads();

        #pragma unroll
        for (int k = 0; k < 16; k++) {
            float4 b0 = *(const float4*)&Bs[k][txx * 4];
            float4 a0 = *(const float4*)&As[k][ty * 8];
            float4 a1 = *(const float4*)&As[k][ty * 8 + 4];
            const float ar[8] = {a0.x, a0.y, a0.z, a0.w, a1.x, a1.y, a1.z, a1.w};
            const float br[4] = {b0.x, b0.y, b0.z, b0.w};
            #pragma unroll
            for (int r = 0; r < 8; r++)
                #pragma unroll
                for (int c = 0; c < 4; c++)
                    acc[r][c] = fmaf(ar[r], br[c], acc[r][c]);
        }
        __syncthreads();
    }

    // Epilogue: exact GELU + LayerNorm over the 64 columns of each row.
    // Row i is held by the 16 threads sharing ty (consecutive lanes within a
    // half-warp) -> shuffle reduction, offsets 8,4,2,1.
    float g[4], bt[4];
    #pragma unroll
    for (int c = 0; c < 4; c++) {
        g[c]  = gamma[txx * 4 + c];
        bt[c] = beta[txx * 4 + c];
    }
    const int f = fbase + chunk;
    #pragma unroll
    for (int r = 0; r < 8; r++) {
        float s = 0.f, sq = 0.f;
        #pragma unroll
        for (int c = 0; c < 4; c++) {
            float v = gelu_exact(acc[r][c]);
            acc[r][c] = v;
            s += v; sq += v * v;
        }
        #pragma unroll
        for (int off = 8; off >= 1; off >>= 1) {
            s  += __shfl_xor_sync(0xffffffffu, s,  off);
            sq += __shfl_xor_sync(0xffffffffu, sq, off);
        }
        const float mu   = s * (1.f / 64.f);
        const float var  = sq * (1.f / 64.f) - mu * mu;
        const float rstd = rsqrtf(var + LN_EPS);
        float4 o;
        o.x = (acc[r][0] - mu) * rstd * g[0] + bt[0];
        o.y = (acc[r][1] - mu) * rstd * g[1] + bt[1];
        o.z = (acc[r][2] - mu) * rstd * g[2] + bt[2];
        o.w = (acc[r][3] - mu) * rstd * g[3] + bt[3];
        const int i = bm + ty * 8 + r;
        *(float4*)(g_Fi + ((size_t)i * NF_ + f) * D_ + txx * 4) = o;
    }
}

// ---------------------------------------------------------------------------
// Kernel B: per (b,h):
//   V[m][d]   = Fi_b[m,:] @ wv[:, h*64+d]          (register GEMM, 128x64x64)
//   mV[m]     = (1/64) sum_d |V[m][d]|              (reduced in-register)
//   logit[m]  = mV[m] * (Fi_b[m,:] . qt_bh) / 8
//   A         = softmax_m(logit)
//   S[d]      = (A^T Fi_b) @ wv_h[:, d]             (V never materialized)
// ---------------------------------------------------------------------------
#define FST_STRIDE 132   // padded row stride for Fst (mult of 4 for float4)

__global__ __launch_bounds__(128) void attn_kernel(
    const float* __restrict__ wv,
    float* __restrict__ out)
{
    extern __shared__ float sm[];
    float* Fst    = sm;                        // [64][FST_STRIDE]  Fi_b transposed
    float* Ws     = Fst + 64 * FST_STRIDE;     // [64][64]          wv_h
    float* logits = Ws + 64 * 64;              // [128]
    float* qts    = logits + 128;              // [64]
    float* mvs    = qts + 64;                  // [128]
    float* rbuf   = mvs + 128;                 // [32]
    float* gvec   = rbuf + 32;                 // [64]

    const int tid = threadIdx.x;
    const int h   = blockIdx.x;
    const int b   = blockIdx.y;

    const float* Fi = g_Fi + (size_t)b * NF_ * D_;

    // Load Fi_b transposed: Fst[d'][m]
    {
        const int m = tid;
        #pragma unroll
        for (int v = 0; v < 16; v++) {
            float4 fv = *(const float4*)(Fi + m * 64 + v * 4);
            Fst[(v * 4 + 0) * FST_STRIDE + m] = fv.x;
            Fst[(v * 4 + 1) * FST_STRIDE + m] = fv.y;
            Fst[(v * 4 + 2) * FST_STRIDE + m] = fv.z;
            Fst[(v * 4 + 3) * FST_STRIDE + m] = fv.w;
        }
    }
    // Load wv_h: Ws[d'][d]
    {
        const int dp = tid >> 1, half = tid & 1;
        const float* src = wv + (size_t)dp * 512 + h * 64 + half * 32;
        float* dst = Ws + dp * 64 + half * 32;
        #pragma unroll
        for (int v = 0; v < 8; v++)
            *(float4*)(dst + v * 4) = *(const float4*)(src + v * 4);
    }
    if (tid < 64) qts[tid] = g_qt[((size_t)b * 8 + h) * 64 + tid];
    __syncthreads();

    // Register GEMM: rows m = tm*8+r, cols d = tdq*8+c, K = 64
    const int tm = tid >> 3;   // 0..15
    const int tdq = tid & 7;   // 0..7
    float acc[8][8];
    #pragma unroll
    for (int r = 0; r < 8; r++)
        #pragma unroll
        for (int c = 0; c < 8; c++) acc[r][c] = 0.f;

    #pragma unroll 4
    for (int k = 0; k < 64; k++) {
        float4 f0 = *(const float4*)&Fst[k * FST_STRIDE + tm * 8];
        float4 f1 = *(const float4*)&Fst[k * FST_STRIDE + tm * 8 + 4];
        float4 w0 = *(const float4*)&Ws[k * 64 + tdq * 8];
        float4 w1 = *(const float4*)&Ws[k * 64 + tdq * 8 + 4];
        const float fr[8] = {f0.x, f0.y, f0.z, f0.w, f1.x, f1.y, f1.z, f1.w};
        const float wr[8] = {w0.x, w0.y, w0.z, w0.w, w1.x, w1.y, w1.z, w1.w};
        #pragma unroll
        for (int r = 0; r < 8; r++)
            #pragma unroll
            for (int c = 0; c < 8; c++)
                acc[r][c] = fmaf(fr[r], wr[c], acc[r][c]);
    }

    // mV: abs-sum across d (8 local cols + shuffle over the 8 tdq lanes)
    #pragma unroll
    for (int r = 0; r < 8; r++) {
        float s = 0.f;
        #pragma unroll
        for (int c = 0; c < 8; c++) s += fabsf(acc[r][c]);
        #pragma unroll
        for (int off = 4; off >= 1; off >>= 1)
            s += __shfl_xor_sync(0xffffffffu, s, off, 8);
        if (tdq == r) mvs[tm * 8 + r] = s * (1.f / 64.f);
    }
    __syncthreads();

    // logits[m] = mV[m] * (Fi[m,:].qt) / 8
    {
        const int m = tid;
        float s = 0.f;
        #pragma unroll 8
        for (int k = 0; k < 64; k++)
            s = fmaf(Fst[k * FST_STRIDE + m], qts[k], s);
        logits[m] = mvs[m] * s * 0.125f;
    }
    __syncthreads();

    // Softmax over 128 (4 warps)
    const float lg = logits[tid];
    float mx = lg;
    #pragma unroll
    for (int off = 16; off >= 1; off >>= 1)
        mx = fmaxf(mx, __shfl_xor_sync(0xffffffffu, mx, off));
    if ((tid & 31) == 0) rbuf[tid >> 5] = mx;
    __syncthreads();
    mx = fmaxf(fmaxf(rbuf[0], rbuf[1]), fmaxf(rbuf[2], rbuf[3]));

    const float e = expf(lg - mx);
    float se = e;
    #pragma unroll
    for (int off = 16; off >= 1; off >>= 1)
        se += __shfl_xor_sync(0xffffffffu, se, off);
    if ((tid & 31) == 0) rbuf[4 + (tid >> 5)] = se;
    logits[tid] = e;   // only thread tid reads/writes logits[tid] here
    __syncthreads();
    const float inv = 1.f / (rbuf[4] + rbuf[5] + rbuf[6] + rbuf[7]);

    // gvec[d'] = sum_m A[m] * Fi[m][d']
    if (tid < 64) {
        float s = 0.f;
        #pragma unroll 8
        for (int m = 0; m < 128; m++)
            s = fmaf(logits[m], Fst[tid * FST_STRIDE + m], s);
        gvec[tid] = s * inv;
    }
    __syncthreads();

    // S[d] = sum_{d'} gvec[d'] * wv_h[d'][d]
    if (tid < 64) {
        float s = 0.f;
        #pragma unroll 8
        for (int k = 0; k < 64; k++)
            s = fmaf(gvec[k], Ws[k * 64 + tid], s);
        out[((size_t)b * 8 + h) * 64 + tid] = s;
    }
}

// ---------------------------------------------------------------------------
// Launch
// ---------------------------------------------------------------------------
extern "C" void kernel_launch(void* const* d_in, const int* in_sizes, int n_in,
                              void* d_out, int out_size)
{
    const float* feature  = (const float*)d_in[0];
    const float* hidden   = (const float*)d_in[1];
    const float* command  = (const float*)d_in[2];
    const float* wz       = (const float*)d_in[3];
    const float* wh       = (const float*)d_in[4];
    const float* wq       = (const float*)d_in[5];
    const float* wk       = (const float*)d_in[6];
    const float* wv       = (const float*)d_in[7];
    const float* ln_gamma = (const float*)d_in[8];
    const float* ln_beta  = (const float*)d_in[9];
    float* out = (float*)d_out;

    const int attn_smem = (64 * FST_STRIDE + 64 * 64 + 128 + 64 + 128 + 32 + 64) * 4;
    cudaFuncSetAttribute(attn_kernel, cudaFuncAttributeMaxDynamicSharedMemorySize, attn_smem);

    q_kernel<<<B_SZ, 128>>>(command, wq, wk);

    dim3 gA(64, 8);
    proj_gelu_ln_kernel<<<gA, 256>>>(feature, wz, ln_gamma, ln_beta, 2048, 0);
    proj_gelu_ln_kernel<<<gA, 256>>>(hidden,  wh, ln_gamma, ln_beta, 1024, 64);

    dim3 gB(H_, B_SZ);
    attn_kernel<<<gB, 128, attn_smem>>>(wv, out);
}

// round 6
// speedup vs baseline: 1.5348x; 1.5348x over previous
#include <cuda_runtime.h>
#include <cuda_bf16.h>
#include <mma.h>
#include <cstdint>
#include <stdint.h>
#include <math.h>

using namespace nvcuda;

// Problem constants
#define B_SZ   1024
#define NF_    128
#define D_     64
#define H_     8
#define MCOLS  4096
#define LN_EPS 1e-5f

// ---------------------------------------------------------------------------
// Scratch (__device__ globals; allocation APIs are forbidden)
// ---------------------------------------------------------------------------
__device__ float g_Fi[(size_t)B_SZ * NF_ * D_];   // [b][f][d] post-LN features
__device__ float g_qt[(size_t)B_SZ * H_ * D_];    // [b][h][d'] = wk_h @ Q_bh

// bf16 split planes (hi + lo) for tensor-core GEMMs
__device__ __nv_bfloat16 g_fh[2097152], g_fl[2097152];   // feature 1024x2048
__device__ __nv_bfloat16 g_hh[1048576], g_hl[1048576];   // hidden  1024x1024
__device__ __nv_bfloat16 g_wzh[8388608], g_wzl[8388608]; // wz      2048x4096
__device__ __nv_bfloat16 g_whh[4194304], g_whl[4194304]; // wh      1024x4096

__device__ __forceinline__ float gelu_exact(float x) {
    return 0.5f * x * (1.0f + erff(x * 0.70710678118654752f));
}

__device__ __forceinline__ void cp_async16(uint32_t dst, const void* src) {
    asm volatile("cp.async.cg.shared.global [%0], [%1], 16;\n"
                 :: "r"(dst), "l"(__cvta_generic_to_global(src)));
}

// ---------------------------------------------------------------------------
// Convert fp32 array -> bf16 hi/lo planes (split precision)
// ---------------------------------------------------------------------------
__global__ __launch_bounds__(256) void convert_kernel(const float* __restrict__ src,
                                                      int sel, int n4)
{
    __nv_bfloat16 *hi, *lo;
    switch (sel) {
        case 0:  hi = g_fh;  lo = g_fl;  break;
        case 1:  hi = g_hh;  lo = g_hl;  break;
        case 2:  hi = g_wzh; lo = g_wzl; break;
        default: hi = g_whh; lo = g_whl; break;
    }
    const int stride = gridDim.x * blockDim.x;
    for (int j = blockIdx.x * blockDim.x + threadIdx.x; j < n4; j += stride) {
        float4 v = ((const float4*)src)[j];
        __nv_bfloat16 h0 = __float2bfloat16(v.x);
        __nv_bfloat16 h1 = __float2bfloat16(v.y);
        __nv_bfloat16 h2 = __float2bfloat16(v.z);
        __nv_bfloat16 h3 = __float2bfloat16(v.w);
        __nv_bfloat16 l0 = __float2bfloat16(v.x - __bfloat162float(h0));
        __nv_bfloat16 l1 = __float2bfloat16(v.y - __bfloat162float(h1));
        __nv_bfloat16 l2 = __float2bfloat16(v.z - __bfloat162float(h2));
        __nv_bfloat16 l3 = __float2bfloat16(v.w - __bfloat162float(h3));
        ((__nv_bfloat162*)hi)[j * 2 + 0] = __nv_bfloat162(h0, h1);
        ((__nv_bfloat162*)hi)[j * 2 + 1] = __nv_bfloat162(h2, h3);
        ((__nv_bfloat162*)lo)[j * 2 + 0] = __nv_bfloat162(l0, l1);
        ((__nv_bfloat162*)lo)[j * 2 + 1] = __nv_bfloat162(l2, l3);
    }
}

// ---------------------------------------------------------------------------
// Kernel Q: Q = command @ wq, then qt[b,h,d'] = sum_d wk[d', h*64+d] * Q[b,h*64+d]
// ---------------------------------------------------------------------------
__global__ __launch_bounds__(128) void q_kernel(
    const float* __restrict__ command,
    const float* __restrict__ wq,
    const float* __restrict__ wk)
{
    __shared__ float cs[128];
    __shared__ float Qs[512];
    __shared__ float Wb[64][68];

    const int tid = threadIdx.x;
    const int b   = blockIdx.x;

    cs[tid] = command[(size_t)b * 128 + tid];
    __syncthreads();

    #pragma unroll
    for (int o = 0; o < 4; o++) {
        const int j = tid + o * 128;
        float s = 0.f;
        #pragma unroll 8
        for (int e = 0; e < 128; e++)
            s = fmaf(cs[e], wq[(size_t)e * 512 + j], s);
        Qs[j] = s;
    }
    __syncthreads();

    for (int h = 0; h < 8; h++) {
        const int dp = tid >> 1, half = tid & 1;
        const float* src = wk + (size_t)dp * 512 + h * 64 + half * 32;
        #pragma unroll
        for (int v = 0; v < 8; v++) {
            float4 w = *(const float4*)(src + v * 4);
            *(float4*)&Wb[dp][half * 32 + v * 4] = w;
        }
        __syncthreads();
        if (tid < 64) {
            float s = 0.f;
            #pragma unroll 8
            for (int d = 0; d < 64; d++)
                s = fmaf(Wb[tid][d], Qs[h * 64 + d], s);
            g_qt[((size_t)b * 8 + h) * 64 + tid] = s;
        }
        __syncthreads();
    }
}

// ---------------------------------------------------------------------------
// wmma bf16-split projection GEMM + GELU + LayerNorm   (base sm_100 safe)
//   C tile 128x128 per CTA, 8 warps (4m x 2n), warp tile 32x64.
//   K staged in chunks of 32, double-buffered cp.async.
//   3 MMAs per tile pair: ah*bh + ah*bl + al*bh  (split-bf16, err ~1e-5).
//   Epilogue: frags -> smem C (reuses stage mem) -> GELU + per-row LN(64) -> g_Fi.
// ---------------------------------------------------------------------------
#define KC     32
#define A_STR  40     // bf16 elems; 80B  = 5*16  (wmma ldm ok)
#define B_STR  136    // bf16 elems; 272B = 17*16
#define C_STR  140    // f32 elems;  560B = 35*16
#define A_PLANE (128 * A_STR * 2)                 // 10240 B
#define B_PLANE (KC * B_STR * 2)                  // 8704 B
#define STAGE_B (2 * A_PLANE + 2 * B_PLANE)       // 37888 B
#define SMEM_GB 512
#define PROJ_SMEM (SMEM_GB + 2 * STAGE_B)         // 76288 B  (C buf 71680 fits in stages)

__global__ __launch_bounds__(256, 1) void proj_wmma_kernel(
    const float* __restrict__ gamma,
    const float* __restrict__ beta,
    int sel, int K, int fbase)
{
    extern __shared__ char smem[];
    const int tid = threadIdx.x;
    const int wid = tid >> 5;

    const __nv_bfloat16 *Ah_g, *Al_g, *Wh_g, *Wl_g;
    if (sel == 0) { Ah_g = g_fh; Al_g = g_fl; Wh_g = g_wzh; Wl_g = g_wzl; }
    else          { Ah_g = g_hh; Al_g = g_hl; Wh_g = g_whh; Wl_g = g_whl; }

    const int bm = blockIdx.x * 128;
    const int bn = blockIdx.y * 128;

    if (tid < 64) {
        *(float*)(smem + tid * 4)       = gamma[tid];
        *(float*)(smem + 256 + tid * 4) = beta[tid];
    }

    const int warp_m = wid & 3;    // 0..3 -> 32-row slab
    const int warp_n = wid >> 2;   // 0..1 -> 64-col slab

    wmma::fragment<wmma::accumulator, 16, 16, 16, float> acc[2][4];
    #pragma unroll
    for (int fm = 0; fm < 2; fm++)
        #pragma unroll
        for (int fn = 0; fn < 4; fn++)
            wmma::fill_fragment(acc[fm][fn], 0.0f);

    const int nK = K / KC;

    // stage loader: 2048 cp.async chunks of 16B (A: 1024, B: 1024), 8 per thread
    auto load_stage = [&](int it, int buf) {
        const int kt = it * KC;
        char* stg = smem + SMEM_GB + buf * STAGE_B;
        const uint32_t stg_u = (uint32_t)__cvta_generic_to_shared(stg);
        // A: plane(2) x 128 rows x 4 chunks(16B)
        #pragma unroll
        for (int rep = 0; rep < 4; rep++) {
            const int i = tid + rep * 256;        // 0..1023
            const int plane = i >> 9;
            const int r     = (i >> 2) & 127;
            const int c     = i & 3;
            const __nv_bfloat16* gp = (plane ? Al_g : Ah_g)
                                    + (size_t)(bm + r) * K + kt + c * 8;
            cp_async16(stg_u + plane * A_PLANE + r * (A_STR * 2) + c * 16, gp);
        }
        // B: plane(2) x 32 k-rows x 16 chunks(16B)  (W row-major [K][N])
        #pragma unroll
        for (int rep = 0; rep < 4; rep++) {
            const int i = tid + rep * 256;        // 0..1023
            const int plane = i >> 9;
            const int kk    = (i >> 4) & 31;
            const int c     = i & 15;
            const __nv_bfloat16* gp = (plane ? Wl_g : Wh_g)
                                    + (size_t)(kt + kk) * MCOLS + bn + c * 8;
            cp_async16(stg_u + 2 * A_PLANE + plane * B_PLANE + kk * (B_STR * 2) + c * 16, gp);
        }
        asm volatile("cp.async.commit_group;");
    };

    load_stage(0, 0);

    for (int it = 0; it < nK; it++) {
        const int buf = it & 1;
        if (it + 1 < nK) {
            load_stage(it + 1, buf ^ 1);
            asm volatile("cp.async.wait_group 1;");
        } else {
            asm volatile("cp.async.wait_group 0;");
        }
        __syncthreads();

        const char* stg = smem + SMEM_GB + buf * STAGE_B;
        const __nv_bfloat16* As_hi = (const __nv_bfloat16*)(stg);
        const __nv_bfloat16* As_lo = (const __nv_bfloat16*)(stg + A_PLANE);
        const __nv_bfloat16* Bs_hi = (const __nv_bfloat16*)(stg + 2 * A_PLANE);
        const __nv_bfloat16* Bs_lo = (const __nv_bfloat16*)(stg + 2 * A_PLANE + B_PLANE);

        #pragma unroll
        for (int kk = 0; kk < KC; kk += 16) {
            wmma::fragment<wmma::matrix_a, 16, 16, 16, __nv_bfloat16, wmma::row_major> ah[2], al[2];
            #pragma unroll
            for (int fm = 0; fm < 2; fm++) {
                const int rr = warp_m * 32 + fm * 16;
                wmma::load_matrix_sync(ah[fm], As_hi + rr * A_STR + kk, A_STR);
                wmma::load_matrix_sync(al[fm], As_lo + rr * A_STR + kk, A_STR);
            }
            #pragma unroll
            for (int fn = 0; fn < 4; fn++) {
                wmma::fragment<wmma::matrix_b, 16, 16, 16, __nv_bfloat16, wmma::row_major> bh, bl;
                const int cc = warp_n * 64 + fn * 16;
                wmma::load_matrix_sync(bh, Bs_hi + kk * B_STR + cc, B_STR);
                wmma::load_matrix_sync(bl, Bs_lo + kk * B_STR + cc, B_STR);
                #pragma unroll
                for (int fm = 0; fm < 2; fm++) {
                    wmma::mma_sync(acc[fm][fn], ah[fm], bh, acc[fm][fn]);
                    wmma::mma_sync(acc[fm][fn], ah[fm], bl, acc[fm][fn]);
                    wmma::mma_sync(acc[fm][fn], al[fm], bh, acc[fm][fn]);
                }
            }
        }
        __syncthreads();   // stage buffer reuse (next load / C store)
    }

    // ---- Epilogue: frags -> smem C, then GELU + LN per (row, 64-col group) ----
    float* Cs = (float*)(smem + SMEM_GB);
    #pragma unroll
    for (int fm = 0; fm < 2; fm++)
        #pragma unroll
        for (int fn = 0; fn < 4; fn++)
            wmma::store_matrix_sync(Cs + (warp_m * 32 + fm * 16) * C_STR + warp_n * 64 + fn * 16,
                                    acc[fm][fn], C_STR, wmma::mem_row_major);
    __syncthreads();

    const float* gs = (const float*)(smem);
    const float* bs = (const float*)(smem + 256);
    {
        const int row = tid >> 1;       // 0..127
        const int grp = tid & 1;        // 0..1  (64-col LN group)
        const float* src = Cs + row * C_STR + grp * 64;

        float v[64];
        float s = 0.f, sq = 0.f;
        #pragma unroll
        for (int c = 0; c < 64; c++) {
            float x = gelu_exact(src[c]);
            v[c] = x;
            s += x; sq += x * x;
        }
        const float mu   = s * (1.f / 64.f);
        const float var  = sq * (1.f / 64.f) - mu * mu;
        const float rstd = rsqrtf(var + LN_EPS);

        const int f = fbase + (bn >> 6) + grp;
        float* dst = g_Fi + ((size_t)(bm + row) * NF_ + f) * D_;
        #pragma unroll
        for (int c4 = 0; c4 < 16; c4++) {
            float4 o;
            o.x = (v[c4 * 4 + 0] - mu) * rstd * gs[c4 * 4 + 0] + bs[c4 * 4 + 0];
            o.y = (v[c4 * 4 + 1] - mu) * rstd * gs[c4 * 4 + 1] + bs[c4 * 4 + 1];
            o.z = (v[c4 * 4 + 2] - mu) * rstd * gs[c4 * 4 + 2] + bs[c4 * 4 + 2];
            o.w = (v[c4 * 4 + 3] - mu) * rstd * gs[c4 * 4 + 3] + bs[c4 * 4 + 3];
            *(float4*)(dst + c4 * 4) = o;
        }
    }
}

// ---------------------------------------------------------------------------
// Kernel B (unchanged from round 1, passing): per (b,h) attention
// ---------------------------------------------------------------------------
#define FST_STRIDE 132

__global__ __launch_bounds__(128) void attn_kernel(
    const float* __restrict__ wv,
    float* __restrict__ out)
{
    extern __shared__ float sm[];
    float* Fst    = sm;
    float* Ws     = Fst + 64 * FST_STRIDE;
    float* logits = Ws + 64 * 64;
    float* qts    = logits + 128;
    float* mvs    = qts + 64;
    float* rbuf   = mvs + 128;
    float* gvec   = rbuf + 32;

    const int tid = threadIdx.x;
    const int h   = blockIdx.x;
    const int b   = blockIdx.y;

    const float* Fi = g_Fi + (size_t)b * NF_ * D_;

    {
        const int m = tid;
        #pragma unroll
        for (int v = 0; v < 16; v++) {
            float4 fv = *(const float4*)(Fi + m * 64 + v * 4);
            Fst[(v * 4 + 0) * FST_STRIDE + m] = fv.x;
            Fst[(v * 4 + 1) * FST_STRIDE + m] = fv.y;
            Fst[(v * 4 + 2) * FST_STRIDE + m] = fv.z;
            Fst[(v * 4 + 3) * FST_STRIDE + m] = fv.w;
        }
    }
    {
        const int dp = tid >> 1, half = tid & 1;
        const float* src = wv + (size_t)dp * 512 + h * 64 + half * 32;
        float* dst = Ws + dp * 64 + half * 32;
        #pragma unroll
        for (int v = 0; v < 8; v++)
            *(float4*)(dst + v * 4) = *(const float4*)(src + v * 4);
    }
    if (tid < 64) qts[tid] = g_qt[((size_t)b * 8 + h) * 64 + tid];
    __syncthreads();

    const int tm = tid >> 3;
    const int tdq = tid & 7;
    float acc[8][8];
    #pragma unroll
    for (int r = 0; r < 8; r++)
        #pragma unroll
        for (int c = 0; c < 8; c++) acc[r][c] = 0.f;

    #pragma unroll 4
    for (int k = 0; k < 64; k++) {
        float4 f0 = *(const float4*)&Fst[k * FST_STRIDE + tm * 8];
        float4 f1 = *(const float4*)&Fst[k * FST_STRIDE + tm * 8 + 4];
        float4 w0 = *(const float4*)&Ws[k * 64 + tdq * 8];
        float4 w1 = *(const float4*)&Ws[k * 64 + tdq * 8 + 4];
        const float fr[8] = {f0.x, f0.y, f0.z, f0.w, f1.x, f1.y, f1.z, f1.w};
        const float wr[8] = {w0.x, w0.y, w0.z, w0.w, w1.x, w1.y, w1.z, w1.w};
        #pragma unroll
        for (int r = 0; r < 8; r++)
            #pragma unroll
            for (int c = 0; c < 8; c++)
                acc[r][c] = fmaf(fr[r], wr[c], acc[r][c]);
    }

    #pragma unroll
    for (int r = 0; r < 8; r++) {
        float s = 0.f;
        #pragma unroll
        for (int c = 0; c < 8; c++) s += fabsf(acc[r][c]);
        #pragma unroll
        for (int off = 4; off >= 1; off >>= 1)
            s += __shfl_xor_sync(0xffffffffu, s, off, 8);
        if (tdq == r) mvs[tm * 8 + r] = s * (1.f / 64.f);
    }
    __syncthreads();

    {
        const int m = tid;
        float s = 0.f;
        #pragma unroll 8
        for (int k = 0; k < 64; k++)
            s = fmaf(Fst[k * FST_STRIDE + m], qts[k], s);
        logits[m] = mvs[m] * s * 0.125f;
    }
    __syncthreads();

    const float lg = logits[tid];
    float mx = lg;
    #pragma unroll
    for (int off = 16; off >= 1; off >>= 1)
        mx = fmaxf(mx, __shfl_xor_sync(0xffffffffu, mx, off));
    if ((tid & 31) == 0) rbuf[tid >> 5] = mx;
    __syncthreads();
    mx = fmaxf(fmaxf(rbuf[0], rbuf[1]), fmaxf(rbuf[2], rbuf[3]));

    const float e = expf(lg - mx);
    float se = e;
    #pragma unroll
    for (int off = 16; off >= 1; off >>= 1)
        se += __shfl_xor_sync(0xffffffffu, se, off);
    if ((tid & 31) == 0) rbuf[4 + (tid >> 5)] = se;
    logits[tid] = e;
    __syncthreads();
    const float inv = 1.f / (rbuf[4] + rbuf[5] + rbuf[6] + rbuf[7]);

    if (tid < 64) {
        float s = 0.f;
        #pragma unroll 8
        for (int m = 0; m < 128; m++)
            s = fmaf(logits[m], Fst[tid * FST_STRIDE + m], s);
        gvec[tid] = s * inv;
    }
    __syncthreads();

    if (tid < 64) {
        float s = 0.f;
        #pragma unroll 8
        for (int k = 0; k < 64; k++)
            s = fmaf(gvec[k], Ws[k * 64 + tid], s);
        out[((size_t)b * 8 + h) * 64 + tid] = s;
    }
}

// ---------------------------------------------------------------------------
// Launch
// ---------------------------------------------------------------------------
extern "C" void kernel_launch(void* const* d_in, const int* in_sizes, int n_in,
                              void* d_out, int out_size)
{
    const float* feature  = (const float*)d_in[0];
    const float* hidden   = (const float*)d_in[1];
    const float* command  = (const float*)d_in[2];
    const float* wz       = (const float*)d_in[3];
    const float* wh       = (const float*)d_in[4];
    const float* wq       = (const float*)d_in[5];
    const float* wk       = (const float*)d_in[6];
    const float* wv       = (const float*)d_in[7];
    const float* ln_gamma = (const float*)d_in[8];
    const float* ln_beta  = (const float*)d_in[9];
    float* out = (float*)d_out;

    const int attn_smem = (64 * FST_STRIDE + 64 * 64 + 128 + 64 + 128 + 32 + 64) * 4;
    cudaFuncSetAttribute(attn_kernel, cudaFuncAttributeMaxDynamicSharedMemorySize, attn_smem);
    cudaFuncSetAttribute(proj_wmma_kernel, cudaFuncAttributeMaxDynamicSharedMemorySize, PROJ_SMEM);

    // Split-precision conversions
    convert_kernel<<<1024, 256>>>(feature, 0, 2097152 / 4);
    convert_kernel<<<1024, 256>>>(hidden,  1, 1048576 / 4);
    convert_kernel<<<2048, 256>>>(wz,      2, 8388608 / 4);
    convert_kernel<<<2048, 256>>>(wh,      3, 4194304 / 4);

    q_kernel<<<B_SZ, 128>>>(command, wq, wk);

    // wmma projections: grid (m-tiles=8, n-tiles=32), 256 threads
    proj_wmma_kernel<<<dim3(8, 32), 256, PROJ_SMEM>>>(ln_gamma, ln_beta, 0, 2048, 0);
    proj_wmma_kernel<<<dim3(8, 32), 256, PROJ_SMEM>>>(ln_gamma, ln_beta, 1, 1024, 64);

    dim3 gB(H_, B_SZ);
    attn_kernel<<<gB, 128, attn_smem>>>(wv, out);
}

// round 7
// speedup vs baseline: 1.7774x; 1.1581x over previous
#include <cuda_runtime.h>
#include <cuda_bf16.h>
#include <mma.h>
#include <cstdint>
#include <stdint.h>
#include <math.h>

using namespace nvcuda;

// Problem constants
#define B_SZ   1024
#define NF_    128
#define D_     64
#define H_     8
#define MCOLS  4096
#define LN_EPS 1e-5f

// ---------------------------------------------------------------------------
// Scratch (__device__ globals)
// ---------------------------------------------------------------------------
__device__ float g_Fi[(size_t)B_SZ * NF_ * D_];   // [b][m][d] post-LN features (fp32)
__device__ float g_qt[(size_t)B_SZ * H_ * D_];    // [b][h][d'] = wk_h @ Q_bh
__device__ float g_mv[(size_t)B_SZ * H_ * NF_];   // [b][h][m]  mean |V|

// bf16 split planes
__device__ __nv_bfloat16 g_fh[2097152], g_fl[2097152];   // feature 1024x2048
__device__ __nv_bfloat16 g_hh[1048576], g_hl[1048576];   // hidden  1024x1024
__device__ __nv_bfloat16 g_wzh[8388608], g_wzl[8388608]; // wz      2048x4096
__device__ __nv_bfloat16 g_whh[4194304], g_whl[4194304]; // wh      1024x4096
__device__ __nv_bfloat16 g_wvh[32768],  g_wvl[32768];    // wv      64x512
__device__ __nv_bfloat16 g_Fih[8388608], g_Fil[8388608]; // Fi      [b][m][d]

__device__ __forceinline__ float gelu_exact(float x) {
    return 0.5f * x * (1.0f + erff(x * 0.70710678118654752f));
}

__device__ __forceinline__ void cp_async16(uint32_t dst, const void* src) {
    asm volatile("cp.async.cg.shared.global [%0], [%1], 16;\n"
                 :: "r"(dst), "l"(__cvta_generic_to_global(src)));
}

// ---------------------------------------------------------------------------
// Convert fp32 array -> bf16 hi/lo planes (split precision)
// ---------------------------------------------------------------------------
__global__ __launch_bounds__(256) void convert_kernel(const float* __restrict__ src,
                                                      int sel, int n4)
{
    __nv_bfloat16 *hi, *lo;
    switch (sel) {
        case 0:  hi = g_fh;  lo = g_fl;  break;
        case 1:  hi = g_hh;  lo = g_hl;  break;
        case 2:  hi = g_wzh; lo = g_wzl; break;
        case 3:  hi = g_whh; lo = g_whl; break;
        default: hi = g_wvh; lo = g_wvl; break;
    }
    const int stride = gridDim.x * blockDim.x;
    for (int j = blockIdx.x * blockDim.x + threadIdx.x; j < n4; j += stride) {
        float4 v = ((const float4*)src)[j];
        __nv_bfloat16 h0 = __float2bfloat16(v.x);
        __nv_bfloat16 h1 = __float2bfloat16(v.y);
        __nv_bfloat16 h2 = __float2bfloat16(v.z);
        __nv_bfloat16 h3 = __float2bfloat16(v.w);
        __nv_bfloat16 l0 = __float2bfloat16(v.x - __bfloat162float(h0));
        __nv_bfloat16 l1 = __float2bfloat16(v.y - __bfloat162float(h1));
        __nv_bfloat16 l2 = __float2bfloat16(v.z - __bfloat162float(h2));
        __nv_bfloat16 l3 = __float2bfloat16(v.w - __bfloat162float(h3));
        ((__nv_bfloat162*)hi)[j * 2 + 0] = __nv_bfloat162(h0, h1);
        ((__nv_bfloat162*)hi)[j * 2 + 1] = __nv_bfloat162(h2, h3);
        ((__nv_bfloat162*)lo)[j * 2 + 0] = __nv_bfloat162(l0, l1);
        ((__nv_bfloat162*)lo)[j * 2 + 1] = __nv_bfloat162(l2, l3);
    }
}

// ---------------------------------------------------------------------------
// Kernel Q
// ---------------------------------------------------------------------------
__global__ __launch_bounds__(128) void q_kernel(
    const float* __restrict__ command,
    const float* __restrict__ wq,
    const float* __restrict__ wk)
{
    __shared__ float cs[128];
    __shared__ float Qs[512];
    __shared__ float Wb[64][68];

    const int tid = threadIdx.x;
    const int b   = blockIdx.x;

    cs[tid] = command[(size_t)b * 128 + tid];
    __syncthreads();

    #pragma unroll
    for (int o = 0; o < 4; o++) {
        const int j = tid + o * 128;
        float s = 0.f;
        #pragma unroll 8
        for (int e = 0; e < 128; e++)
            s = fmaf(cs[e], wq[(size_t)e * 512 + j], s);
        Qs[j] = s;
    }
    __syncthreads();

    for (int h = 0; h < 8; h++) {
        const int dp = tid >> 1, half = tid & 1;
        const float* src = wk + (size_t)dp * 512 + h * 64 + half * 32;
        #pragma unroll
        for (int v = 0; v < 8; v++) {
            float4 w = *(const float4*)(src + v * 4);
            *(float4*)&Wb[dp][half * 32 + v * 4] = w;
        }
        __syncthreads();
        if (tid < 64) {
            float s = 0.f;
            #pragma unroll 8
            for (int d = 0; d < 64; d++)
                s = fmaf(Wb[tid][d], Qs[h * 64 + d], s);
            g_qt[((size_t)b * 8 + h) * 64 + tid] = s;
        }
        __syncthreads();
    }
}

// ---------------------------------------------------------------------------
// wmma bf16-split projection GEMM + GELU + LayerNorm (proven round-6 kernel,
// now also emits bf16 hi/lo planes of Fi, and 2 CTAs/SM).
// ---------------------------------------------------------------------------
#define KC     32
#define A_STR  40
#define B_STR  136
#define C_STR  140
#define A_PLANE (128 * A_STR * 2)
#define B_PLANE (KC * B_STR * 2)
#define STAGE_B (2 * A_PLANE + 2 * B_PLANE)
#define SMEM_GB 512
#define PROJ_SMEM (SMEM_GB + 2 * STAGE_B)

__global__ __launch_bounds__(256, 2) void proj_wmma_kernel(
    const float* __restrict__ gamma,
    const float* __restrict__ beta,
    int sel, int K, int fbase)
{
    extern __shared__ char smem[];
    const int tid = threadIdx.x;
    const int wid = tid >> 5;

    const __nv_bfloat16 *Ah_g, *Al_g, *Wh_g, *Wl_g;
    if (sel == 0) { Ah_g = g_fh; Al_g = g_fl; Wh_g = g_wzh; Wl_g = g_wzl; }
    else          { Ah_g = g_hh; Al_g = g_hl; Wh_g = g_whh; Wl_g = g_whl; }

    const int bm = blockIdx.x * 128;
    const int bn = blockIdx.y * 128;

    if (tid < 64) {
        *(float*)(smem + tid * 4)       = gamma[tid];
        *(float*)(smem + 256 + tid * 4) = beta[tid];
    }

    const int warp_m = wid & 3;
    const int warp_n = wid >> 2;

    wmma::fragment<wmma::accumulator, 16, 16, 16, float> acc[2][4];
    #pragma unroll
    for (int fm = 0; fm < 2; fm++)
        #pragma unroll
        for (int fn = 0; fn < 4; fn++)
            wmma::fill_fragment(acc[fm][fn], 0.0f);

    const int nK = K / KC;

    auto load_stage = [&](int it, int buf) {
        const int kt = it * KC;
        char* stg = smem + SMEM_GB + buf * STAGE_B;
        const uint32_t stg_u = (uint32_t)__cvta_generic_to_shared(stg);
        #pragma unroll
        for (int rep = 0; rep < 4; rep++) {
            const int i = tid + rep * 256;
            const int plane = i >> 9;
            const int r     = (i >> 2) & 127;
            const int c     = i & 3;
            const __nv_bfloat16* gp = (plane ? Al_g : Ah_g)
                                    + (size_t)(bm + r) * K + kt + c * 8;
            cp_async16(stg_u + plane * A_PLANE + r * (A_STR * 2) + c * 16, gp);
        }
        #pragma unroll
        for (int rep = 0; rep < 4; rep++) {
            const int i = tid + rep * 256;
            const int plane = i >> 9;
            const int kk    = (i >> 4) & 31;
            const int c     = i & 15;
            const __nv_bfloat16* gp = (plane ? Wl_g : Wh_g)
                                    + (size_t)(kt + kk) * MCOLS + bn + c * 8;
            cp_async16(stg_u + 2 * A_PLANE + plane * B_PLANE + kk * (B_STR * 2) + c * 16, gp);
        }
        asm volatile("cp.async.commit_group;");
    };

    load_stage(0, 0);

    for (int it = 0; it < nK; it++) {
        const int buf = it & 1;
        if (it + 1 < nK) {
            load_stage(it + 1, buf ^ 1);
            asm volatile("cp.async.wait_group 1;");
        } else {
            asm volatile("cp.async.wait_group 0;");
        }
        __syncthreads();

        const char* stg = smem + SMEM_GB + buf * STAGE_B;
        const __nv_bfloat16* As_hi = (const __nv_bfloat16*)(stg);
        const __nv_bfloat16* As_lo = (const __nv_bfloat16*)(stg + A_PLANE);
        const __nv_bfloat16* Bs_hi = (const __nv_bfloat16*)(stg + 2 * A_PLANE);
        const __nv_bfloat16* Bs_lo = (const __nv_bfloat16*)(stg + 2 * A_PLANE + B_PLANE);

        #pragma unroll
        for (int kk = 0; kk < KC; kk += 16) {
            wmma::fragment<wmma::matrix_a, 16, 16, 16, __nv_bfloat16, wmma::row_major> ah[2], al[2];
            #pragma unroll
            for (int fm = 0; fm < 2; fm++) {
                const int rr = warp_m * 32 + fm * 16;
                wmma::load_matrix_sync(ah[fm], As_hi + rr * A_STR + kk, A_STR);
                wmma::load_matrix_sync(al[fm], As_lo + rr * A_STR + kk, A_STR);
            }
            #pragma unroll
            for (int fn = 0; fn < 4; fn++) {
                wmma::fragment<wmma::matrix_b, 16, 16, 16, __nv_bfloat16, wmma::row_major> bh, bl;
                const int cc = warp_n * 64 + fn * 16;
                wmma::load_matrix_sync(bh, Bs_hi + kk * B_STR + cc, B_STR);
                wmma::load_matrix_sync(bl, Bs_lo + kk * B_STR + cc, B_STR);
                #pragma unroll
                for (int fm = 0; fm < 2; fm++) {
                    wmma::mma_sync(acc[fm][fn], ah[fm], bh, acc[fm][fn]);
                    wmma::mma_sync(acc[fm][fn], ah[fm], bl, acc[fm][fn]);
                    wmma::mma_sync(acc[fm][fn], al[fm], bh, acc[fm][fn]);
                }
            }
        }
        __syncthreads();
    }

    // ---- Epilogue: frags -> smem C, then GELU + LN, write fp32 + bf16 planes
    float* Cs = (float*)(smem + SMEM_GB);
    #pragma unroll
    for (int fm = 0; fm < 2; fm++)
        #pragma unroll
        for (int fn = 0; fn < 4; fn++)
            wmma::store_matrix_sync(Cs + (warp_m * 32 + fm * 16) * C_STR + warp_n * 64 + fn * 16,
                                    acc[fm][fn], C_STR, wmma::mem_row_major);
    __syncthreads();

    const float* gs = (const float*)(smem);
    const float* bs = (const float*)(smem + 256);
    {
        const int row = tid >> 1;
        const int grp = tid & 1;
        const float* src = Cs + row * C_STR + grp * 64;

        float v[64];
        float s = 0.f, sq = 0.f;
        #pragma unroll
        for (int c = 0; c < 64; c++) {
            float x = gelu_exact(src[c]);
            v[c] = x;
            s += x; sq += x * x;
        }
        const float mu   = s * (1.f / 64.f);
        const float var  = sq * (1.f / 64.f) - mu * mu;
        const float rstd = rsqrtf(var + LN_EPS);

        const int f = fbase + (bn >> 6) + grp;
        const size_t base = ((size_t)(bm + row) * NF_ + f) * D_;
        float* dst = g_Fi + base;
        __nv_bfloat162* dh = (__nv_bfloat162*)(g_Fih + base);
        __nv_bfloat162* dl = (__nv_bfloat162*)(g_Fil + base);
        #pragma unroll
        for (int c4 = 0; c4 < 16; c4++) {
            float4 o;
            o.x = (v[c4 * 4 + 0] - mu) * rstd * gs[c4 * 4 + 0] + bs[c4 * 4 + 0];
            o.y = (v[c4 * 4 + 1] - mu) * rstd * gs[c4 * 4 + 1] + bs[c4 * 4 + 1];
            o.z = (v[c4 * 4 + 2] - mu) * rstd * gs[c4 * 4 + 2] + bs[c4 * 4 + 2];
            o.w = (v[c4 * 4 + 3] - mu) * rstd * gs[c4 * 4 + 3] + bs[c4 * 4 + 3];
            *(float4*)(dst + c4 * 4) = o;
            __nv_bfloat16 hx = __float2bfloat16(o.x);
            __nv_bfloat16 hy = __float2bfloat16(o.y);
            __nv_bfloat16 hz = __float2bfloat16(o.z);
            __nv_bfloat16 hw = __float2bfloat16(o.w);
            dh[c4 * 2 + 0] = __nv_bfloat162(hx, hy);
            dh[c4 * 2 + 1] = __nv_bfloat162(hz, hw);
            dl[c4 * 2 + 0] = __nv_bfloat162(__float2bfloat16(o.x - __bfloat162float(hx)),
                                            __float2bfloat16(o.y - __bfloat162float(hy)));
            dl[c4 * 2 + 1] = __nv_bfloat162(__float2bfloat16(o.z - __bfloat162float(hz)),
                                            __float2bfloat16(o.w - __bfloat162float(hw)));
        }
    }
}

// ---------------------------------------------------------------------------
// mv_kernel: per b, V = Fi_b @ wv via wmma (bf16 split); mV = mean_d |V|.
//   Fi: [128 x 64] planes from smem. wv chunks: [64 x 128] (2 heads per chunk).
//   8 warps: warp_m(4) x warp_n(2); warp tile 32x64; frags 2x4; K=64.
// ---------------------------------------------------------------------------
#define MV_A_STR 72                          // bf16 elems (144B = 9*16)
#define MV_APL   (128 * MV_A_STR * 2)        // 18432 B
#define MV_B_STR 136
#define MV_BPL   (64 * MV_B_STR * 2)         // 17408 B
#define MV_C_STR 136
#define MV_SMEM  (2 * MV_APL + 2 * MV_BPL + 128 * MV_C_STR * 4)  // 141312 B

__global__ __launch_bounds__(256, 1) void mv_kernel()
{
    extern __shared__ char smem[];
    const int tid = threadIdx.x;
    const int wid = tid >> 5;
    const int lid = tid & 31;
    const int b   = blockIdx.x;

    char* Afi = smem;                       // Fi hi plane
    char* Afl = smem + MV_APL;              // Fi lo plane
    char* Bwh = smem + 2 * MV_APL;          // wv hi chunk
    char* Bwl = Bwh + MV_BPL;
    float* Cs = (float*)(Bwl + MV_BPL);

    const uint32_t smem_u = (uint32_t)__cvta_generic_to_shared(smem);

    // Load Fi planes: 2 planes x 128 rows x 8 chunks(16B) = 2048; 8/thread
    {
        const size_t base = (size_t)b * NF_ * D_;
        #pragma unroll
        for (int rep = 0; rep < 8; rep++) {
            const int i = tid + rep * 256;
            const int plane = i >> 10;
            const int r     = (i >> 3) & 127;
            const int c     = i & 7;
            const __nv_bfloat16* gp = (plane ? g_Fil : g_Fih) + base + r * 64 + c * 8;
            cp_async16(smem_u + plane * MV_APL + r * (MV_A_STR * 2) + c * 16, gp);
        }
        asm volatile("cp.async.commit_group;");
    }

    const int warp_m = wid & 3;
    const int warp_n = wid >> 2;
    const uint32_t bwh_u = (uint32_t)__cvta_generic_to_shared(Bwh);

    for (int nc = 0; nc < 4; nc++) {
        // load wv chunk [64 k x 128 n] hi/lo: 2048 chunks, 8/thread
        #pragma unroll
        for (int rep = 0; rep < 8; rep++) {
            const int i = tid + rep * 256;
            const int plane = i >> 10;
            const int kk    = (i >> 4) & 63;
            const int c     = i & 15;
            const __nv_bfloat16* gp = (plane ? g_wvl : g_wvh) + kk * 512 + nc * 128 + c * 8;
            cp_async16(bwh_u + plane * MV_BPL + kk * (MV_B_STR * 2) + c * 16, gp);
        }
        asm volatile("cp.async.commit_group;");
        asm volatile("cp.async.wait_group 0;");
        __syncthreads();

        wmma::fragment<wmma::accumulator, 16, 16, 16, float> acc[2][4];
        #pragma unroll
        for (int fm = 0; fm < 2; fm++)
            #pragma unroll
            for (int fn = 0; fn < 4; fn++)
                wmma::fill_fragment(acc[fm][fn], 0.0f);

        const __nv_bfloat16* As_hi = (const __nv_bfloat16*)Afi;
        const __nv_bfloat16* As_lo = (const __nv_bfloat16*)Afl;
        const __nv_bfloat16* Bs_hi = (const __nv_bfloat16*)Bwh;
        const __nv_bfloat16* Bs_lo = (const __nv_bfloat16*)Bwl;

        #pragma unroll
        for (int kk = 0; kk < 64; kk += 16) {
            wmma::fragment<wmma::matrix_a, 16, 16, 16, __nv_bfloat16, wmma::row_major> ah[2], al[2];
            #pragma unroll
            for (int fm = 0; fm < 2; fm++) {
                const int rr = warp_m * 32 + fm * 16;
                wmma::load_matrix_sync(ah[fm], As_hi + rr * MV_A_STR + kk, MV_A_STR);
                wmma::load_matrix_sync(al[fm], As_lo + rr * MV_A_STR + kk, MV_A_STR);
            }
            #pragma unroll
            for (int fn = 0; fn < 4; fn++) {
                wmma::fragment<wmma::matrix_b, 16, 16, 16, __nv_bfloat16, wmma::row_major> bh, bl;
                const int cc = warp_n * 64 + fn * 16;
                wmma::load_matrix_sync(bh, Bs_hi + kk * MV_B_STR + cc, MV_B_STR);
                wmma::load_matrix_sync(bl, Bs_lo + kk * MV_B_STR + cc, MV_B_STR);
                #pragma unroll
                for (int fm = 0; fm < 2; fm++) {
                    wmma::mma_sync(acc[fm][fn], ah[fm], bh, acc[fm][fn]);
                    wmma::mma_sync(acc[fm][fn], ah[fm], bl, acc[fm][fn]);
                    wmma::mma_sync(acc[fm][fn], al[fm], bh, acc[fm][fn]);
                }
            }
        }
        __syncthreads();   // Bw reuse barrier not needed yet, but Cs shared next
        #pragma unroll
        for (int fm = 0; fm < 2; fm++)
            #pragma unroll
            for (int fn = 0; fn < 4; fn++)
                wmma::store_matrix_sync(Cs + (warp_m * 32 + fm * 16) * MV_C_STR + warp_n * 64 + fn * 16,
                                        acc[fm][fn], MV_C_STR, wmma::mem_row_major);
        __syncthreads();

        // abs-row-sums: warp w owns rows w*16..w*16+15; lanes sweep columns
        #pragma unroll
        for (int hh = 0; hh < 2; hh++) {
            for (int mi = 0; mi < 16; mi++) {
                const int m = wid * 16 + mi;
                const float* rowp = Cs + m * MV_C_STR + hh * 64;
                float s = fabsf(rowp[lid]) + fabsf(rowp[lid + 32]);
                #pragma unroll
                for (int off = 16; off >= 1; off >>= 1)
                    s += __shfl_xor_sync(0xffffffffu, s, off);
                if (lid == 0)
                    g_mv[((size_t)b * 8 + nc * 2 + hh) * 128 + m] = s * (1.f / 64.f);
            }
        }
        __syncthreads();
    }
}

// ---------------------------------------------------------------------------
// attn_lite: per b: logits (Fi.qt * mv / 8), softmax, gvec = A^T Fi, S = gvec@wv
// ---------------------------------------------------------------------------
#define FSTR 129   // odd*4B stride: conflict-free in both access directions
#define LITE_SMEM ((64 * FSTR + 512 + 1024 + 1024 + 512) * 4)

__global__ __launch_bounds__(256, 1) void attn_lite_kernel(
    const float* __restrict__ wv,
    float* __restrict__ out)
{
    extern __shared__ float sm[];
    float* Fst  = sm;                 // [64][FSTR]  Fi transposed
    float* qts  = Fst + 64 * FSTR;    // [512]
    float* mvs  = qts + 512;          // [1024] (h,m)
    float* Aw   = mvs + 1024;         // [1024] logits -> weights
    float* gv   = Aw + 1024;          // [512]  (h,d)

    const int tid = threadIdx.x;
    const int b   = blockIdx.x;

    // Load Fi transposed: thread (m = tid&127, half = tid>>7) does 8 float4
    {
        const float* Fi = g_Fi + (size_t)b * NF_ * D_;
        const int m = tid & 127, half = tid >> 7;
        #pragma unroll
        for (int v = 0; v < 8; v++) {
            const int vv = half * 8 + v;
            float4 fv = *(const float4*)(Fi + m * 64 + vv * 4);
            Fst[(vv * 4 + 0) * FSTR + m] = fv.x;
            Fst[(vv * 4 + 1) * FSTR + m] = fv.y;
            Fst[(vv * 4 + 2) * FSTR + m] = fv.z;
            Fst[(vv * 4 + 3) * FSTR + m] = fv.w;
        }
    }
    #pragma unroll
    for (int r = 0; r < 2; r++)
        qts[tid + r * 256] = g_qt[(size_t)b * 512 + tid + r * 256];
    #pragma unroll
    for (int r = 0; r < 4; r++)
        mvs[tid + r * 256] = g_mv[(size_t)b * 1024 + tid + r * 256];
    __syncthreads();

    // logits: 1024 (h,m); 4 per thread
    #pragma unroll
    for (int r = 0; r < 4; r++) {
        const int idx = tid + r * 256;
        const int h = idx >> 7, m = idx & 127;
        float s = 0.f;
        #pragma unroll 8
        for (int k = 0; k < 64; k++)
            s = fmaf(Fst[k * FSTR + m], qts[h * 64 + k], s);
        Aw[idx] = mvs[idx] * s * 0.125f;
    }
    __syncthreads();

    // softmax: warp w = head w; 4 values per lane
    {
        const int w = tid >> 5, lane = tid & 31;
        float v0 = Aw[w * 128 + lane];
        float v1 = Aw[w * 128 + lane + 32];
        float v2 = Aw[w * 128 + lane + 64];
        float v3 = Aw[w * 128 + lane + 96];
        float mx = fmaxf(fmaxf(v0, v1), fmaxf(v2, v3));
        #pragma unroll
        for (int off = 16; off >= 1; off >>= 1)
            mx = fmaxf(mx, __shfl_xor_sync(0xffffffffu, mx, off));
        v0 = expf(v0 - mx); v1 = expf(v1 - mx);
        v2 = expf(v2 - mx); v3 = expf(v3 - mx);
        float se = v0 + v1 + v2 + v3;
        #pragma unroll
        for (int off = 16; off >= 1; off >>= 1)
            se += __shfl_xor_sync(0xffffffffu, se, off);
        const float inv = 1.f / se;
        Aw[w * 128 + lane]      = v0 * inv;
        Aw[w * 128 + lane + 32] = v1 * inv;
        Aw[w * 128 + lane + 64] = v2 * inv;
        Aw[w * 128 + lane + 96] = v3 * inv;
    }
    __syncthreads();

    // gvec: 512 (h,d); 2 per thread
    #pragma unroll
    for (int r = 0; r < 2; r++) {
        const int idx = tid + r * 256;
        const int h = idx >> 6, d = idx & 63;
        float s = 0.f;
        #pragma unroll 8
        for (int m = 0; m < 128; m++)
            s = fmaf(Aw[h * 128 + m], Fst[d * FSTR + m], s);
        gv[idx] = s;
    }
    __syncthreads();

    // S: 512 (h,d); 2 per thread; wv fp32 global (L2-hot)
    #pragma unroll
    for (int r = 0; r < 2; r++) {
        const int idx = tid + r * 256;
        const int h = idx >> 6, d = idx & 63;
        float s = 0.f;
        #pragma unroll 8
        for (int k = 0; k < 64; k++)
            s = fmaf(gv[h * 64 + k], wv[(size_t)k * 512 + h * 64 + d], s);
        out[(size_t)b * 512 + idx] = s;
    }
}

// ---------------------------------------------------------------------------
// Launch
// ---------------------------------------------------------------------------
extern "C" void kernel_launch(void* const* d_in, const int* in_sizes, int n_in,
                              void* d_out, int out_size)
{
    const float* feature  = (const float*)d_in[0];
    const float* hidden   = (const float*)d_in[1];
    const float* command  = (const float*)d_in[2];
    const float* wz       = (const float*)d_in[3];
    const float* wh       = (const float*)d_in[4];
    const float* wq       = (const float*)d_in[5];
    const float* wk       = (const float*)d_in[6];
    const float* wv       = (const float*)d_in[7];
    const float* ln_gamma = (const float*)d_in[8];
    const float* ln_beta  = (const float*)d_in[9];
    float* out = (float*)d_out;

    cudaFuncSetAttribute(proj_wmma_kernel, cudaFuncAttributeMaxDynamicSharedMemorySize, PROJ_SMEM);
    cudaFuncSetAttribute(mv_kernel, cudaFuncAttributeMaxDynamicSharedMemorySize, MV_SMEM);
    cudaFuncSetAttribute(attn_lite_kernel, cudaFuncAttributeMaxDynamicSharedMemorySize, LITE_SMEM);

    // Split-precision conversions
    convert_kernel<<<1024, 256>>>(feature, 0, 2097152 / 4);
    convert_kernel<<<1024, 256>>>(hidden,  1, 1048576 / 4);
    convert_kernel<<<2048, 256>>>(wz,      2, 8388608 / 4);
    convert_kernel<<<2048, 256>>>(wh,      3, 4194304 / 4);
    convert_kernel<<<32,   256>>>(wv,      4, 32768 / 4);

    q_kernel<<<B_SZ, 128>>>(command, wq, wk);

    proj_wmma_kernel<<<dim3(8, 32), 256, PROJ_SMEM>>>(ln_gamma, ln_beta, 0, 2048, 0);
    proj_wmma_kernel<<<dim3(8, 32), 256, PROJ_SMEM>>>(ln_gamma, ln_beta, 1, 1024, 64);

    mv_kernel<<<B_SZ, 256, MV_SMEM>>>();
    attn_lite_kernel<<<B_SZ, 256, LITE_SMEM>>>(wv, out);
}

// round 9
// speedup vs baseline: 2.2034x; 1.2396x over previous
#include <cuda_runtime.h>
#include <cuda_bf16.h>
#include <mma.h>
#include <cstdint>
#include <stdint.h>
#include <math.h>

using namespace nvcuda;

// Problem constants
#define B_SZ   1024
#define NF_    128
#define D_     64
#define H_     8
#define MCOLS  4096
#define LN_EPS 1e-5f

// ---------------------------------------------------------------------------
// Scratch (__device__ globals)
// ---------------------------------------------------------------------------
__device__ float g_Fi[(size_t)B_SZ * NF_ * D_];   // [b][m][d] post-LN features (fp32)
__device__ float g_qt[(size_t)B_SZ * H_ * D_];    // [b][h][d'] folded K-query
__device__ float g_mv[(size_t)B_SZ * H_ * NF_];   // [b][h][m]  mean |V|
__device__ float g_wqt[128 * 512];                // [e][h*64+d'] folded wq/wk

// bf16 split planes
__device__ __nv_bfloat16 g_fh[2097152], g_fl[2097152];   // feature 1024x2048
__device__ __nv_bfloat16 g_hh[1048576], g_hl[1048576];   // hidden  1024x1024
__device__ __nv_bfloat16 g_wzh[8388608], g_wzl[8388608]; // wz      2048x4096
__device__ __nv_bfloat16 g_whh[4194304], g_whl[4194304]; // wh      1024x4096
__device__ __nv_bfloat16 g_wvh[32768];                   // wv      64x512 (hi only)
__device__ __nv_bfloat16 g_Fih[8388608];                 // Fi hi   [b][m][d]

__device__ __forceinline__ float gelu_exact(float x) {
    return 0.5f * x * (1.0f + erff(x * 0.70710678118654752f));
}

__device__ __forceinline__ void cp_async16(uint32_t dst, const void* src) {
    asm volatile("cp.async.cg.shared.global [%0], [%1], 16;\n"
                 :: "r"(dst), "l"(__cvta_generic_to_global(src)));
}

// ---------------------------------------------------------------------------
// Convert fp32 -> bf16 hi/lo planes (split precision); sel 4 = wv hi-only
// ---------------------------------------------------------------------------
__global__ __launch_bounds__(256) void convert_kernel(const float* __restrict__ src,
                                                      int sel, int n4)
{
    __nv_bfloat16 *hi, *lo;
    switch (sel) {
        case 0:  hi = g_fh;  lo = g_fl;  break;
        case 1:  hi = g_hh;  lo = g_hl;  break;
        case 2:  hi = g_wzh; lo = g_wzl; break;
        case 3:  hi = g_whh; lo = g_whl; break;
        default: hi = g_wvh; lo = 0;     break;
    }
    const int stride = gridDim.x * blockDim.x;
    for (int j = blockIdx.x * blockDim.x + threadIdx.x; j < n4; j += stride) {
        float4 v = ((const float4*)src)[j];
        __nv_bfloat16 h0 = __float2bfloat16(v.x);
        __nv_bfloat16 h1 = __float2bfloat16(v.y);
        __nv_bfloat16 h2 = __float2bfloat16(v.z);
        __nv_bfloat16 h3 = __float2bfloat16(v.w);
        ((__nv_bfloat162*)hi)[j * 2 + 0] = __nv_bfloat162(h0, h1);
        ((__nv_bfloat162*)hi)[j * 2 + 1] = __nv_bfloat162(h2, h3);
        if (lo) {
            __nv_bfloat16 l0 = __float2bfloat16(v.x - __bfloat162float(h0));
            __nv_bfloat16 l1 = __float2bfloat16(v.y - __bfloat162float(h1));
            __nv_bfloat16 l2 = __float2bfloat16(v.z - __bfloat162float(h2));
            __nv_bfloat16 l3 = __float2bfloat16(v.w - __bfloat162float(h3));
            ((__nv_bfloat162*)lo)[j * 2 + 0] = __nv_bfloat162(l0, l1);
            ((__nv_bfloat162*)lo)[j * 2 + 1] = __nv_bfloat162(l2, l3);
        }
    }
}

// ---------------------------------------------------------------------------
// wqt_kernel: Wqt[e, h*64+dp] = sum_d wq[e, h*64+d] * wk[dp, h*64+d]
// ---------------------------------------------------------------------------
__global__ __launch_bounds__(256) void wqt_kernel(
    const float* __restrict__ wq,
    const float* __restrict__ wk)
{
    const int idx = blockIdx.x * 256 + threadIdx.x;   // 65536 total
    const int e  = idx >> 9;
    const int j  = idx & 511;
    const int h  = j >> 6;
    const int dp = j & 63;
    float s = 0.f;
    const float* wqp = wq + (size_t)e * 512 + h * 64;
    const float* wkp = wk + (size_t)dp * 512 + h * 64;
    #pragma unroll 8
    for (int d = 0; d < 64; d++)
        s = fmaf(wqp[d], wkp[d], s);
    g_wqt[e * 512 + j] = s;
}

// ---------------------------------------------------------------------------
// qt_kernel: qt = command @ Wqt   ([1024,128]@[128,512])
//   grid (32 b-tiles, 4 j-tiles), 256 threads; dynamic smem (84KB > 48KB static cap)
// ---------------------------------------------------------------------------
#define QT_WSTR 132
#define QT_SMEM ((32 * 128 + 128 * QT_WSTR) * 4)   // 83968 B

__global__ __launch_bounds__(256) void qt_kernel(const float* __restrict__ command)
{
    extern __shared__ float qsm[];
    float* cmds = qsm;                  // [32 * 128]
    float* Wq   = qsm + 32 * 128;       // [128 * QT_WSTR]

    const int tid = threadIdx.x;
    const int bb  = blockIdx.x * 32;
    const int jt  = blockIdx.y * 128;

    #pragma unroll
    for (int rep = 0; rep < 4; rep++) {
        const int i = tid + rep * 256;        // 0..1023 float4
        const int row = i >> 5, c4 = i & 31;
        float4 v = *(const float4*)(command + (size_t)(bb + row) * 128 + c4 * 4);
        *(float4*)(cmds + row * 128 + c4 * 4) = v;
    }
    #pragma unroll
    for (int rep = 0; rep < 16; rep++) {
        const int i = tid + rep * 256;        // 0..4095 float4
        const int row = i >> 5, c4 = i & 31;
        float4 v = *(const float4*)(g_wqt + row * 512 + jt + c4 * 4);
        *(float4*)(Wq + row * QT_WSTR + c4 * 4) = v;
    }
    __syncthreads();

    const int r = tid >> 3;       // 0..31 (b row)
    const int g = tid & 7;        // 0..7  (16-col group)
    float acc[16];
    #pragma unroll
    for (int c = 0; c < 16; c++) acc[c] = 0.f;

    #pragma unroll 4
    for (int k = 0; k < 128; k++) {
        const float a = cmds[r * 128 + k];
        const float* wp = Wq + k * QT_WSTR + g * 16;
        #pragma unroll
        for (int c = 0; c < 16; c++)
            acc[c] = fmaf(a, wp[c], acc[c]);
    }

    float* dst = g_qt + (size_t)(bb + r) * 512 + jt + g * 16;
    #pragma unroll
    for (int c4 = 0; c4 < 4; c4++)
        *(float4*)(dst + c4 * 4) = make_float4(acc[c4 * 4], acc[c4 * 4 + 1],
                                               acc[c4 * 4 + 2], acc[c4 * 4 + 3]);
}

// ---------------------------------------------------------------------------
// wmma bf16-split projection GEMM + GELU + LayerNorm (round-7 proven; epilogue
// writes fp32 Fi + bf16 hi plane only).
// ---------------------------------------------------------------------------
#define KC     32
#define A_STR  40
#define B_STR  136
#define C_STR  140
#define A_PLANE (128 * A_STR * 2)
#define B_PLANE (KC * B_STR * 2)
#define STAGE_B (2 * A_PLANE + 2 * B_PLANE)
#define SMEM_GB 512
#define PROJ_SMEM (SMEM_GB + 2 * STAGE_B)

__global__ __launch_bounds__(256, 2) void proj_wmma_kernel(
    const float* __restrict__ gamma,
    const float* __restrict__ beta,
    int sel, int K, int fbase)
{
    extern __shared__ char smem[];
    const int tid = threadIdx.x;
    const int wid = tid >> 5;

    const __nv_bfloat16 *Ah_g, *Al_g, *Wh_g, *Wl_g;
    if (sel == 0) { Ah_g = g_fh; Al_g = g_fl; Wh_g = g_wzh; Wl_g = g_wzl; }
    else          { Ah_g = g_hh; Al_g = g_hl; Wh_g = g_whh; Wl_g = g_whl; }

    const int bm = blockIdx.x * 128;
    const int bn = blockIdx.y * 128;

    if (tid < 64) {
        *(float*)(smem + tid * 4)       = gamma[tid];
        *(float*)(smem + 256 + tid * 4) = beta[tid];
    }

    const int warp_m = wid & 3;
    const int warp_n = wid >> 2;

    wmma::fragment<wmma::accumulator, 16, 16, 16, float> acc[2][4];
    #pragma unroll
    for (int fm = 0; fm < 2; fm++)
        #pragma unroll
        for (int fn = 0; fn < 4; fn++)
            wmma::fill_fragment(acc[fm][fn], 0.0f);

    const int nK = K / KC;

    auto load_stage = [&](int it, int buf) {
        const int kt = it * KC;
        char* stg = smem + SMEM_GB + buf * STAGE_B;
        const uint32_t stg_u = (uint32_t)__cvta_generic_to_shared(stg);
        #pragma unroll
        for (int rep = 0; rep < 4; rep++) {
            const int i = tid + rep * 256;
            const int plane = i >> 9;
            const int r     = (i >> 2) & 127;
            const int c     = i & 3;
            const __nv_bfloat16* gp = (plane ? Al_g : Ah_g)
                                    + (size_t)(bm + r) * K + kt + c * 8;
            cp_async16(stg_u + plane * A_PLANE + r * (A_STR * 2) + c * 16, gp);
        }
        #pragma unroll
        for (int rep = 0; rep < 4; rep++) {
            const int i = tid + rep * 256;
            const int plane = i >> 9;
            const int kk    = (i >> 4) & 31;
            const int c     = i & 15;
            const __nv_bfloat16* gp = (plane ? Wl_g : Wh_g)
                                    + (size_t)(kt + kk) * MCOLS + bn + c * 8;
            cp_async16(stg_u + 2 * A_PLANE + plane * B_PLANE + kk * (B_STR * 2) + c * 16, gp);
        }
        asm volatile("cp.async.commit_group;");
    };

    load_stage(0, 0);

    for (int it = 0; it < nK; it++) {
        const int buf = it & 1;
        if (it + 1 < nK) {
            load_stage(it + 1, buf ^ 1);
            asm volatile("cp.async.wait_group 1;");
        } else {
            asm volatile("cp.async.wait_group 0;");
        }
        __syncthreads();

        const char* stg = smem + SMEM_GB + buf * STAGE_B;
        const __nv_bfloat16* As_hi = (const __nv_bfloat16*)(stg);
        const __nv_bfloat16* As_lo = (const __nv_bfloat16*)(stg + A_PLANE);
        const __nv_bfloat16* Bs_hi = (const __nv_bfloat16*)(stg + 2 * A_PLANE);
        const __nv_bfloat16* Bs_lo = (const __nv_bfloat16*)(stg + 2 * A_PLANE + B_PLANE);

        #pragma unroll
        for (int kk = 0; kk < KC; kk += 16) {
            wmma::fragment<wmma::matrix_a, 16, 16, 16, __nv_bfloat16, wmma::row_major> ah[2], al[2];
            #pragma unroll
            for (int fm = 0; fm < 2; fm++) {
                const int rr = warp_m * 32 + fm * 16;
                wmma::load_matrix_sync(ah[fm], As_hi + rr * A_STR + kk, A_STR);
                wmma::load_matrix_sync(al[fm], As_lo + rr * A_STR + kk, A_STR);
            }
            #pragma unroll
            for (int fn = 0; fn < 4; fn++) {
                wmma::fragment<wmma::matrix_b, 16, 16, 16, __nv_bfloat16, wmma::row_major> bh, bl;
                const int cc = warp_n * 64 + fn * 16;
                wmma::load_matrix_sync(bh, Bs_hi + kk * B_STR + cc, B_STR);
                wmma::load_matrix_sync(bl, Bs_lo + kk * B_STR + cc, B_STR);
                #pragma unroll
                for (int fm = 0; fm < 2; fm++) {
                    wmma::mma_sync(acc[fm][fn], ah[fm], bh, acc[fm][fn]);
                    wmma::mma_sync(acc[fm][fn], ah[fm], bl, acc[fm][fn]);
                    wmma::mma_sync(acc[fm][fn], al[fm], bh, acc[fm][fn]);
                }
            }
        }
        __syncthreads();
    }

    // ---- Epilogue
    float* Cs = (float*)(smem + SMEM_GB);
    #pragma unroll
    for (int fm = 0; fm < 2; fm++)
        #pragma unroll
        for (int fn = 0; fn < 4; fn++)
            wmma::store_matrix_sync(Cs + (warp_m * 32 + fm * 16) * C_STR + warp_n * 64 + fn * 16,
                                    acc[fm][fn], C_STR, wmma::mem_row_major);
    __syncthreads();

    const float* gs = (const float*)(smem);
    const float* bs = (const float*)(smem + 256);
    {
        const int row = tid >> 1;
        const int grp = tid & 1;
        const float* src = Cs + row * C_STR + grp * 64;

        float v[64];
        float s = 0.f, sq = 0.f;
        #pragma unroll
        for (int c = 0; c < 64; c++) {
            float x = gelu_exact(src[c]);
            v[c] = x;
            s += x; sq += x * x;
        }
        const float mu   = s * (1.f / 64.f);
        const float var  = sq * (1.f / 64.f) - mu * mu;
        const float rstd = rsqrtf(var + LN_EPS);

        const int f = fbase + (bn >> 6) + grp;
        const size_t base = ((size_t)(bm + row) * NF_ + f) * D_;
        float* dst = g_Fi + base;
        __nv_bfloat162* dh = (__nv_bfloat162*)(g_Fih + base);
        #pragma unroll
        for (int c4 = 0; c4 < 16; c4++) {
            float4 o;
            o.x = (v[c4 * 4 + 0] - mu) * rstd * gs[c4 * 4 + 0] + bs[c4 * 4 + 0];
            o.y = (v[c4 * 4 + 1] - mu) * rstd * gs[c4 * 4 + 1] + bs[c4 * 4 + 1];
            o.z = (v[c4 * 4 + 2] - mu) * rstd * gs[c4 * 4 + 2] + bs[c4 * 4 + 2];
            o.w = (v[c4 * 4 + 3] - mu) * rstd * gs[c4 * 4 + 3] + bs[c4 * 4 + 3];
            *(float4*)(dst + c4 * 4) = o;
            dh[c4 * 2 + 0] = __nv_bfloat162(__float2bfloat16(o.x), __float2bfloat16(o.y));
            dh[c4 * 2 + 1] = __nv_bfloat162(__float2bfloat16(o.z), __float2bfloat16(o.w));
        }
    }
}

// ---------------------------------------------------------------------------
// mv_kernel (single bf16): per b, V = Fi_b @ wv via wmma; mV = mean_d |V|.
// ---------------------------------------------------------------------------
#define MV_A_STR 72
#define MV_APL   (128 * MV_A_STR * 2)        // 18432 B
#define MV_B_STR 136
#define MV_BPL   (64 * MV_B_STR * 2)         // 17408 B
#define MV_C_STR 132
#define MV_SMEM  (MV_APL + 2 * MV_BPL + 128 * MV_C_STR * 4)  // 120832 B

__global__ __launch_bounds__(256, 1) void mv_kernel()
{
    extern __shared__ char smem[];
    const int tid = threadIdx.x;
    const int wid = tid >> 5;
    const int b   = blockIdx.x;

    char* Afi = smem;                       // Fi hi plane
    char* Bw  = smem + MV_APL;              // wv hi chunks (double buffered)
    float* Cs = (float*)(Bw + 2 * MV_BPL);

    const uint32_t afi_u = (uint32_t)__cvta_generic_to_shared(Afi);
    const uint32_t bw_u  = (uint32_t)__cvta_generic_to_shared(Bw);

    // Load Fi hi: 128 rows x 8 chunks(16B) = 1024; 4/thread
    {
        const size_t base = (size_t)b * NF_ * D_;
        #pragma unroll
        for (int rep = 0; rep < 4; rep++) {
            const int i = tid + rep * 256;
            const int r = i >> 3;
            const int c = i & 7;
            cp_async16(afi_u + r * (MV_A_STR * 2) + c * 16, g_Fih + base + r * 64 + c * 8);
        }
    }
    auto load_b = [&](int nc, int buf) {
        #pragma unroll
        for (int rep = 0; rep < 4; rep++) {
            const int i = tid + rep * 256;
            const int kk = i >> 4;
            const int c  = i & 15;
            cp_async16(bw_u + buf * MV_BPL + kk * (MV_B_STR * 2) + c * 16,
                       g_wvh + kk * 512 + nc * 128 + c * 8);
        }
        asm volatile("cp.async.commit_group;");
    };
    load_b(0, 0);

    const int warp_m = wid & 3;
    const int warp_n = wid >> 2;

    for (int nc = 0; nc < 4; nc++) {
        const int buf = nc & 1;
        if (nc + 1 < 4) {
            load_b(nc + 1, buf ^ 1);
            asm volatile("cp.async.wait_group 1;");
        } else {
            asm volatile("cp.async.wait_group 0;");
        }
        __syncthreads();

        wmma::fragment<wmma::accumulator, 16, 16, 16, float> acc[2][4];
        #pragma unroll
        for (int fm = 0; fm < 2; fm++)
            #pragma unroll
            for (int fn = 0; fn < 4; fn++)
                wmma::fill_fragment(acc[fm][fn], 0.0f);

        const __nv_bfloat16* As = (const __nv_bfloat16*)Afi;
        const __nv_bfloat16* Bs = (const __nv_bfloat16*)(Bw + buf * MV_BPL);

        #pragma unroll
        for (int kk = 0; kk < 64; kk += 16) {
            wmma::fragment<wmma::matrix_a, 16, 16, 16, __nv_bfloat16, wmma::row_major> af[2];
            #pragma unroll
            for (int fm = 0; fm < 2; fm++)
                wmma::load_matrix_sync(af[fm], As + (warp_m * 32 + fm * 16) * MV_A_STR + kk, MV_A_STR);
            #pragma unroll
            for (int fn = 0; fn < 4; fn++) {
                wmma::fragment<wmma::matrix_b, 16, 16, 16, __nv_bfloat16, wmma::row_major> bf;
                wmma::load_matrix_sync(bf, Bs + kk * MV_B_STR + warp_n * 64 + fn * 16, MV_B_STR);
                #pragma unroll
                for (int fm = 0; fm < 2; fm++)
                    wmma::mma_sync(acc[fm][fn], af[fm], bf, acc[fm][fn]);
            }
        }
        #pragma unroll
        for (int fm = 0; fm < 2; fm++)
            #pragma unroll
            for (int fn = 0; fn < 4; fn++)
                wmma::store_matrix_sync(Cs + (warp_m * 32 + fm * 16) * MV_C_STR + warp_n * 64 + fn * 16,
                                        acc[fm][fn], MV_C_STR, wmma::mem_row_major);
        __syncthreads();

        // thread-per-(m, head-half): 256 threads = 128 rows x 2 halves
        {
            const int hh = tid >> 7;
            const int m  = tid & 127;
            const float* rowp = Cs + m * MV_C_STR + hh * 64;
            float s = 0.f;
            #pragma unroll 16
            for (int c = 0; c < 64; c++)
                s += fabsf(rowp[c]);
            g_mv[((size_t)b * 8 + nc * 2 + hh) * 128 + m] = s * (1.f / 64.f);
        }
        __syncthreads();
    }
}

// ---------------------------------------------------------------------------
// attn_lite (round-7 proven): logits, softmax, gvec = A^T Fi, S = gvec@wv
// ---------------------------------------------------------------------------
#define FSTR 129
#define LITE_SMEM ((64 * FSTR + 512 + 1024 + 1024 + 512) * 4)

__global__ __launch_bounds__(256, 1) void attn_lite_kernel(
    const float* __restrict__ wv,
    float* __restrict__ out)
{
    extern __shared__ float sm[];
    float* Fst  = sm;
    float* qts  = Fst + 64 * FSTR;
    float* mvs  = qts + 512;
    float* Aw   = mvs + 1024;
    float* gv   = Aw + 1024;

    const int tid = threadIdx.x;
    const int b   = blockIdx.x;

    {
        const float* Fi = g_Fi + (size_t)b * NF_ * D_;
        const int m = tid & 127, half = tid >> 7;
        #pragma unroll
        for (int v = 0; v < 8; v++) {
            const int vv = half * 8 + v;
            float4 fv = *(const float4*)(Fi + m * 64 + vv * 4);
            Fst[(vv * 4 + 0) * FSTR + m] = fv.x;
            Fst[(vv * 4 + 1) * FSTR + m] = fv.y;
            Fst[(vv * 4 + 2) * FSTR + m] = fv.z;
            Fst[(vv * 4 + 3) * FSTR + m] = fv.w;
        }
    }
    #pragma unroll
    for (int r = 0; r < 2; r++)
        qts[tid + r * 256] = g_qt[(size_t)b * 512 + tid + r * 256];
    #pragma unroll
    for (int r = 0; r < 4; r++)
        mvs[tid + r * 256] = g_mv[(size_t)b * 1024 + tid + r * 256];
    __syncthreads();

    #pragma unroll
    for (int r = 0; r < 4; r++) {
        const int idx = tid + r * 256;
        const int h = idx >> 7, m = idx & 127;
        float s = 0.f;
        #pragma unroll 8
        for (int k = 0; k < 64; k++)
            s = fmaf(Fst[k * FSTR + m], qts[h * 64 + k], s);
        Aw[idx] = mvs[idx] * s * 0.125f;
    }
    __syncthreads();

    {
        const int w = tid >> 5, lane = tid & 31;
        float v0 = Aw[w * 128 + lane];
        float v1 = Aw[w * 128 + lane + 32];
        float v2 = Aw[w * 128 + lane + 64];
        float v3 = Aw[w * 128 + lane + 96];
        float mx = fmaxf(fmaxf(v0, v1), fmaxf(v2, v3));
        #pragma unroll
        for (int off = 16; off >= 1; off >>= 1)
            mx = fmaxf(mx, __shfl_xor_sync(0xffffffffu, mx, off));
        v0 = expf(v0 - mx); v1 = expf(v1 - mx);
        v2 = expf(v2 - mx); v3 = expf(v3 - mx);
        float se = v0 + v1 + v2 + v3;
        #pragma unroll
        for (int off = 16; off >= 1; off >>= 1)
            se += __shfl_xor_sync(0xffffffffu, se, off);
        const float inv = 1.f / se;
        Aw[w * 128 + lane]      = v0 * inv;
        Aw[w * 128 + lane + 32] = v1 * inv;
        Aw[w * 128 + lane + 64] = v2 * inv;
        Aw[w * 128 + lane + 96] = v3 * inv;
    }
    __syncthreads();

    #pragma unroll
    for (int r = 0; r < 2; r++) {
        const int idx = tid + r * 256;
        const int h = idx >> 6, d = idx & 63;
        float s = 0.f;
        #pragma unroll 8
        for (int m = 0; m < 128; m++)
            s = fmaf(Aw[h * 128 + m], Fst[d * FSTR + m], s);
        gv[idx] = s;
    }
    __syncthreads();

    #pragma unroll
    for (int r = 0; r < 2; r++) {
        const int idx = tid + r * 256;
        const int h = idx >> 6, d = idx & 63;
        float s = 0.f;
        #pragma unroll 8
        for (int k = 0; k < 64; k++)
            s = fmaf(gv[h * 64 + k], wv[(size_t)k * 512 + h * 64 + d], s);
        out[(size_t)b * 512 + idx] = s;
    }
}

// ---------------------------------------------------------------------------
// Launch
// ---------------------------------------------------------------------------
extern "C" void kernel_launch(void* const* d_in, const int* in_sizes, int n_in,
                              void* d_out, int out_size)
{
    const float* feature  = (const float*)d_in[0];
    const float* hidden   = (const float*)d_in[1];
    const float* command  = (const float*)d_in[2];
    const float* wz       = (const float*)d_in[3];
    const float* wh       = (const float*)d_in[4];
    const float* wq       = (const float*)d_in[5];
    const float* wk       = (const float*)d_in[6];
    const float* wv       = (const float*)d_in[7];
    const float* ln_gamma = (const float*)d_in[8];
    const float* ln_beta  = (const float*)d_in[9];
    float* out = (float*)d_out;

    cudaFuncSetAttribute(proj_wmma_kernel, cudaFuncAttributeMaxDynamicSharedMemorySize, PROJ_SMEM);
    cudaFuncSetAttribute(mv_kernel, cudaFuncAttributeMaxDynamicSharedMemorySize, MV_SMEM);
    cudaFuncSetAttribute(attn_lite_kernel, cudaFuncAttributeMaxDynamicSharedMemorySize, LITE_SMEM);
    cudaFuncSetAttribute(qt_kernel, cudaFuncAttributeMaxDynamicSharedMemorySize, QT_SMEM);

    convert_kernel<<<1024, 256>>>(feature, 0, 2097152 / 4);
    convert_kernel<<<1024, 256>>>(hidden,  1, 1048576 / 4);
    convert_kernel<<<2048, 256>>>(wz,      2, 8388608 / 4);
    convert_kernel<<<2048, 256>>>(wh,      3, 4194304 / 4);
    convert_kernel<<<32,   256>>>(wv,      4, 32768 / 4);

    wqt_kernel<<<256, 256>>>(wq, wk);
    qt_kernel<<<dim3(32, 4), 256, QT_SMEM>>>(command);

    proj_wmma_kernel<<<dim3(8, 32), 256, PROJ_SMEM>>>(ln_gamma, ln_beta, 0, 2048, 0);
    proj_wmma_kernel<<<dim3(8, 32), 256, PROJ_SMEM>>>(ln_gamma, ln_beta, 1, 1024, 64);

    mv_kernel<<<B_SZ, 256, MV_SMEM>>>();
    attn_lite_kernel<<<B_SZ, 256, LITE_SMEM>>>(wv, out);
}

// round 10
// speedup vs baseline: 3.0122x; 1.3671x over previous
#include <cuda_runtime.h>
#include <cuda_fp16.h>
#include <mma.h>
#include <cstdint>
#include <stdint.h>
#include <math.h>

using namespace nvcuda;

// Problem constants
#define B_SZ   1024
#define NF_    128
#define D_     64
#define H_     8
#define MCOLS  4096
#define LN_EPS 1e-5f

// ---------------------------------------------------------------------------
// Scratch (__device__ globals)
// ---------------------------------------------------------------------------
__device__ float g_Fi[(size_t)B_SZ * NF_ * D_];   // [b][m][d] post-LN features (fp32)
__device__ float g_qt[(size_t)B_SZ * H_ * D_];    // [b][h][d'] folded K-query
__device__ float g_mv[(size_t)B_SZ * H_ * NF_];   // [b][h][m]  mean |V|
__device__ float g_wqt[128 * 512];                // [e][h*64+d'] folded wq/wk

// fp16 planes: activations split (hi+lo), weights single
__device__ __half g_fh[2097152], g_fl[2097152];   // feature 1024x2048 (split)
__device__ __half g_hh[1048576], g_hl[1048576];   // hidden  1024x1024 (split)
__device__ __half g_wzh[8388608];                 // wz      2048x4096 (single)
__device__ __half g_whh[4194304];                 // wh      1024x4096 (single)
__device__ __half g_wvh[32768];                   // wv      64x512    (single)
__device__ __half g_Fih[8388608];                 // Fi      [b][m][d] (single)

__device__ __forceinline__ float gelu_exact(float x) {
    return 0.5f * x * (1.0f + erff(x * 0.70710678118654752f));
}

__device__ __forceinline__ void cp_async16(uint32_t dst, const void* src) {
    asm volatile("cp.async.cg.shared.global [%0], [%1], 16;\n"
                 :: "r"(dst), "l"(__cvta_generic_to_global(src)));
}

// ---------------------------------------------------------------------------
// Converts: split (hi+lo) and single-plane fp16
// ---------------------------------------------------------------------------
__global__ __launch_bounds__(256) void convert_split_kernel(const float* __restrict__ src,
                                                            int sel, int n4)
{
    __half *hi, *lo;
    if (sel == 0) { hi = g_fh; lo = g_fl; }
    else          { hi = g_hh; lo = g_hl; }
    const int stride = gridDim.x * blockDim.x;
    for (int j = blockIdx.x * blockDim.x + threadIdx.x; j < n4; j += stride) {
        float4 v = ((const float4*)src)[j];
        __half h0 = __float2half(v.x);
        __half h1 = __float2half(v.y);
        __half h2 = __float2half(v.z);
        __half h3 = __float2half(v.w);
        ((__half2*)hi)[j * 2 + 0] = __halves2half2(h0, h1);
        ((__half2*)hi)[j * 2 + 1] = __halves2half2(h2, h3);
        __half l0 = __float2half(v.x - __half2float(h0));
        __half l1 = __float2half(v.y - __half2float(h1));
        __half l2 = __float2half(v.z - __half2float(h2));
        __half l3 = __float2half(v.w - __half2float(h3));
        ((__half2*)lo)[j * 2 + 0] = __halves2half2(l0, l1);
        ((__half2*)lo)[j * 2 + 1] = __halves2half2(l2, l3);
    }
}

__global__ __launch_bounds__(256) void convert_single_kernel(const float* __restrict__ src,
                                                             int sel, int n4)
{
    __half* hi;
    if (sel == 2)      hi = g_wzh;
    else if (sel == 3) hi = g_whh;
    else               hi = g_wvh;
    const int stride = gridDim.x * blockDim.x;
    for (int j = blockIdx.x * blockDim.x + threadIdx.x; j < n4; j += stride) {
        float4 v = ((const float4*)src)[j];
        ((__half2*)hi)[j * 2 + 0] = __halves2half2(__float2half(v.x), __float2half(v.y));
        ((__half2*)hi)[j * 2 + 1] = __halves2half2(__float2half(v.z), __float2half(v.w));
    }
}

// ---------------------------------------------------------------------------
// wqt_kernel: Wqt[e, h*64+dp] = sum_d wq[e, h*64+d] * wk[dp, h*64+d]
// ---------------------------------------------------------------------------
__global__ __launch_bounds__(256) void wqt_kernel(
    const float* __restrict__ wq,
    const float* __restrict__ wk)
{
    const int idx = blockIdx.x * 256 + threadIdx.x;
    const int e  = idx >> 9;
    const int j  = idx & 511;
    const int h  = j >> 6;
    const int dp = j & 63;
    float s = 0.f;
    const float* wqp = wq + (size_t)e * 512 + h * 64;
    const float* wkp = wk + (size_t)dp * 512 + h * 64;
    #pragma unroll 8
    for (int d = 0; d < 64; d++)
        s = fmaf(wqp[d], wkp[d], s);
    g_wqt[e * 512 + j] = s;
}

// ---------------------------------------------------------------------------
// qt_kernel: qt = command @ Wqt
// ---------------------------------------------------------------------------
#define QT_WSTR 132
#define QT_SMEM ((32 * 128 + 128 * QT_WSTR) * 4)

__global__ __launch_bounds__(256) void qt_kernel(const float* __restrict__ command)
{
    extern __shared__ float qsm[];
    float* cmds = qsm;
    float* Wq   = qsm + 32 * 128;

    const int tid = threadIdx.x;
    const int bb  = blockIdx.x * 32;
    const int jt  = blockIdx.y * 128;

    #pragma unroll
    for (int rep = 0; rep < 4; rep++) {
        const int i = tid + rep * 256;
        const int row = i >> 5, c4 = i & 31;
        float4 v = *(const float4*)(command + (size_t)(bb + row) * 128 + c4 * 4);
        *(float4*)(cmds + row * 128 + c4 * 4) = v;
    }
    #pragma unroll
    for (int rep = 0; rep < 16; rep++) {
        const int i = tid + rep * 256;
        const int row = i >> 5, c4 = i & 31;
        float4 v = *(const float4*)(g_wqt + row * 512 + jt + c4 * 4);
        *(float4*)(Wq + row * QT_WSTR + c4 * 4) = v;
    }
    __syncthreads();

    const int r = tid >> 3;
    const int g = tid & 7;
    float acc[16];
    #pragma unroll
    for (int c = 0; c < 16; c++) acc[c] = 0.f;

    #pragma unroll 4
    for (int k = 0; k < 128; k++) {
        const float a = cmds[r * 128 + k];
        const float* wp = Wq + k * QT_WSTR + g * 16;
        #pragma unroll
        for (int c = 0; c < 16; c++)
            acc[c] = fmaf(a, wp[c], acc[c]);
    }

    float* dst = g_qt + (size_t)(bb + r) * 512 + jt + g * 16;
    #pragma unroll
    for (int c4 = 0; c4 < 4; c4++)
        *(float4*)(dst + c4 * 4) = make_float4(acc[c4 * 4], acc[c4 * 4 + 1],
                                               acc[c4 * 4 + 2], acc[c4 * 4 + 3]);
}

// ---------------------------------------------------------------------------
// wmma fp16 2-pass projection GEMM + GELU + LayerNorm
//   a = ah + al (fp16 split, exact); b = fp16 single. acc += ah*b; acc += al*b.
// ---------------------------------------------------------------------------
#define KC     32
#define A_STR  40
#define B_STR  136
#define C_STR  140
#define A_PLANE (128 * A_STR * 2)                 // 10240 B
#define B_PLANE (KC * B_STR * 2)                  // 8704 B
#define STAGE_B (2 * A_PLANE + B_PLANE)           // 29184 B
#define SMEM_GB 512
#define C_BYTES (128 * C_STR * 4)                 // 71680 B
#define PROJ_SMEM (SMEM_GB + C_BYTES)             // 72192 B  (> 512 + 2*STAGE_B)

__global__ __launch_bounds__(256, 2) void proj_wmma_kernel(
    const float* __restrict__ gamma,
    const float* __restrict__ beta,
    int sel, int K, int fbase)
{
    extern __shared__ char smem[];
    const int tid = threadIdx.x;
    const int wid = tid >> 5;

    const __half *Ah_g, *Al_g, *Wh_g;
    if (sel == 0) { Ah_g = g_fh; Al_g = g_fl; Wh_g = g_wzh; }
    else          { Ah_g = g_hh; Al_g = g_hl; Wh_g = g_whh; }

    const int bm = blockIdx.x * 128;
    const int bn = blockIdx.y * 128;

    if (tid < 64) {
        *(float*)(smem + tid * 4)       = gamma[tid];
        *(float*)(smem + 256 + tid * 4) = beta[tid];
    }

    const int warp_m = wid & 3;
    const int warp_n = wid >> 2;

    wmma::fragment<wmma::accumulator, 16, 16, 16, float> acc[2][4];
    #pragma unroll
    for (int fm = 0; fm < 2; fm++)
        #pragma unroll
        for (int fn = 0; fn < 4; fn++)
            wmma::fill_fragment(acc[fm][fn], 0.0f);

    const int nK = K / KC;

    auto load_stage = [&](int it, int buf) {
        const int kt = it * KC;
        char* stg = smem + SMEM_GB + buf * STAGE_B;
        const uint32_t stg_u = (uint32_t)__cvta_generic_to_shared(stg);
        // A: 2 planes x 128 rows x 4 chunks(16B) = 1024; 4/thread
        #pragma unroll
        for (int rep = 0; rep < 4; rep++) {
            const int i = tid + rep * 256;
            const int plane = i >> 9;
            const int r     = (i >> 2) & 127;
            const int c     = i & 3;
            const __half* gp = (plane ? Al_g : Ah_g)
                             + (size_t)(bm + r) * K + kt + c * 8;
            cp_async16(stg_u + plane * A_PLANE + r * (A_STR * 2) + c * 16, gp);
        }
        // B: 1 plane x 32 k-rows x 16 chunks = 512; 2/thread
        #pragma unroll
        for (int rep = 0; rep < 2; rep++) {
            const int i = tid + rep * 256;
            const int kk = i >> 4;
            const int c  = i & 15;
            const __half* gp = Wh_g + (size_t)(kt + kk) * MCOLS + bn + c * 8;
            cp_async16(stg_u + 2 * A_PLANE + kk * (B_STR * 2) + c * 16, gp);
        }
        asm volatile("cp.async.commit_group;");
    };

    load_stage(0, 0);

    for (int it = 0; it < nK; it++) {
        const int buf = it & 1;
        if (it + 1 < nK) {
            load_stage(it + 1, buf ^ 1);
            asm volatile("cp.async.wait_group 1;");
        } else {
            asm volatile("cp.async.wait_group 0;");
        }
        __syncthreads();

        const char* stg = smem + SMEM_GB + buf * STAGE_B;
        const __half* As_hi = (const __half*)(stg);
        const __half* As_lo = (const __half*)(stg + A_PLANE);
        const __half* Bs    = (const __half*)(stg + 2 * A_PLANE);

        #pragma unroll
        for (int kk = 0; kk < KC; kk += 16) {
            wmma::fragment<wmma::matrix_a, 16, 16, 16, __half, wmma::row_major> ah[2], al[2];
            #pragma unroll
            for (int fm = 0; fm < 2; fm++) {
                const int rr = warp_m * 32 + fm * 16;
                wmma::load_matrix_sync(ah[fm], As_hi + rr * A_STR + kk, A_STR);
                wmma::load_matrix_sync(al[fm], As_lo + rr * A_STR + kk, A_STR);
            }
            #pragma unroll
            for (int fn = 0; fn < 4; fn++) {
                wmma::fragment<wmma::matrix_b, 16, 16, 16, __half, wmma::row_major> bf;
                wmma::load_matrix_sync(bf, Bs + kk * B_STR + warp_n * 64 + fn * 16, B_STR);
                #pragma unroll
                for (int fm = 0; fm < 2; fm++) {
                    wmma::mma_sync(acc[fm][fn], ah[fm], bf, acc[fm][fn]);
                    wmma::mma_sync(acc[fm][fn], al[fm], bf, acc[fm][fn]);
                }
            }
        }
        __syncthreads();
    }

    // ---- Epilogue
    float* Cs = (float*)(smem + SMEM_GB);
    #pragma unroll
    for (int fm = 0; fm < 2; fm++)
        #pragma unroll
        for (int fn = 0; fn < 4; fn++)
            wmma::store_matrix_sync(Cs + (warp_m * 32 + fm * 16) * C_STR + warp_n * 64 + fn * 16,
                                    acc[fm][fn], C_STR, wmma::mem_row_major);
    __syncthreads();

    const float* gs = (const float*)(smem);
    const float* bs = (const float*)(smem + 256);
    {
        const int row = tid >> 1;
        const int grp = tid & 1;
        const float* src = Cs + row * C_STR + grp * 64;

        float v[64];
        float s = 0.f, sq = 0.f;
        #pragma unroll
        for (int c = 0; c < 64; c++) {
            float x = gelu_exact(src[c]);
            v[c] = x;
            s += x; sq += x * x;
        }
        const float mu   = s * (1.f / 64.f);
        const float var  = sq * (1.f / 64.f) - mu * mu;
        const float rstd = rsqrtf(var + LN_EPS);

        const int f = fbase + (bn >> 6) + grp;
        const size_t base = ((size_t)(bm + row) * NF_ + f) * D_;
        float* dst = g_Fi + base;
        __half2* dh = (__half2*)(g_Fih + base);
        #pragma unroll
        for (int c4 = 0; c4 < 16; c4++) {
            float4 o;
            o.x = (v[c4 * 4 + 0] - mu) * rstd * gs[c4 * 4 + 0] + bs[c4 * 4 + 0];
            o.y = (v[c4 * 4 + 1] - mu) * rstd * gs[c4 * 4 + 1] + bs[c4 * 4 + 1];
            o.z = (v[c4 * 4 + 2] - mu) * rstd * gs[c4 * 4 + 2] + bs[c4 * 4 + 2];
            o.w = (v[c4 * 4 + 3] - mu) * rstd * gs[c4 * 4 + 3] + bs[c4 * 4 + 3];
            *(float4*)(dst + c4 * 4) = o;
            dh[c4 * 2 + 0] = __halves2half2(__float2half(o.x), __float2half(o.y));
            dh[c4 * 2 + 1] = __halves2half2(__float2half(o.z), __float2half(o.w));
        }
    }
}

// ---------------------------------------------------------------------------
// mv_kernel (fp16 single): per b, V = Fi_b @ wv via wmma; mV = mean_d |V|.
// ---------------------------------------------------------------------------
#define MV_A_STR 72
#define MV_APL   (128 * MV_A_STR * 2)
#define MV_B_STR 136
#define MV_BPL   (64 * MV_B_STR * 2)
#define MV_C_STR 132
#define MV_SMEM  (MV_APL + 2 * MV_BPL + 128 * MV_C_STR * 4)

__global__ __launch_bounds__(256, 1) void mv_kernel()
{
    extern __shared__ char smem[];
    const int tid = threadIdx.x;
    const int wid = tid >> 5;
    const int b   = blockIdx.x;

    char* Afi = smem;
    char* Bw  = smem + MV_APL;
    float* Cs = (float*)(Bw + 2 * MV_BPL);

    const uint32_t afi_u = (uint32_t)__cvta_generic_to_shared(Afi);
    const uint32_t bw_u  = (uint32_t)__cvta_generic_to_shared(Bw);

    {
        const size_t base = (size_t)b * NF_ * D_;
        #pragma unroll
        for (int rep = 0; rep < 4; rep++) {
            const int i = tid + rep * 256;
            const int r = i >> 3;
            const int c = i & 7;
            cp_async16(afi_u + r * (MV_A_STR * 2) + c * 16, g_Fih + base + r * 64 + c * 8);
        }
    }
    auto load_b = [&](int nc, int buf) {
        #pragma unroll
        for (int rep = 0; rep < 4; rep++) {
            const int i = tid + rep * 256;
            const int kk = i >> 4;
            const int c  = i & 15;
            cp_async16(bw_u + buf * MV_BPL + kk * (MV_B_STR * 2) + c * 16,
                       g_wvh + kk * 512 + nc * 128 + c * 8);
        }
        asm volatile("cp.async.commit_group;");
    };
    load_b(0, 0);

    const int warp_m = wid & 3;
    const int warp_n = wid >> 2;

    for (int nc = 0; nc < 4; nc++) {
        const int buf = nc & 1;
        if (nc + 1 < 4) {
            load_b(nc + 1, buf ^ 1);
            asm volatile("cp.async.wait_group 1;");
        } else {
            asm volatile("cp.async.wait_group 0;");
        }
        __syncthreads();

        wmma::fragment<wmma::accumulator, 16, 16, 16, float> acc[2][4];
        #pragma unroll
        for (int fm = 0; fm < 2; fm++)
            #pragma unroll
            for (int fn = 0; fn < 4; fn++)
                wmma::fill_fragment(acc[fm][fn], 0.0f);

        const __half* As = (const __half*)Afi;
        const __half* Bs = (const __half*)(Bw + buf * MV_BPL);

        #pragma unroll
        for (int kk = 0; kk < 64; kk += 16) {
            wmma::fragment<wmma::matrix_a, 16, 16, 16, __half, wmma::row_major> af[2];
            #pragma unroll
            for (int fm = 0; fm < 2; fm++)
                wmma::load_matrix_sync(af[fm], As + (warp_m * 32 + fm * 16) * MV_A_STR + kk, MV_A_STR);
            #pragma unroll
            for (int fn = 0; fn < 4; fn++) {
                wmma::fragment<wmma::matrix_b, 16, 16, 16, __half, wmma::row_major> bf;
                wmma::load_matrix_sync(bf, Bs + kk * MV_B_STR + warp_n * 64 + fn * 16, MV_B_STR);
                #pragma unroll
                for (int fm = 0; fm < 2; fm++)
                    wmma::mma_sync(acc[fm][fn], af[fm], bf, acc[fm][fn]);
            }
        }
        #pragma unroll
        for (int fm = 0; fm < 2; fm++)
            #pragma unroll
            for (int fn = 0; fn < 4; fn++)
                wmma::store_matrix_sync(Cs + (warp_m * 32 + fm * 16) * MV_C_STR + warp_n * 64 + fn * 16,
                                        acc[fm][fn], MV_C_STR, wmma::mem_row_major);
        __syncthreads();

        {
            const int hh = tid >> 7;
            const int m  = tid & 127;
            const float* rowp = Cs + m * MV_C_STR + hh * 64;
            float s = 0.f;
            #pragma unroll 16
            for (int c = 0; c < 64; c++)
                s += fabsf(rowp[c]);
            g_mv[((size_t)b * 8 + nc * 2 + hh) * 128 + m] = s * (1.f / 64.f);
        }
        __syncthreads();
    }
}

// ---------------------------------------------------------------------------
// attn_lite (proven): logits, softmax, gvec = A^T Fi, S = gvec@wv
// ---------------------------------------------------------------------------
#define FSTR 129
#define LITE_SMEM ((64 * FSTR + 512 + 1024 + 1024 + 512) * 4)

__global__ __launch_bounds__(256, 1) void attn_lite_kernel(
    const float* __restrict__ wv,
    float* __restrict__ out)
{
    extern __shared__ float sm[];
    float* Fst  = sm;
    float* qts  = Fst + 64 * FSTR;
    float* mvs  = qts + 512;
    float* Aw   = mvs + 1024;
    float* gv   = Aw + 1024;

    const int tid = threadIdx.x;
    const int b   = blockIdx.x;

    {
        const float* Fi = g_Fi + (size_t)b * NF_ * D_;
        const int m = tid & 127, half = tid >> 7;
        #pragma unroll
        for (int v = 0; v < 8; v++) {
            const int vv = half * 8 + v;
            float4 fv = *(const float4*)(Fi + m * 64 + vv * 4);
            Fst[(vv * 4 + 0) * FSTR + m] = fv.x;
            Fst[(vv * 4 + 1) * FSTR + m] = fv.y;
            Fst[(vv * 4 + 2) * FSTR + m] = fv.z;
            Fst[(vv * 4 + 3) * FSTR + m] = fv.w;
        }
    }
    #pragma unroll
    for (int r = 0; r < 2; r++)
        qts[tid + r * 256] = g_qt[(size_t)b * 512 + tid + r * 256];
    #pragma unroll
    for (int r = 0; r < 4; r++)
        mvs[tid + r * 256] = g_mv[(size_t)b * 1024 + tid + r * 256];
    __syncthreads();

    #pragma unroll
    for (int r = 0; r < 4; r++) {
        const int idx = tid + r * 256;
        const int h = idx >> 7, m = idx & 127;
        float s = 0.f;
        #pragma unroll 8
        for (int k = 0; k < 64; k++)
            s = fmaf(Fst[k * FSTR + m], qts[h * 64 + k], s);
        Aw[idx] = mvs[idx] * s * 0.125f;
    }
    __syncthreads();

    {
        const int w = tid >> 5, lane = tid & 31;
        float v0 = Aw[w * 128 + lane];
        float v1 = Aw[w * 128 + lane + 32];
        float v2 = Aw[w * 128 + lane + 64];
        float v3 = Aw[w * 128 + lane + 96];
        float mx = fmaxf(fmaxf(v0, v1), fmaxf(v2, v3));
        #pragma unroll
        for (int off = 16; off >= 1; off >>= 1)
            mx = fmaxf(mx, __shfl_xor_sync(0xffffffffu, mx, off));
        v0 = expf(v0 - mx); v1 = expf(v1 - mx);
        v2 = expf(v2 - mx); v3 = expf(v3 - mx);
        float se = v0 + v1 + v2 + v3;
        #pragma unroll
        for (int off = 16; off >= 1; off >>= 1)
            se += __shfl_xor_sync(0xffffffffu, se, off);
        const float inv = 1.f / se;
        Aw[w * 128 + lane]      = v0 * inv;
        Aw[w * 128 + lane + 32] = v1 * inv;
        Aw[w * 128 + lane + 64] = v2 * inv;
        Aw[w * 128 + lane + 96] = v3 * inv;
    }
    __syncthreads();

    #pragma unroll
    for (int r = 0; r < 2; r++) {
        const int idx = tid + r * 256;
        const int h = idx >> 6, d = idx & 63;
        float s = 0.f;
        #pragma unroll 8
        for (int m = 0; m < 128; m++)
            s = fmaf(Aw[h * 128 + m], Fst[d * FSTR + m], s);
        gv[idx] = s;
    }
    __syncthreads();

    #pragma unroll
    for (int r = 0; r < 2; r++) {
        const int idx = tid + r * 256;
        const int h = idx >> 6, d = idx & 63;
        float s = 0.f;
        #pragma unroll 8
        for (int k = 0; k < 64; k++)
            s = fmaf(gv[h * 64 + k], wv[(size_t)k * 512 + h * 64 + d], s);
        out[(size_t)b * 512 + idx] = s;
    }
}

// ---------------------------------------------------------------------------
// Launch
// ---------------------------------------------------------------------------
extern "C" void kernel_launch(void* const* d_in, const int* in_sizes, int n_in,
                              void* d_out, int out_size)
{
    const float* feature  = (const float*)d_in[0];
    const float* hidden   = (const float*)d_in[1];
    const float* command  = (const float*)d_in[2];
    const float* wz       = (const float*)d_in[3];
    const float* wh       = (const float*)d_in[4];
    const float* wq       = (const float*)d_in[5];
    const float* wk       = (const float*)d_in[6];
    const float* wv       = (const float*)d_in[7];
    const float* ln_gamma = (const float*)d_in[8];
    const float* ln_beta  = (const float*)d_in[9];
    float* out = (float*)d_out;

    cudaFuncSetAttribute(proj_wmma_kernel, cudaFuncAttributeMaxDynamicSharedMemorySize, PROJ_SMEM);
    cudaFuncSetAttribute(mv_kernel, cudaFuncAttributeMaxDynamicSharedMemorySize, MV_SMEM);
    cudaFuncSetAttribute(attn_lite_kernel, cudaFuncAttributeMaxDynamicSharedMemorySize, LITE_SMEM);
    cudaFuncSetAttribute(qt_kernel, cudaFuncAttributeMaxDynamicSharedMemorySize, QT_SMEM);

    convert_split_kernel<<<1024, 256>>>(feature, 0, 2097152 / 4);
    convert_split_kernel<<<1024, 256>>>(hidden,  1, 1048576 / 4);
    convert_single_kernel<<<2048, 256>>>(wz,     2, 8388608 / 4);
    convert_single_kernel<<<1024, 256>>>(wh,     3, 4194304 / 4);
    convert_single_kernel<<<32,   256>>>(wv,     4, 32768 / 4);

    wqt_kernel<<<256, 256>>>(wq, wk);
    qt_kernel<<<dim3(32, 4), 256, QT_SMEM>>>(command);

    proj_wmma_kernel<<<dim3(8, 32), 256, PROJ_SMEM>>>(ln_gamma, ln_beta, 0, 2048, 0);
    proj_wmma_kernel<<<dim3(8, 32), 256, PROJ_SMEM>>>(ln_gamma, ln_beta, 1, 1024, 64);

    mv_kernel<<<B_SZ, 256, MV_SMEM>>>();
    attn_lite_kernel<<<B_SZ, 256, LITE_SMEM>>>(wv, out);
}

// round 11
// speedup vs baseline: 3.7176x; 1.2342x over previous
#include <cuda_runtime.h>
#include <cuda_fp16.h>
#include <mma.h>
#include <cstdint>
#include <stdint.h>
#include <math.h>

using namespace nvcuda;

// Problem constants
#define B_SZ   1024
#define NF_    128
#define D_     64
#define H_     8
#define MCOLS  4096
#define LN_EPS 1e-5f

// ---------------------------------------------------------------------------
// Scratch (__device__ globals)
// ---------------------------------------------------------------------------
__device__ float g_Fi[(size_t)B_SZ * NF_ * D_];   // [b][m][d] post-LN features (fp32)
__device__ float g_qt[(size_t)B_SZ * H_ * D_];    // [b][h][d'] folded K-query
__device__ float g_mv[(size_t)B_SZ * H_ * NF_];   // [b][h][m]  mean |V|
__device__ float g_wqt[128 * 512];                // [e][h*64+d'] folded wq/wk

// fp16 single planes (precision budget: weights+activations single -> ~3.4e-4)
__device__ __half g_fh[2097152];                  // feature 1024x2048
__device__ __half g_hh[1048576];                  // hidden  1024x1024
__device__ __half g_wzh[8388608];                 // wz      2048x4096
__device__ __half g_whh[4194304];                 // wh      1024x4096
__device__ __half g_wvh[32768];                   // wv      64x512
__device__ __half g_Fih[8388608];                 // Fi      [b][m][d]

__device__ __forceinline__ float gelu_exact(float x) {
    return 0.5f * x * (1.0f + erff(x * 0.70710678118654752f));
}

__device__ __forceinline__ void cp_async16(uint32_t dst, const void* src) {
    asm volatile("cp.async.cg.shared.global [%0], [%1], 16;\n"
                 :: "r"(dst), "l"(__cvta_generic_to_global(src)));
}

// ---------------------------------------------------------------------------
// Convert fp32 -> fp16 single plane
// ---------------------------------------------------------------------------
__global__ __launch_bounds__(256) void convert_single_kernel(const float* __restrict__ src,
                                                             int sel, int n4)
{
    __half* hi;
    switch (sel) {
        case 0:  hi = g_fh;  break;
        case 1:  hi = g_hh;  break;
        case 2:  hi = g_wzh; break;
        case 3:  hi = g_whh; break;
        default: hi = g_wvh; break;
    }
    const int stride = gridDim.x * blockDim.x;
    for (int j = blockIdx.x * blockDim.x + threadIdx.x; j < n4; j += stride) {
        float4 v = ((const float4*)src)[j];
        ((__half2*)hi)[j * 2 + 0] = __halves2half2(__float2half(v.x), __float2half(v.y));
        ((__half2*)hi)[j * 2 + 1] = __halves2half2(__float2half(v.z), __float2half(v.w));
    }
}

// ---------------------------------------------------------------------------
// wqt_kernel: Wqt[e, h*64+dp] = sum_d wq[e, h*64+d] * wk[dp, h*64+d]
// ---------------------------------------------------------------------------
__global__ __launch_bounds__(256) void wqt_kernel(
    const float* __restrict__ wq,
    const float* __restrict__ wk)
{
    const int idx = blockIdx.x * 256 + threadIdx.x;
    const int e  = idx >> 9;
    const int j  = idx & 511;
    const int h  = j >> 6;
    const int dp = j & 63;
    float s = 0.f;
    const float* wqp = wq + (size_t)e * 512 + h * 64;
    const float* wkp = wk + (size_t)dp * 512 + h * 64;
    #pragma unroll 8
    for (int d = 0; d < 64; d++)
        s = fmaf(wqp[d], wkp[d], s);
    g_wqt[e * 512 + j] = s;
}

// ---------------------------------------------------------------------------
// qt_kernel: qt = command @ Wqt
// ---------------------------------------------------------------------------
#define QT_WSTR 132
#define QT_SMEM ((32 * 128 + 128 * QT_WSTR) * 4)

__global__ __launch_bounds__(256) void qt_kernel(const float* __restrict__ command)
{
    extern __shared__ float qsm[];
    float* cmds = qsm;
    float* Wq   = qsm + 32 * 128;

    const int tid = threadIdx.x;
    const int bb  = blockIdx.x * 32;
    const int jt  = blockIdx.y * 128;

    #pragma unroll
    for (int rep = 0; rep < 4; rep++) {
        const int i = tid + rep * 256;
        const int row = i >> 5, c4 = i & 31;
        float4 v = *(const float4*)(command + (size_t)(bb + row) * 128 + c4 * 4);
        *(float4*)(cmds + row * 128 + c4 * 4) = v;
    }
    #pragma unroll
    for (int rep = 0; rep < 16; rep++) {
        const int i = tid + rep * 256;
        const int row = i >> 5, c4 = i & 31;
        float4 v = *(const float4*)(g_wqt + row * 512 + jt + c4 * 4);
        *(float4*)(Wq + row * QT_WSTR + c4 * 4) = v;
    }
    __syncthreads();

    const int r = tid >> 3;
    const int g = tid & 7;
    float acc[16];
    #pragma unroll
    for (int c = 0; c < 16; c++) acc[c] = 0.f;

    #pragma unroll 4
    for (int k = 0; k < 128; k++) {
        const float a = cmds[r * 128 + k];
        const float* wp = Wq + k * QT_WSTR + g * 16;
        #pragma unroll
        for (int c = 0; c < 16; c++)
            acc[c] = fmaf(a, wp[c], acc[c]);
    }

    float* dst = g_qt + (size_t)(bb + r) * 512 + jt + g * 16;
    #pragma unroll
    for (int c4 = 0; c4 < 4; c4++)
        *(float4*)(dst + c4 * 4) = make_float4(acc[c4 * 4], acc[c4 * 4 + 1],
                                               acc[c4 * 4 + 2], acc[c4 * 4 + 3]);
}

// ---------------------------------------------------------------------------
// wmma fp16 single-pass projection GEMM + GELU + LayerNorm.
//   Fused grid: blockIdx.y in [0,32) -> feature@wz; [32,64) -> hidden@wh.
// ---------------------------------------------------------------------------
#define KC     32
#define A_STR  40
#define B_STR  136
#define C_STR  140
#define A_PLANE (128 * A_STR * 2)                 // 10240 B
#define B_PLANE (KC * B_STR * 2)                  // 8704 B
#define STAGE_B (A_PLANE + B_PLANE)               // 18944 B
#define SMEM_GB 512
#define C_BYTES (128 * C_STR * 4)                 // 71680 B
#define PROJ_SMEM (SMEM_GB + C_BYTES)             // 72192 B (> 512 + 2*STAGE_B)

__global__ __launch_bounds__(256, 2) void proj_wmma_kernel(
    const float* __restrict__ gamma,
    const float* __restrict__ beta)
{
    extern __shared__ char smem[];
    const int tid = threadIdx.x;
    const int wid = tid >> 5;

    const int sel = (blockIdx.y >= 32) ? 1 : 0;
    const __half* Ah_g = sel ? g_hh  : g_fh;
    const __half* Wh_g = sel ? g_whh : g_wzh;
    const int K        = sel ? 1024  : 2048;
    const int fbase    = sel ? 64    : 0;

    const int bm = blockIdx.x * 128;
    const int bn = (blockIdx.y & 31) * 128;

    if (tid < 64) {
        *(float*)(smem + tid * 4)       = gamma[tid];
        *(float*)(smem + 256 + tid * 4) = beta[tid];
    }

    const int warp_m = wid & 3;
    const int warp_n = wid >> 2;

    wmma::fragment<wmma::accumulator, 16, 16, 16, float> acc[2][4];
    #pragma unroll
    for (int fm = 0; fm < 2; fm++)
        #pragma unroll
        for (int fn = 0; fn < 4; fn++)
            wmma::fill_fragment(acc[fm][fn], 0.0f);

    const int nK = K / KC;

    auto load_stage = [&](int it, int buf) {
        const int kt = it * KC;
        char* stg = smem + SMEM_GB + buf * STAGE_B;
        const uint32_t stg_u = (uint32_t)__cvta_generic_to_shared(stg);
        // A: 128 rows x 4 chunks(16B) = 512; 2/thread
        #pragma unroll
        for (int rep = 0; rep < 2; rep++) {
            const int i = tid + rep * 256;
            const int r = i >> 2;
            const int c = i & 3;
            const __half* gp = Ah_g + (size_t)(bm + r) * K + kt + c * 8;
            cp_async16(stg_u + r * (A_STR * 2) + c * 16, gp);
        }
        // B: 32 k-rows x 16 chunks = 512; 2/thread
        #pragma unroll
        for (int rep = 0; rep < 2; rep++) {
            const int i = tid + rep * 256;
            const int kk = i >> 4;
            const int c  = i & 15;
            const __half* gp = Wh_g + (size_t)(kt + kk) * MCOLS + bn + c * 8;
            cp_async16(stg_u + A_PLANE + kk * (B_STR * 2) + c * 16, gp);
        }
        asm volatile("cp.async.commit_group;");
    };

    load_stage(0, 0);

    for (int it = 0; it < nK; it++) {
        const int buf = it & 1;
        if (it + 1 < nK) {
            load_stage(it + 1, buf ^ 1);
            asm volatile("cp.async.wait_group 1;");
        } else {
            asm volatile("cp.async.wait_group 0;");
        }
        __syncthreads();

        const char* stg = smem + SMEM_GB + buf * STAGE_B;
        const __half* As = (const __half*)(stg);
        const __half* Bs = (const __half*)(stg + A_PLANE);

        #pragma unroll
        for (int kk = 0; kk < KC; kk += 16) {
            wmma::fragment<wmma::matrix_a, 16, 16, 16, __half, wmma::row_major> af[2];
            #pragma unroll
            for (int fm = 0; fm < 2; fm++)
                wmma::load_matrix_sync(af[fm], As + (warp_m * 32 + fm * 16) * A_STR + kk, A_STR);
            #pragma unroll
            for (int fn = 0; fn < 4; fn++) {
                wmma::fragment<wmma::matrix_b, 16, 16, 16, __half, wmma::row_major> bf;
                wmma::load_matrix_sync(bf, Bs + kk * B_STR + warp_n * 64 + fn * 16, B_STR);
                #pragma unroll
                for (int fm = 0; fm < 2; fm++)
                    wmma::mma_sync(acc[fm][fn], af[fm], bf, acc[fm][fn]);
            }
        }
        __syncthreads();
    }

    // ---- Epilogue
    float* Cs = (float*)(smem + SMEM_GB);
    #pragma unroll
    for (int fm = 0; fm < 2; fm++)
        #pragma unroll
        for (int fn = 0; fn < 4; fn++)
            wmma::store_matrix_sync(Cs + (warp_m * 32 + fm * 16) * C_STR + warp_n * 64 + fn * 16,
                                    acc[fm][fn], C_STR, wmma::mem_row_major);
    __syncthreads();

    const float* gs = (const float*)(smem);
    const float* bs = (const float*)(smem + 256);
    {
        const int row = tid >> 1;
        const int grp = tid & 1;
        const float* src = Cs + row * C_STR + grp * 64;

        float v[64];
        float s = 0.f, sq = 0.f;
        #pragma unroll
        for (int c = 0; c < 64; c++) {
            float x = gelu_exact(src[c]);
            v[c] = x;
            s += x; sq += x * x;
        }
        const float mu   = s * (1.f / 64.f);
        const float var  = sq * (1.f / 64.f) - mu * mu;
        const float rstd = rsqrtf(var + LN_EPS);

        const int f = fbase + (bn >> 6) + grp;
        const size_t base = ((size_t)(bm + row) * NF_ + f) * D_;
        float* dst = g_Fi + base;
        __half2* dh = (__half2*)(g_Fih + base);
        #pragma unroll
        for (int c4 = 0; c4 < 16; c4++) {
            float4 o;
            o.x = (v[c4 * 4 + 0] - mu) * rstd * gs[c4 * 4 + 0] + bs[c4 * 4 + 0];
            o.y = (v[c4 * 4 + 1] - mu) * rstd * gs[c4 * 4 + 1] + bs[c4 * 4 + 1];
            o.z = (v[c4 * 4 + 2] - mu) * rstd * gs[c4 * 4 + 2] + bs[c4 * 4 + 2];
            o.w = (v[c4 * 4 + 3] - mu) * rstd * gs[c4 * 4 + 3] + bs[c4 * 4 + 3];
            *(float4*)(dst + c4 * 4) = o;
            dh[c4 * 2 + 0] = __halves2half2(__float2half(o.x), __float2half(o.y));
            dh[c4 * 2 + 1] = __halves2half2(__float2half(o.z), __float2half(o.w));
        }
    }
}

// ---------------------------------------------------------------------------
// mv_kernel (fp16): per b, V = Fi_b @ wv via wmma; mV = mean_d |V|.
// ---------------------------------------------------------------------------
#define MV_A_STR 72
#define MV_APL   (128 * MV_A_STR * 2)
#define MV_B_STR 136
#define MV_BPL   (64 * MV_B_STR * 2)
#define MV_C_STR 132
#define MV_SMEM  (MV_APL + 2 * MV_BPL + 128 * MV_C_STR * 4)

__global__ __launch_bounds__(256, 1) void mv_kernel()
{
    extern __shared__ char smem[];
    const int tid = threadIdx.x;
    const int wid = tid >> 5;
    const int b   = blockIdx.x;

    char* Afi = smem;
    char* Bw  = smem + MV_APL;
    float* Cs = (float*)(Bw + 2 * MV_BPL);

    const uint32_t afi_u = (uint32_t)__cvta_generic_to_shared(Afi);
    const uint32_t bw_u  = (uint32_t)__cvta_generic_to_shared(Bw);

    {
        const size_t base = (size_t)b * NF_ * D_;
        #pragma unroll
        for (int rep = 0; rep < 4; rep++) {
            const int i = tid + rep * 256;
            const int r = i >> 3;
            const int c = i & 7;
            cp_async16(afi_u + r * (MV_A_STR * 2) + c * 16, g_Fih + base + r * 64 + c * 8);
        }
    }
    auto load_b = [&](int nc, int buf) {
        #pragma unroll
        for (int rep = 0; rep < 4; rep++) {
            const int i = tid + rep * 256;
            const int kk = i >> 4;
            const int c  = i & 15;
            cp_async16(bw_u + buf * MV_BPL + kk * (MV_B_STR * 2) + c * 16,
                       g_wvh + kk * 512 + nc * 128 + c * 8);
        }
        asm volatile("cp.async.commit_group;");
    };
    load_b(0, 0);

    const int warp_m = wid & 3;
    const int warp_n = wid >> 2;

    for (int nc = 0; nc < 4; nc++) {
        const int buf = nc & 1;
        if (nc + 1 < 4) {
            load_b(nc + 1, buf ^ 1);
            asm volatile("cp.async.wait_group 1;");
        } else {
            asm volatile("cp.async.wait_group 0;");
        }
        __syncthreads();

        wmma::fragment<wmma::accumulator, 16, 16, 16, float> acc[2][4];
        #pragma unroll
        for (int fm = 0; fm < 2; fm++)
            #pragma unroll
            for (int fn = 0; fn < 4; fn++)
                wmma::fill_fragment(acc[fm][fn], 0.0f);

        const __half* As = (const __half*)Afi;
        const __half* Bs = (const __half*)(Bw + buf * MV_BPL);

        #pragma unroll
        for (int kk = 0; kk < 64; kk += 16) {
            wmma::fragment<wmma::matrix_a, 16, 16, 16, __half, wmma::row_major> af[2];
            #pragma unroll
            for (int fm = 0; fm < 2; fm++)
                wmma::load_matrix_sync(af[fm], As + (warp_m * 32 + fm * 16) * MV_A_STR + kk, MV_A_STR);
            #pragma unroll
            for (int fn = 0; fn < 4; fn++) {
                wmma::fragment<wmma::matrix_b, 16, 16, 16, __half, wmma::row_major> bf;
                wmma::load_matrix_sync(bf, Bs + kk * MV_B_STR + warp_n * 64 + fn * 16, MV_B_STR);
                #pragma unroll
                for (int fm = 0; fm < 2; fm++)
                    wmma::mma_sync(acc[fm][fn], af[fm], bf, acc[fm][fn]);
            }
        }
        #pragma unroll
        for (int fm = 0; fm < 2; fm++)
            #pragma unroll
            for (int fn = 0; fn < 4; fn++)
                wmma::store_matrix_sync(Cs + (warp_m * 32 + fm * 16) * MV_C_STR + warp_n * 64 + fn * 16,
                                        acc[fm][fn], MV_C_STR, wmma::mem_row_major);
        __syncthreads();

        {
            const int hh = tid >> 7;
            const int m  = tid & 127;
            const float* rowp = Cs + m * MV_C_STR + hh * 64;
            float s = 0.f;
            #pragma unroll 16
            for (int c = 0; c < 64; c++)
                s += fabsf(rowp[c]);
            g_mv[((size_t)b * 8 + nc * 2 + hh) * 128 + m] = s * (1.f / 64.f);
        }
        __syncthreads();
    }
}

// ---------------------------------------------------------------------------
// attn_lite (proven): logits, softmax, gvec = A^T Fi, S = gvec@wv
// ---------------------------------------------------------------------------
#define FSTR 129
#define LITE_SMEM ((64 * FSTR + 512 + 1024 + 1024 + 512) * 4)

__global__ __launch_bounds__(256, 1) void attn_lite_kernel(
    const float* __restrict__ wv,
    float* __restrict__ out)
{
    extern __shared__ float sm[];
    float* Fst  = sm;
    float* qts  = Fst + 64 * FSTR;
    float* mvs  = qts + 512;
    float* Aw   = mvs + 1024;
    float* gv   = Aw + 1024;

    const int tid = threadIdx.x;
    const int b   = blockIdx.x;

    {
        const float* Fi = g_Fi + (size_t)b * NF_ * D_;
        const int m = tid & 127, half = tid >> 7;
        #pragma unroll
        for (int v = 0; v < 8; v++) {
            const int vv = half * 8 + v;
            float4 fv = *(const float4*)(Fi + m * 64 + vv * 4);
            Fst[(vv * 4 + 0) * FSTR + m] = fv.x;
            Fst[(vv * 4 + 1) * FSTR + m] = fv.y;
            Fst[(vv * 4 + 2) * FSTR + m] = fv.z;
            Fst[(vv * 4 + 3) * FSTR + m] = fv.w;
        }
    }
    #pragma unroll
    for (int r = 0; r < 2; r++)
        qts[tid + r * 256] = g_qt[(size_t)b * 512 + tid + r * 256];
    #pragma unroll
    for (int r = 0; r < 4; r++)
        mvs[tid + r * 256] = g_mv[(size_t)b * 1024 + tid + r * 256];
    __syncthreads();

    #pragma unroll
    for (int r = 0; r < 4; r++) {
        const int idx = tid + r * 256;
        const int h = idx >> 7, m = idx & 127;
        float s = 0.f;
        #pragma unroll 8
        for (int k = 0; k < 64; k++)
            s = fmaf(Fst[k * FSTR + m], qts[h * 64 + k], s);
        Aw[idx] = mvs[idx] * s * 0.125f;
    }
    __syncthreads();

    {
        const int w = tid >> 5, lane = tid & 31;
        float v0 = Aw[w * 128 + lane];
        float v1 = Aw[w * 128 + lane + 32];
        float v2 = Aw[w * 128 + lane + 64];
        float v3 = Aw[w * 128 + lane + 96];
        float mx = fmaxf(fmaxf(v0, v1), fmaxf(v2, v3));
        #pragma unroll
        for (int off = 16; off >= 1; off >>= 1)
            mx = fmaxf(mx, __shfl_xor_sync(0xffffffffu, mx, off));
        v0 = expf(v0 - mx); v1 = expf(v1 - mx);
        v2 = expf(v2 - mx); v3 = expf(v3 - mx);
        float se = v0 + v1 + v2 + v3;
        #pragma unroll
        for (int off = 16; off >= 1; off >>= 1)
            se += __shfl_xor_sync(0xffffffffu, se, off);
        const float inv = 1.f / se;
        Aw[w * 128 + lane]      = v0 * inv;
        Aw[w * 128 + lane + 32] = v1 * inv;
        Aw[w * 128 + lane + 64] = v2 * inv;
        Aw[w * 128 + lane + 96] = v3 * inv;
    }
    __syncthreads();

    #pragma unroll
    for (int r = 0; r < 2; r++) {
        const int idx = tid + r * 256;
        const int h = idx >> 6, d = idx & 63;
        float s = 0.f;
        #pragma unroll 8
        for (int m = 0; m < 128; m++)
            s = fmaf(Aw[h * 128 + m], Fst[d * FSTR + m], s);
        gv[idx] = s;
    }
    __syncthreads();

    #pragma unroll
    for (int r = 0; r < 2; r++) {
        const int idx = tid + r * 256;
        const int h = idx >> 6, d = idx & 63;
        float s = 0.f;
        #pragma unroll 8
        for (int k = 0; k < 64; k++)
            s = fmaf(gv[h * 64 + k], wv[(size_t)k * 512 + h * 64 + d], s);
        out[(size_t)b * 512 + idx] = s;
    }
}

// ---------------------------------------------------------------------------
// Launch
// ---------------------------------------------------------------------------
extern "C" void kernel_launch(void* const* d_in, const int* in_sizes, int n_in,
                              void* d_out, int out_size)
{
    const float* feature  = (const float*)d_in[0];
    const float* hidden   = (const float*)d_in[1];
    const float* command  = (const float*)d_in[2];
    const float* wz       = (const float*)d_in[3];
    const float* wh       = (const float*)d_in[4];
    const float* wq       = (const float*)d_in[5];
    const float* wk       = (const float*)d_in[6];
    const float* wv       = (const float*)d_in[7];
    const float* ln_gamma = (const float*)d_in[8];
    const float* ln_beta  = (const float*)d_in[9];
    float* out = (float*)d_out;

    cudaFuncSetAttribute(proj_wmma_kernel, cudaFuncAttributeMaxDynamicSharedMemorySize, PROJ_SMEM);
    cudaFuncSetAttribute(mv_kernel, cudaFuncAttributeMaxDynamicSharedMemorySize, MV_SMEM);
    cudaFuncSetAttribute(attn_lite_kernel, cudaFuncAttributeMaxDynamicSharedMemorySize, LITE_SMEM);
    cudaFuncSetAttribute(qt_kernel, cudaFuncAttributeMaxDynamicSharedMemorySize, QT_SMEM);

    convert_single_kernel<<<1024, 256>>>(feature, 0, 2097152 / 4);
    convert_single_kernel<<<512,  256>>>(hidden,  1, 1048576 / 4);
    convert_single_kernel<<<2048, 256>>>(wz,      2, 8388608 / 4);
    convert_single_kernel<<<1024, 256>>>(wh,      3, 4194304 / 4);
    convert_single_kernel<<<32,   256>>>(wv,      4, 32768 / 4);

    wqt_kernel<<<256, 256>>>(wq, wk);
    qt_kernel<<<dim3(32, 4), 256, QT_SMEM>>>(command);

    // fused projections: y 0-31 = feature@wz, y 32-63 = hidden@wh
    proj_wmma_kernel<<<dim3(8, 64), 256, PROJ_SMEM>>>(ln_gamma, ln_beta);

    mv_kernel<<<B_SZ, 256, MV_SMEM>>>();
    attn_lite_kernel<<<B_SZ, 256, LITE_SMEM>>>(wv, out);
}

// round 12
// speedup vs baseline: 3.9606x; 1.0654x over previous
#include <cuda_runtime.h>
#include <cuda_fp16.h>
#include <mma.h>
#include <cstdint>
#include <stdint.h>
#include <math.h>

using namespace nvcuda;

// Problem constants
#define B_SZ   1024
#define NF_    128
#define D_     64
#define H_     8
#define MCOLS  4096
#define LN_EPS 1e-5f

// ---------------------------------------------------------------------------
// Scratch (__device__ globals)
// ---------------------------------------------------------------------------
__device__ float g_qt[(size_t)B_SZ * H_ * D_];    // [b][h][d'] folded K-query
__device__ float g_wqt[128 * 512];                // [e][h*64+d'] folded wq/wk

// fp16 single planes
__device__ __half g_fh[2097152];                  // feature 1024x2048
__device__ __half g_hh[1048576];                  // hidden  1024x1024
__device__ __half g_wzh[8388608];                 // wz      2048x4096
__device__ __half g_whh[4194304];                 // wh      1024x4096
__device__ __half g_wvh[32768];                   // wv      64x512
__device__ __half g_Fih[8388608];                 // Fi      [b][m][d]

__device__ __forceinline__ float gelu_exact(float x) {
    return 0.5f * x * (1.0f + erff(x * 0.70710678118654752f));
}

__device__ __forceinline__ void cp_async16(uint32_t dst, const void* src) {
    asm volatile("cp.async.cg.shared.global [%0], [%1], 16;\n"
                 :: "r"(dst), "l"(__cvta_generic_to_global(src)));
}

// ---------------------------------------------------------------------------
// convert_all: one launch for every fp32 -> fp16 conversion (segment map over
// concatenated float4 index space; branches coherent per range).
// ---------------------------------------------------------------------------
#define CV_F   524288                    // feature  float4 count
#define CV_H   (CV_F + 262144)           // + hidden
#define CV_WZ  (CV_H + 2097152)          // + wz
#define CV_WH  (CV_WZ + 1048576)         // + wh
#define CV_END (CV_WH + 8192)            // + wv

__global__ __launch_bounds__(256) void convert_all_kernel(
    const float* __restrict__ feature, const float* __restrict__ hidden,
    const float* __restrict__ wz, const float* __restrict__ wh,
    const float* __restrict__ wv)
{
    const int stride = gridDim.x * blockDim.x;
    for (int j = blockIdx.x * blockDim.x + threadIdx.x; j < CV_END; j += stride) {
        const float* src; __half* dst; int off;
        if (j < CV_F)       { src = feature; dst = g_fh;  off = j; }
        else if (j < CV_H)  { src = hidden;  dst = g_hh;  off = j - CV_F; }
        else if (j < CV_WZ) { src = wz;      dst = g_wzh; off = j - CV_H; }
        else if (j < CV_WH) { src = wh;      dst = g_whh; off = j - CV_WZ; }
        else                { src = wv;      dst = g_wvh; off = j - CV_WH; }
        float4 v = ((const float4*)src)[off];
        ((__half2*)dst)[off * 2 + 0] = __halves2half2(__float2half(v.x), __float2half(v.y));
        ((__half2*)dst)[off * 2 + 1] = __halves2half2(__float2half(v.z), __float2half(v.w));
    }
}

// ---------------------------------------------------------------------------
// wqt_kernel: Wqt[e, h*64+dp] = sum_d wq[e, h*64+d] * wk[dp, h*64+d]
// ---------------------------------------------------------------------------
__global__ __launch_bounds__(256) void wqt_kernel(
    const float* __restrict__ wq,
    const float* __restrict__ wk)
{
    const int idx = blockIdx.x * 256 + threadIdx.x;
    const int e  = idx >> 9;
    const int j  = idx & 511;
    const int h  = j >> 6;
    const int dp = j & 63;
    float s = 0.f;
    const float* wqp = wq + (size_t)e * 512 + h * 64;
    const float* wkp = wk + (size_t)dp * 512 + h * 64;
    #pragma unroll 8
    for (int d = 0; d < 64; d++)
        s = fmaf(wqp[d], wkp[d], s);
    g_wqt[e * 512 + j] = s;
}

// ---------------------------------------------------------------------------
// qt_kernel: qt = command @ Wqt
// ---------------------------------------------------------------------------
#define QT_WSTR 132
#define QT_SMEM ((32 * 128 + 128 * QT_WSTR) * 4)

__global__ __launch_bounds__(256) void qt_kernel(const float* __restrict__ command)
{
    extern __shared__ float qsm[];
    float* cmds = qsm;
    float* Wq   = qsm + 32 * 128;

    const int tid = threadIdx.x;
    const int bb  = blockIdx.x * 32;
    const int jt  = blockIdx.y * 128;

    #pragma unroll
    for (int rep = 0; rep < 4; rep++) {
        const int i = tid + rep * 256;
        const int row = i >> 5, c4 = i & 31;
        float4 v = *(const float4*)(command + (size_t)(bb + row) * 128 + c4 * 4);
        *(float4*)(cmds + row * 128 + c4 * 4) = v;
    }
    #pragma unroll
    for (int rep = 0; rep < 16; rep++) {
        const int i = tid + rep * 256;
        const int row = i >> 5, c4 = i & 31;
        float4 v = *(const float4*)(g_wqt + row * 512 + jt + c4 * 4);
        *(float4*)(Wq + row * QT_WSTR + c4 * 4) = v;
    }
    __syncthreads();

    const int r = tid >> 3;
    const int g = tid & 7;
    float acc[16];
    #pragma unroll
    for (int c = 0; c < 16; c++) acc[c] = 0.f;

    #pragma unroll 4
    for (int k = 0; k < 128; k++) {
        const float a = cmds[r * 128 + k];
        const float* wp = Wq + k * QT_WSTR + g * 16;
        #pragma unroll
        for (int c = 0; c < 16; c++)
            acc[c] = fmaf(a, wp[c], acc[c]);
    }

    float* dst = g_qt + (size_t)(bb + r) * 512 + jt + g * 16;
    #pragma unroll
    for (int c4 = 0; c4 < 4; c4++)
        *(float4*)(dst + c4 * 4) = make_float4(acc[c4 * 4], acc[c4 * 4 + 1],
                                               acc[c4 * 4 + 2], acc[c4 * 4 + 3]);
}

// ---------------------------------------------------------------------------
// wmma fp16 projection GEMM + GELU + LayerNorm (fused feature/hidden grid).
//   Epilogue writes fp16 Fi only (fp32 Fi retired).
// ---------------------------------------------------------------------------
#define KC     32
#define A_STR  40
#define B_STR  136
#define C_STR  140
#define A_PLANE (128 * A_STR * 2)
#define B_PLANE (KC * B_STR * 2)
#define STAGE_B (A_PLANE + B_PLANE)
#define SMEM_GB 512
#define C_BYTES (128 * C_STR * 4)
#define PROJ_SMEM (SMEM_GB + C_BYTES)

__global__ __launch_bounds__(256, 2) void proj_wmma_kernel(
    const float* __restrict__ gamma,
    const float* __restrict__ beta)
{
    extern __shared__ char smem[];
    const int tid = threadIdx.x;
    const int wid = tid >> 5;

    const int sel = (blockIdx.y >= 32) ? 1 : 0;
    const __half* Ah_g = sel ? g_hh  : g_fh;
    const __half* Wh_g = sel ? g_whh : g_wzh;
    const int K        = sel ? 1024  : 2048;
    const int fbase    = sel ? 64    : 0;

    const int bm = blockIdx.x * 128;
    const int bn = (blockIdx.y & 31) * 128;

    if (tid < 64) {
        *(float*)(smem + tid * 4)       = gamma[tid];
        *(float*)(smem + 256 + tid * 4) = beta[tid];
    }

    const int warp_m = wid & 3;
    const int warp_n = wid >> 2;

    wmma::fragment<wmma::accumulator, 16, 16, 16, float> acc[2][4];
    #pragma unroll
    for (int fm = 0; fm < 2; fm++)
        #pragma unroll
        for (int fn = 0; fn < 4; fn++)
            wmma::fill_fragment(acc[fm][fn], 0.0f);

    const int nK = K / KC;

    auto load_stage = [&](int it, int buf) {
        const int kt = it * KC;
        char* stg = smem + SMEM_GB + buf * STAGE_B;
        const uint32_t stg_u = (uint32_t)__cvta_generic_to_shared(stg);
        #pragma unroll
        for (int rep = 0; rep < 2; rep++) {
            const int i = tid + rep * 256;
            const int r = i >> 2;
            const int c = i & 3;
            const __half* gp = Ah_g + (size_t)(bm + r) * K + kt + c * 8;
            cp_async16(stg_u + r * (A_STR * 2) + c * 16, gp);
        }
        #pragma unroll
        for (int rep = 0; rep < 2; rep++) {
            const int i = tid + rep * 256;
            const int kk = i >> 4;
            const int c  = i & 15;
            const __half* gp = Wh_g + (size_t)(kt + kk) * MCOLS + bn + c * 8;
            cp_async16(stg_u + A_PLANE + kk * (B_STR * 2) + c * 16, gp);
        }
        asm volatile("cp.async.commit_group;");
    };

    load_stage(0, 0);

    for (int it = 0; it < nK; it++) {
        const int buf = it & 1;
        if (it + 1 < nK) {
            load_stage(it + 1, buf ^ 1);
            asm volatile("cp.async.wait_group 1;");
        } else {
            asm volatile("cp.async.wait_group 0;");
        }
        __syncthreads();

        const char* stg = smem + SMEM_GB + buf * STAGE_B;
        const __half* As = (const __half*)(stg);
        const __half* Bs = (const __half*)(stg + A_PLANE);

        #pragma unroll
        for (int kk = 0; kk < KC; kk += 16) {
            wmma::fragment<wmma::matrix_a, 16, 16, 16, __half, wmma::row_major> af[2];
            #pragma unroll
            for (int fm = 0; fm < 2; fm++)
                wmma::load_matrix_sync(af[fm], As + (warp_m * 32 + fm * 16) * A_STR + kk, A_STR);
            #pragma unroll
            for (int fn = 0; fn < 4; fn++) {
                wmma::fragment<wmma::matrix_b, 16, 16, 16, __half, wmma::row_major> bf;
                wmma::load_matrix_sync(bf, Bs + kk * B_STR + warp_n * 64 + fn * 16, B_STR);
                #pragma unroll
                for (int fm = 0; fm < 2; fm++)
                    wmma::mma_sync(acc[fm][fn], af[fm], bf, acc[fm][fn]);
            }
        }
        __syncthreads();
    }

    // ---- Epilogue: GELU + LN, write fp16 Fi only
    float* Cs = (float*)(smem + SMEM_GB);
    #pragma unroll
    for (int fm = 0; fm < 2; fm++)
        #pragma unroll
        for (int fn = 0; fn < 4; fn++)
            wmma::store_matrix_sync(Cs + (warp_m * 32 + fm * 16) * C_STR + warp_n * 64 + fn * 16,
                                    acc[fm][fn], C_STR, wmma::mem_row_major);
    __syncthreads();

    const float* gs = (const float*)(smem);
    const float* bs = (const float*)(smem + 256);
    {
        const int row = tid >> 1;
        const int grp = tid & 1;
        const float* src = Cs + row * C_STR + grp * 64;

        float v[64];
        float s = 0.f, sq = 0.f;
        #pragma unroll
        for (int c = 0; c < 64; c++) {
            float x = gelu_exact(src[c]);
            v[c] = x;
            s += x; sq += x * x;
        }
        const float mu   = s * (1.f / 64.f);
        const float var  = sq * (1.f / 64.f) - mu * mu;
        const float rstd = rsqrtf(var + LN_EPS);

        const int f = fbase + (bn >> 6) + grp;
        const size_t base = ((size_t)(bm + row) * NF_ + f) * D_;
        __half2* dh = (__half2*)(g_Fih + base);
        #pragma unroll
        for (int c4 = 0; c4 < 16; c4++) {
            float ox = (v[c4 * 4 + 0] - mu) * rstd * gs[c4 * 4 + 0] + bs[c4 * 4 + 0];
            float oy = (v[c4 * 4 + 1] - mu) * rstd * gs[c4 * 4 + 1] + bs[c4 * 4 + 1];
            float oz = (v[c4 * 4 + 2] - mu) * rstd * gs[c4 * 4 + 2] + bs[c4 * 4 + 2];
            float ow = (v[c4 * 4 + 3] - mu) * rstd * gs[c4 * 4 + 3] + bs[c4 * 4 + 3];
            dh[c4 * 2 + 0] = __halves2half2(__float2half(ox), __float2half(oy));
            dh[c4 * 2 + 1] = __halves2half2(__float2half(oz), __float2half(ow));
        }
    }
}

// ---------------------------------------------------------------------------
// attn_fused: per b — V wmma + mV, logits, softmax, gvec, S. Fi fp16 in smem.
// ---------------------------------------------------------------------------
#define AF_A_STR 72                           // halves; 144B rows (16B aligned)
#define AF_FI    0
#define AF_FI_B  (128 * AF_A_STR * 2)         // 18432
#define AF_WV    AF_FI_B
#define AF_BPL   (64 * 136 * 2)               // 17408 per buffer
#define AF_CS    (AF_WV + 2 * AF_BPL)         // 53248
#define AF_CS_B  (128 * 132 * 4)              // 67584
#define AF_QTS   (AF_CS + AF_CS_B)            // 120832
#define AF_MVS   (AF_QTS + 512 * 4)           // 122880
#define AF_AW    (AF_MVS + 1024 * 4)          // 126976
#define AF_GV    (AF_AW + 1024 * 4)           // 131072
#define AF_SMEM  (AF_GV + 512 * 4)            // 133120

__global__ __launch_bounds__(256, 1) void attn_fused_kernel(
    const float* __restrict__ wv,
    float* __restrict__ out)
{
    extern __shared__ char smem[];
    const int tid = threadIdx.x;
    const int wid = tid >> 5;
    const int b   = blockIdx.x;

    const __half* Fi16 = (const __half*)(smem + AF_FI);
    float* Cs  = (float*)(smem + AF_CS);
    float* qts = (float*)(smem + AF_QTS);
    float* mvs = (float*)(smem + AF_MVS);
    float* Aw  = (float*)(smem + AF_AW);
    float* gv  = (float*)(smem + AF_GV);

    const uint32_t fi_u = (uint32_t)__cvta_generic_to_shared(smem + AF_FI);
    const uint32_t wv_u = (uint32_t)__cvta_generic_to_shared(smem + AF_WV);

    // Load Fi fp16: 128 rows x 8 chunks(16B); 4/thread (committed with wv0)
    {
        const size_t base = (size_t)b * NF_ * D_;
        #pragma unroll
        for (int rep = 0; rep < 4; rep++) {
            const int i = tid + rep * 256;
            const int r = i >> 3;
            const int c = i & 7;
            cp_async16(fi_u + r * (AF_A_STR * 2) + c * 16, g_Fih + base + r * 64 + c * 8);
        }
    }
    auto load_b = [&](int nc, int buf) {
        #pragma unroll
        for (int rep = 0; rep < 4; rep++) {
            const int i = tid + rep * 256;
            const int kk = i >> 4;
            const int c  = i & 15;
            cp_async16(wv_u + buf * AF_BPL + kk * (136 * 2) + c * 16,
                       g_wvh + kk * 512 + nc * 128 + c * 8);
        }
        asm volatile("cp.async.commit_group;");
    };
    load_b(0, 0);

    // qt loads (regular ld, overlap with cp.async)
    #pragma unroll
    for (int r = 0; r < 2; r++)
        qts[tid + r * 256] = g_qt[(size_t)b * 512 + tid + r * 256];

    const int warp_m = wid & 3;
    const int warp_n = wid >> 2;

    // ---- Phase 1: V chunks + mV
    for (int nc = 0; nc < 4; nc++) {
        const int buf = nc & 1;
        if (nc + 1 < 4) {
            load_b(nc + 1, buf ^ 1);
            asm volatile("cp.async.wait_group 1;");
        } else {
            asm volatile("cp.async.wait_group 0;");
        }
        __syncthreads();

        wmma::fragment<wmma::accumulator, 16, 16, 16, float> acc[2][4];
        #pragma unroll
        for (int fm = 0; fm < 2; fm++)
            #pragma unroll
            for (int fn = 0; fn < 4; fn++)
                wmma::fill_fragment(acc[fm][fn], 0.0f);

        const __half* As = Fi16;
        const __half* Bs = (const __half*)(smem + AF_WV + buf * AF_BPL);

        #pragma unroll
        for (int kk = 0; kk < 64; kk += 16) {
            wmma::fragment<wmma::matrix_a, 16, 16, 16, __half, wmma::row_major> af[2];
            #pragma unroll
            for (int fm = 0; fm < 2; fm++)
                wmma::load_matrix_sync(af[fm], As + (warp_m * 32 + fm * 16) * AF_A_STR + kk, AF_A_STR);
            #pragma unroll
            for (int fn = 0; fn < 4; fn++) {
                wmma::fragment<wmma::matrix_b, 16, 16, 16, __half, wmma::row_major> bf;
                wmma::load_matrix_sync(bf, Bs + kk * 136 + warp_n * 64 + fn * 16, 136);
                #pragma unroll
                for (int fm = 0; fm < 2; fm++)
                    wmma::mma_sync(acc[fm][fn], af[fm], bf, acc[fm][fn]);
            }
        }
        #pragma unroll
        for (int fm = 0; fm < 2; fm++)
            #pragma unroll
            for (int fn = 0; fn < 4; fn++)
                wmma::store_matrix_sync(Cs + (warp_m * 32 + fm * 16) * 132 + warp_n * 64 + fn * 16,
                                        acc[fm][fn], 132, wmma::mem_row_major);
        __syncthreads();

        {
            const int hh = tid >> 7;
            const int m  = tid & 127;
            const float* rowp = Cs + m * 132 + hh * 64;
            float s = 0.f;
            #pragma unroll 16
            for (int c = 0; c < 64; c++)
                s += fabsf(rowp[c]);
            mvs[(nc * 2 + hh) * 128 + m] = s * (1.f / 64.f);
        }
        __syncthreads();
    }

    // ---- Phase 2: logits = mV * (Fi.qt)/8
    #pragma unroll
    for (int r = 0; r < 4; r++) {
        const int idx = tid + r * 256;
        const int h = idx >> 7, m = idx & 127;
        const __half2* rp = (const __half2*)(Fi16 + m * AF_A_STR);
        const float* qp = qts + h * 64;
        float s = 0.f;
        #pragma unroll 8
        for (int k2 = 0; k2 < 32; k2++) {
            float2 f = __half22float2(rp[k2]);
            s = fmaf(f.x, qp[k2 * 2], s);
            s = fmaf(f.y, qp[k2 * 2 + 1], s);
        }
        Aw[idx] = mvs[idx] * s * 0.125f;
    }
    __syncthreads();

    // ---- Phase 3: softmax per head (warp w = head w)
    {
        const int w = tid >> 5, lane = tid & 31;
        float v0 = Aw[w * 128 + lane];
        float v1 = Aw[w * 128 + lane + 32];
        float v2 = Aw[w * 128 + lane + 64];
        float v3 = Aw[w * 128 + lane + 96];
        float mx = fmaxf(fmaxf(v0, v1), fmaxf(v2, v3));
        #pragma unroll
        for (int off = 16; off >= 1; off >>= 1)
            mx = fmaxf(mx, __shfl_xor_sync(0xffffffffu, mx, off));
        v0 = expf(v0 - mx); v1 = expf(v1 - mx);
        v2 = expf(v2 - mx); v3 = expf(v3 - mx);
        float se = v0 + v1 + v2 + v3;
        #pragma unroll
        for (int off = 16; off >= 1; off >>= 1)
            se += __shfl_xor_sync(0xffffffffu, se, off);
        const float inv = 1.f / se;
        Aw[w * 128 + lane]      = v0 * inv;
        Aw[w * 128 + lane + 32] = v1 * inv;
        Aw[w * 128 + lane + 64] = v2 * inv;
        Aw[w * 128 + lane + 96] = v3 * inv;
    }
    __syncthreads();

    // ---- Phase 4: gvec[h,d] = sum_m Aw[h,m] * Fi[m,d]
    #pragma unroll
    for (int r = 0; r < 2; r++) {
        const int idx = tid + r * 256;
        const int h = idx >> 6, d = idx & 63;
        const float* ap = Aw + h * 128;
        float s = 0.f;
        #pragma unroll 8
        for (int m = 0; m < 128; m++)
            s = fmaf(ap[m], __half2float(Fi16[m * AF_A_STR + d]), s);
        gv[idx] = s;
    }
    __syncthreads();

    // ---- Phase 5: S[h,d] = sum_k gv[h,k] * wv[k, h*64+d]  (fp32 wv, L2-hot)
    #pragma unroll
    for (int r = 0; r < 2; r++) {
        const int idx = tid + r * 256;
        const int h = idx >> 6, d = idx & 63;
        float s = 0.f;
        #pragma unroll 8
        for (int k = 0; k < 64; k++)
            s = fmaf(gv[h * 64 + k], wv[(size_t)k * 512 + h * 64 + d], s);
        out[(size_t)b * 512 + idx] = s;
    }
}

// ---------------------------------------------------------------------------
// Launch
// ---------------------------------------------------------------------------
extern "C" void kernel_launch(void* const* d_in, const int* in_sizes, int n_in,
                              void* d_out, int out_size)
{
    const float* feature  = (const float*)d_in[0];
    const float* hidden   = (const float*)d_in[1];
    const float* command  = (const float*)d_in[2];
    const float* wz       = (const float*)d_in[3];
    const float* wh       = (const float*)d_in[4];
    const float* wq       = (const float*)d_in[5];
    const float* wk       = (const float*)d_in[6];
    const float* wv       = (const float*)d_in[7];
    const float* ln_gamma = (const float*)d_in[8];
    const float* ln_beta  = (const float*)d_in[9];
    float* out = (float*)d_out;

    cudaFuncSetAttribute(proj_wmma_kernel, cudaFuncAttributeMaxDynamicSharedMemorySize, PROJ_SMEM);
    cudaFuncSetAttribute(attn_fused_kernel, cudaFuncAttributeMaxDynamicSharedMemorySize, AF_SMEM);
    cudaFuncSetAttribute(qt_kernel, cudaFuncAttributeMaxDynamicSharedMemorySize, QT_SMEM);

    convert_all_kernel<<<2048, 256>>>(feature, hidden, wz, wh, wv);

    wqt_kernel<<<256, 256>>>(wq, wk);
    qt_kernel<<<dim3(32, 4), 256, QT_SMEM>>>(command);

    // fused projections: y 0-31 = feature@wz, y 32-63 = hidden@wh
    proj_wmma_kernel<<<dim3(8, 64), 256, PROJ_SMEM>>>(ln_gamma, ln_beta);

    attn_fused_kernel<<<B_SZ, 256, AF_SMEM>>>(wv, out);
}

// round 13
// speedup vs baseline: 3.9654x; 1.0012x over previous
#include <cuda_runtime.h>
#include <cuda_fp16.h>
#include <mma.h>
#include <cstdint>
#include <stdint.h>
#include <math.h>

using namespace nvcuda;

// Problem constants
#define B_SZ   1024
#define NF_    128
#define D_     64
#define H_     8
#define MCOLS  4096
#define LN_EPS 1e-5f

// ---------------------------------------------------------------------------
// Scratch (__device__ globals)
// ---------------------------------------------------------------------------
__device__ float g_qt[(size_t)B_SZ * H_ * D_];    // [b][h][d'] folded K-query
__device__ float g_mv[(size_t)B_SZ * H_ * NF_];   // [b][h][m]  mean |V|
__device__ float g_wqt[128 * 512];                // [e][h*64+d'] folded wq/wk

// fp16 single planes
__device__ __half g_fh[2097152];                  // feature 1024x2048
__device__ __half g_hh[1048576];                  // hidden  1024x1024
__device__ __half g_wzh[8388608];                 // wz      2048x4096
__device__ __half g_whh[4194304];                 // wh      1024x4096
__device__ __half g_wvh[32768];                   // wv      64x512
__device__ __half g_Fih[8388608];                 // Fi      [b][m][d]

__device__ __forceinline__ float gelu_exact(float x) {
    return 0.5f * x * (1.0f + erff(x * 0.70710678118654752f));
}

__device__ __forceinline__ void cp_async16(uint32_t dst, const void* src) {
    asm volatile("cp.async.cg.shared.global [%0], [%1], 16;\n"
                 :: "r"(dst), "l"(__cvta_generic_to_global(src)));
}

// ---------------------------------------------------------------------------
// convert_all: single launch for all fp32 -> fp16 conversions
// ---------------------------------------------------------------------------
#define CV_F   524288
#define CV_H   (CV_F + 262144)
#define CV_WZ  (CV_H + 2097152)
#define CV_WH  (CV_WZ + 1048576)
#define CV_END (CV_WH + 8192)

__global__ __launch_bounds__(256) void convert_all_kernel(
    const float* __restrict__ feature, const float* __restrict__ hidden,
    const float* __restrict__ wz, const float* __restrict__ wh,
    const float* __restrict__ wv)
{
    const int stride = gridDim.x * blockDim.x;
    for (int j = blockIdx.x * blockDim.x + threadIdx.x; j < CV_END; j += stride) {
        const float* src; __half* dst; int off;
        if (j < CV_F)       { src = feature; dst = g_fh;  off = j; }
        else if (j < CV_H)  { src = hidden;  dst = g_hh;  off = j - CV_F; }
        else if (j < CV_WZ) { src = wz;      dst = g_wzh; off = j - CV_H; }
        else if (j < CV_WH) { src = wh;      dst = g_whh; off = j - CV_WZ; }
        else                { src = wv;      dst = g_wvh; off = j - CV_WH; }
        float4 v = ((const float4*)src)[off];
        ((__half2*)dst)[off * 2 + 0] = __halves2half2(__float2half(v.x), __float2half(v.y));
        ((__half2*)dst)[off * 2 + 1] = __halves2half2(__float2half(v.z), __float2half(v.w));
    }
}

// ---------------------------------------------------------------------------
// wqt_kernel: Wqt[e, h*64+dp] = sum_d wq[e, h*64+d] * wk[dp, h*64+d]
// ---------------------------------------------------------------------------
__global__ __launch_bounds__(256) void wqt_kernel(
    const float* __restrict__ wq,
    const float* __restrict__ wk)
{
    const int idx = blockIdx.x * 256 + threadIdx.x;
    const int e  = idx >> 9;
    const int j  = idx & 511;
    const int h  = j >> 6;
    const int dp = j & 63;
    float s = 0.f;
    const float* wqp = wq + (size_t)e * 512 + h * 64;
    const float* wkp = wk + (size_t)dp * 512 + h * 64;
    #pragma unroll 8
    for (int d = 0; d < 64; d++)
        s = fmaf(wqp[d], wkp[d], s);
    g_wqt[e * 512 + j] = s;
}

// ---------------------------------------------------------------------------
// qt_kernel: qt = command @ Wqt
// ---------------------------------------------------------------------------
#define QT_WSTR 132
#define QT_SMEM ((32 * 128 + 128 * QT_WSTR) * 4)

__global__ __launch_bounds__(256) void qt_kernel(const float* __restrict__ command)
{
    extern __shared__ float qsm[];
    float* cmds = qsm;
    float* Wq   = qsm + 32 * 128;

    const int tid = threadIdx.x;
    const int bb  = blockIdx.x * 32;
    const int jt  = blockIdx.y * 128;

    #pragma unroll
    for (int rep = 0; rep < 4; rep++) {
        const int i = tid + rep * 256;
        const int row = i >> 5, c4 = i & 31;
        float4 v = *(const float4*)(command + (size_t)(bb + row) * 128 + c4 * 4);
        *(float4*)(cmds + row * 128 + c4 * 4) = v;
    }
    #pragma unroll
    for (int rep = 0; rep < 16; rep++) {
        const int i = tid + rep * 256;
        const int row = i >> 5, c4 = i & 31;
        float4 v = *(const float4*)(g_wqt + row * 512 + jt + c4 * 4);
        *(float4*)(Wq + row * QT_WSTR + c4 * 4) = v;
    }
    __syncthreads();

    const int r = tid >> 3;
    const int g = tid & 7;
    float acc[16];
    #pragma unroll
    for (int c = 0; c < 16; c++) acc[c] = 0.f;

    #pragma unroll 4
    for (int k = 0; k < 128; k++) {
        const float a = cmds[r * 128 + k];
        const float* wp = Wq + k * QT_WSTR + g * 16;
        #pragma unroll
        for (int c = 0; c < 16; c++)
            acc[c] = fmaf(a, wp[c], acc[c]);
    }

    float* dst = g_qt + (size_t)(bb + r) * 512 + jt + g * 16;
    #pragma unroll
    for (int c4 = 0; c4 < 4; c4++)
        *(float4*)(dst + c4 * 4) = make_float4(acc[c4 * 4], acc[c4 * 4 + 1],
                                               acc[c4 * 4 + 2], acc[c4 * 4 + 3]);
}

// ---------------------------------------------------------------------------
// wmma fp16 projection GEMM + GELU + LayerNorm (fused feature/hidden grid;
// 3-stage cp.async pipeline; epilogue writes fp16 Fi).
// ---------------------------------------------------------------------------
#define KC     32
#define A_STR  40
#define B_STR  136
#define C_STR  140
#define A_PLANE (128 * A_STR * 2)
#define B_PLANE (KC * B_STR * 2)
#define STAGE_B (A_PLANE + B_PLANE)               // 18944 B
#define NSTAGE 3
#define SMEM_GB 512
#define C_BYTES (128 * C_STR * 4)                 // 71680 B > 3*STAGE_B (56832)
#define PROJ_SMEM (SMEM_GB + C_BYTES)

__global__ __launch_bounds__(256, 2) void proj_wmma_kernel(
    const float* __restrict__ gamma,
    const float* __restrict__ beta)
{
    extern __shared__ char smem[];
    const int tid = threadIdx.x;
    const int wid = tid >> 5;

    const int sel = (blockIdx.y >= 32) ? 1 : 0;
    const __half* Ah_g = sel ? g_hh  : g_fh;
    const __half* Wh_g = sel ? g_whh : g_wzh;
    const int K        = sel ? 1024  : 2048;
    const int fbase    = sel ? 64    : 0;

    const int bm = blockIdx.x * 128;
    const int bn = (blockIdx.y & 31) * 128;

    if (tid < 64) {
        *(float*)(smem + tid * 4)       = gamma[tid];
        *(float*)(smem + 256 + tid * 4) = beta[tid];
    }

    const int warp_m = wid & 3;
    const int warp_n = wid >> 2;

    wmma::fragment<wmma::accumulator, 16, 16, 16, float> acc[2][4];
    #pragma unroll
    for (int fm = 0; fm < 2; fm++)
        #pragma unroll
        for (int fn = 0; fn < 4; fn++)
            wmma::fill_fragment(acc[fm][fn], 0.0f);

    const int nK = K / KC;

    auto load_stage = [&](int it, int buf) {
        const int kt = it * KC;
        char* stg = smem + SMEM_GB + buf * STAGE_B;
        const uint32_t stg_u = (uint32_t)__cvta_generic_to_shared(stg);
        #pragma unroll
        for (int rep = 0; rep < 2; rep++) {
            const int i = tid + rep * 256;
            const int r = i >> 2;
            const int c = i & 3;
            const __half* gp = Ah_g + (size_t)(bm + r) * K + kt + c * 8;
            cp_async16(stg_u + r * (A_STR * 2) + c * 16, gp);
        }
        #pragma unroll
        for (int rep = 0; rep < 2; rep++) {
            const int i = tid + rep * 256;
            const int kk = i >> 4;
            const int c  = i & 15;
            const __half* gp = Wh_g + (size_t)(kt + kk) * MCOLS + bn + c * 8;
            cp_async16(stg_u + A_PLANE + kk * (B_STR * 2) + c * 16, gp);
        }
        asm volatile("cp.async.commit_group;");
    };

    // prologue: fill 2 stages ahead
    load_stage(0, 0);
    if (nK > 1) load_stage(1, 1);

    for (int it = 0; it < nK; it++) {
        const int buf = it % NSTAGE;
        if (it + 2 < nK) {
            load_stage(it + 2, (it + 2) % NSTAGE);
            asm volatile("cp.async.wait_group 2;");
        } else if (it + 1 < nK) {
            asm volatile("cp.async.wait_group 1;");
        } else {
            asm volatile("cp.async.wait_group 0;");
        }
        __syncthreads();

        const char* stg = smem + SMEM_GB + buf * STAGE_B;
        const __half* As = (const __half*)(stg);
        const __half* Bs = (const __half*)(stg + A_PLANE);

        #pragma unroll
        for (int kk = 0; kk < KC; kk += 16) {
            wmma::fragment<wmma::matrix_a, 16, 16, 16, __half, wmma::row_major> af[2];
            #pragma unroll
            for (int fm = 0; fm < 2; fm++)
                wmma::load_matrix_sync(af[fm], As + (warp_m * 32 + fm * 16) * A_STR + kk, A_STR);
            #pragma unroll
            for (int fn = 0; fn < 4; fn++) {
                wmma::fragment<wmma::matrix_b, 16, 16, 16, __half, wmma::row_major> bf;
                wmma::load_matrix_sync(bf, Bs + kk * B_STR + warp_n * 64 + fn * 16, B_STR);
                #pragma unroll
                for (int fm = 0; fm < 2; fm++)
                    wmma::mma_sync(acc[fm][fn], af[fm], bf, acc[fm][fn]);
            }
        }
        __syncthreads();
    }

    // ---- Epilogue: GELU + LN, write fp16 Fi
    float* Cs = (float*)(smem + SMEM_GB);
    #pragma unroll
    for (int fm = 0; fm < 2; fm++)
        #pragma unroll
        for (int fn = 0; fn < 4; fn++)
            wmma::store_matrix_sync(Cs + (warp_m * 32 + fm * 16) * C_STR + warp_n * 64 + fn * 16,
                                    acc[fm][fn], C_STR, wmma::mem_row_major);
    __syncthreads();

    const float* gs = (const float*)(smem);
    const float* bs = (const float*)(smem + 256);
    {
        const int row = tid >> 1;
        const int grp = tid & 1;
        const float* src = Cs + row * C_STR + grp * 64;

        float v[64];
        float s = 0.f, sq = 0.f;
        #pragma unroll
        for (int c = 0; c < 64; c++) {
            float x = gelu_exact(src[c]);
            v[c] = x;
            s += x; sq += x * x;
        }
        const float mu   = s * (1.f / 64.f);
        const float var  = sq * (1.f / 64.f) - mu * mu;
        const float rstd = rsqrtf(var + LN_EPS);

        const int f = fbase + (bn >> 6) + grp;
        const size_t base = ((size_t)(bm + row) * NF_ + f) * D_;
        __half2* dh = (__half2*)(g_Fih + base);
        #pragma unroll
        for (int c4 = 0; c4 < 16; c4++) {
            float ox = (v[c4 * 4 + 0] - mu) * rstd * gs[c4 * 4 + 0] + bs[c4 * 4 + 0];
            float oy = (v[c4 * 4 + 1] - mu) * rstd * gs[c4 * 4 + 1] + bs[c4 * 4 + 1];
            float oz = (v[c4 * 4 + 2] - mu) * rstd * gs[c4 * 4 + 2] + bs[c4 * 4 + 2];
            float ow = (v[c4 * 4 + 3] - mu) * rstd * gs[c4 * 4 + 3] + bs[c4 * 4 + 3];
            dh[c4 * 2 + 0] = __halves2half2(__float2half(ox), __float2half(oy));
            dh[c4 * 2 + 1] = __halves2half2(__float2half(oz), __float2half(ow));
        }
    }
}

// ---------------------------------------------------------------------------
// mv_kernel (fp16, proven R11 shape): per b, V = Fi_b @ wv; mV = mean_d |V|.
// ---------------------------------------------------------------------------
#define MV_A_STR 72
#define MV_APL   (128 * MV_A_STR * 2)
#define MV_B_STR 136
#define MV_BPL   (64 * MV_B_STR * 2)
#define MV_C_STR 132
#define MV_SMEM  (MV_APL + 2 * MV_BPL + 128 * MV_C_STR * 4)

__global__ __launch_bounds__(256, 1) void mv_kernel()
{
    extern __shared__ char smem[];
    const int tid = threadIdx.x;
    const int wid = tid >> 5;
    const int b   = blockIdx.x;

    char* Afi = smem;
    char* Bw  = smem + MV_APL;
    float* Cs = (float*)(Bw + 2 * MV_BPL);

    const uint32_t afi_u = (uint32_t)__cvta_generic_to_shared(Afi);
    const uint32_t bw_u  = (uint32_t)__cvta_generic_to_shared(Bw);

    {
        const size_t base = (size_t)b * NF_ * D_;
        #pragma unroll
        for (int rep = 0; rep < 4; rep++) {
            const int i = tid + rep * 256;
            const int r = i >> 3;
            const int c = i & 7;
            cp_async16(afi_u + r * (MV_A_STR * 2) + c * 16, g_Fih + base + r * 64 + c * 8);
        }
    }
    auto load_b = [&](int nc, int buf) {
        #pragma unroll
        for (int rep = 0; rep < 4; rep++) {
            const int i = tid + rep * 256;
            const int kk = i >> 4;
            const int c  = i & 15;
            cp_async16(bw_u + buf * MV_BPL + kk * (MV_B_STR * 2) + c * 16,
                       g_wvh + kk * 512 + nc * 128 + c * 8);
        }
        asm volatile("cp.async.commit_group;");
    };
    load_b(0, 0);

    const int warp_m = wid & 3;
    const int warp_n = wid >> 2;

    for (int nc = 0; nc < 4; nc++) {
        const int buf = nc & 1;
        if (nc + 1 < 4) {
            load_b(nc + 1, buf ^ 1);
            asm volatile("cp.async.wait_group 1;");
        } else {
            asm volatile("cp.async.wait_group 0;");
        }
        __syncthreads();

        wmma::fragment<wmma::accumulator, 16, 16, 16, float> acc[2][4];
        #pragma unroll
        for (int fm = 0; fm < 2; fm++)
            #pragma unroll
            for (int fn = 0; fn < 4; fn++)
                wmma::fill_fragment(acc[fm][fn], 0.0f);

        const __half* As = (const __half*)Afi;
        const __half* Bs = (const __half*)(Bw + buf * MV_BPL);

        #pragma unroll
        for (int kk = 0; kk < 64; kk += 16) {
            wmma::fragment<wmma::matrix_a, 16, 16, 16, __half, wmma::row_major> af[2];
            #pragma unroll
            for (int fm = 0; fm < 2; fm++)
                wmma::load_matrix_sync(af[fm], As + (warp_m * 32 + fm * 16) * MV_A_STR + kk, MV_A_STR);
            #pragma unroll
            for (int fn = 0; fn < 4; fn++) {
                wmma::fragment<wmma::matrix_b, 16, 16, 16, __half, wmma::row_major> bf;
                wmma::load_matrix_sync(bf, Bs + kk * MV_B_STR + warp_n * 64 + fn * 16, MV_B_STR);
                #pragma unroll
                for (int fm = 0; fm < 2; fm++)
                    wmma::mma_sync(acc[fm][fn], af[fm], bf, acc[fm][fn]);
            }
        }
        #pragma unroll
        for (int fm = 0; fm < 2; fm++)
            #pragma unroll
            for (int fn = 0; fn < 4; fn++)
                wmma::store_matrix_sync(Cs + (warp_m * 32 + fm * 16) * MV_C_STR + warp_n * 64 + fn * 16,
                                        acc[fm][fn], MV_C_STR, wmma::mem_row_major);
        __syncthreads();

        {
            const int hh = tid >> 7;
            const int m  = tid & 127;
            const float* rowp = Cs + m * MV_C_STR + hh * 64;
            float s = 0.f;
            #pragma unroll 16
            for (int c = 0; c < 64; c++)
                s += fabsf(rowp[c]);
            g_mv[((size_t)b * 8 + nc * 2 + hh) * 128 + m] = s * (1.f / 64.f);
        }
        __syncthreads();
    }
}

// ---------------------------------------------------------------------------
// attn_lite (proven R11 shape, fp16 Fi source): logits, softmax, gvec, S
// ---------------------------------------------------------------------------
#define FSTR 129
#define LITE_SMEM ((64 * FSTR + 512 + 1024 + 1024 + 512) * 4)

__global__ __launch_bounds__(256, 1) void attn_lite_kernel(
    const float* __restrict__ wv,
    float* __restrict__ out)
{
    extern __shared__ float sm[];
    float* Fst  = sm;
    float* qts  = Fst + 64 * FSTR;
    float* mvs  = qts + 512;
    float* Aw   = mvs + 1024;
    float* gv   = Aw + 1024;

    const int tid = threadIdx.x;
    const int b   = blockIdx.x;

    // Load Fi (fp16) transposed into fp32 smem: thread (m, half) does 4 chunks
    {
        const __half* Fi = g_Fih + (size_t)b * NF_ * D_;
        const int m = tid & 127, half = tid >> 7;
        #pragma unroll
        for (int v = 0; v < 4; v++) {
            const int c8 = half * 4 + v;           // 8-half chunk index (0..7)
            const __half2* p = (const __half2*)(Fi + m * 64 + c8 * 8);
            #pragma unroll
            for (int e = 0; e < 4; e++) {
                float2 f = __half22float2(p[e]);
                Fst[(c8 * 8 + e * 2 + 0) * FSTR + m] = f.x;
                Fst[(c8 * 8 + e * 2 + 1) * FSTR + m] = f.y;
            }
        }
    }
    #pragma unroll
    for (int r = 0; r < 2; r++)
        qts[tid + r * 256] = g_qt[(size_t)b * 512 + tid + r * 256];
    #pragma unroll
    for (int r = 0; r < 4; r++)
        mvs[tid + r * 256] = g_mv[(size_t)b * 1024 + tid + r * 256];
    __syncthreads();

    #pragma unroll
    for (int r = 0; r < 4; r++) {
        const int idx = tid + r * 256;
        const int h = idx >> 7, m = idx & 127;
        float s = 0.f;
        #pragma unroll 8
        for (int k = 0; k < 64; k++)
            s = fmaf(Fst[k * FSTR + m], qts[h * 64 + k], s);
        Aw[idx] = mvs[idx] * s * 0.125f;
    }
    __syncthreads();

    {
        const int w = tid >> 5, lane = tid & 31;
        float v0 = Aw[w * 128 + lane];
        float v1 = Aw[w * 128 + lane + 32];
        float v2 = Aw[w * 128 + lane + 64];
        float v3 = Aw[w * 128 + lane + 96];
        float mx = fmaxf(fmaxf(v0, v1), fmaxf(v2, v3));
        #pragma unroll
        for (int off = 16; off >= 1; off >>= 1)
            mx = fmaxf(mx, __shfl_xor_sync(0xffffffffu, mx, off));
        v0 = expf(v0 - mx); v1 = expf(v1 - mx);
        v2 = expf(v2 - mx); v3 = expf(v3 - mx);
        float se = v0 + v1 + v2 + v3;
        #pragma unroll
        for (int off = 16; off >= 1; off >>= 1)
            se += __shfl_xor_sync(0xffffffffu, se, off);
        const float inv = 1.f / se;
        Aw[w * 128 + lane]      = v0 * inv;
        Aw[w * 128 + lane + 32] = v1 * inv;
        Aw[w * 128 + lane + 64] = v2 * inv;
        Aw[w * 128 + lane + 96] = v3 * inv;
    }
    __syncthreads();

    #pragma unroll
    for (int r = 0; r < 2; r++) {
        const int idx = tid + r * 256;
        const int h = idx >> 6, d = idx & 63;
        float s = 0.f;
        #pragma unroll 8
        for (int m = 0; m < 128; m++)
            s = fmaf(Aw[h * 128 + m], Fst[d * FSTR + m], s);
        gv[idx] = s;
    }
    __syncthreads();

    #pragma unroll
    for (int r = 0; r < 2; r++) {
        const int idx = tid + r * 256;
        const int h = idx >> 6, d = idx & 63;
        float s = 0.f;
        #pragma unroll 8
        for (int k = 0; k < 64; k++)
            s = fmaf(gv[h * 64 + k], wv[(size_t)k * 512 + h * 64 + d], s);
        out[(size_t)b * 512 + idx] = s;
    }
}

// ---------------------------------------------------------------------------
// Launch
// ---------------------------------------------------------------------------
extern "C" void kernel_launch(void* const* d_in, const int* in_sizes, int n_in,
                              void* d_out, int out_size)
{
    const float* feature  = (const float*)d_in[0];
    const float* hidden   = (const float*)d_in[1];
    const float* command  = (const float*)d_in[2];
    const float* wz       = (const float*)d_in[3];
    const float* wh       = (const float*)d_in[4];
    const float* wq       = (const float*)d_in[5];
    const float* wk       = (const float*)d_in[6];
    const float* wv       = (const float*)d_in[7];
    const float* ln_gamma = (const float*)d_in[8];
    const float* ln_beta  = (const float*)d_in[9];
    float* out = (float*)d_out;

    cudaFuncSetAttribute(proj_wmma_kernel, cudaFuncAttributeMaxDynamicSharedMemorySize, PROJ_SMEM);
    cudaFuncSetAttribute(mv_kernel, cudaFuncAttributeMaxDynamicSharedMemorySize, MV_SMEM);
    cudaFuncSetAttribute(attn_lite_kernel, cudaFuncAttributeMaxDynamicSharedMemorySize, LITE_SMEM);
    cudaFuncSetAttribute(qt_kernel, cudaFuncAttributeMaxDynamicSharedMemorySize, QT_SMEM);

    convert_all_kernel<<<2048, 256>>>(feature, hidden, wz, wh, wv);

    wqt_kernel<<<256, 256>>>(wq, wk);
    qt_kernel<<<dim3(32, 4), 256, QT_SMEM>>>(command);

    // fused projections: y 0-31 = feature@wz, y 32-63 = hidden@wh
    proj_wmma_kernel<<<dim3(8, 64), 256, PROJ_SMEM>>>(ln_gamma, ln_beta);

    mv_kernel<<<B_SZ, 256, MV_SMEM>>>();
    attn_lite_kernel<<<B_SZ, 256, LITE_SMEM>>>(wv, out);
}

// round 14
// speedup vs baseline: 4.2977x; 1.0838x over previous
#include <cuda_runtime.h>
#include <cuda_fp16.h>
#include <mma.h>
#include <cstdint>
#include <stdint.h>
#include <math.h>

using namespace nvcuda;

// Problem constants
#define B_SZ   1024
#define NF_    128
#define D_     64
#define H_     8
#define MCOLS  4096
#define LN_EPS 1e-5f

// ---------------------------------------------------------------------------
// Scratch (__device__ globals)
// ---------------------------------------------------------------------------
__device__ float g_qt[(size_t)B_SZ * H_ * D_];    // [b][h][d'] folded K-query
__device__ float g_mv[(size_t)B_SZ * H_ * NF_];   // [b][h][m]  mean |V|
__device__ float g_wqt[128 * 512];                // [e][h*64+d'] folded wq/wk

// fp16 single planes
__device__ __half g_fh[2097152];                  // feature 1024x2048
__device__ __half g_hh[1048576];                  // hidden  1024x1024
__device__ __half g_wzh[8388608];                 // wz      2048x4096
__device__ __half g_whh[4194304];                 // wh      1024x4096
__device__ __half g_wvh[32768];                   // wv      64x512
__device__ __half g_Fih[8388608];                 // Fi      [b][m][d]

__device__ __forceinline__ float gelu_exact(float x) {
    return 0.5f * x * (1.0f + erff(x * 0.70710678118654752f));
}

__device__ __forceinline__ void cp_async16(uint32_t dst, const void* src) {
    asm volatile("cp.async.cg.shared.global [%0], [%1], 16;\n"
                 :: "r"(dst), "l"(__cvta_generic_to_global(src)));
}

// ---------------------------------------------------------------------------
// convert_all: single launch for all fp32 -> fp16 conversions
// ---------------------------------------------------------------------------
#define CV_F   524288
#define CV_H   (CV_F + 262144)
#define CV_WZ  (CV_H + 2097152)
#define CV_WH  (CV_WZ + 1048576)
#define CV_END (CV_WH + 8192)

__global__ __launch_bounds__(256) void convert_all_kernel(
    const float* __restrict__ feature, const float* __restrict__ hidden,
    const float* __restrict__ wz, const float* __restrict__ wh,
    const float* __restrict__ wv)
{
    const int stride = gridDim.x * blockDim.x;
    for (int j = blockIdx.x * blockDim.x + threadIdx.x; j < CV_END; j += stride) {
        const float* src; __half* dst; int off;
        if (j < CV_F)       { src = feature; dst = g_fh;  off = j; }
        else if (j < CV_H)  { src = hidden;  dst = g_hh;  off = j - CV_F; }
        else if (j < CV_WZ) { src = wz;      dst = g_wzh; off = j - CV_H; }
        else if (j < CV_WH) { src = wh;      dst = g_whh; off = j - CV_WZ; }
        else                { src = wv;      dst = g_wvh; off = j - CV_WH; }
        float4 v = ((const float4*)src)[off];
        ((__half2*)dst)[off * 2 + 0] = __halves2half2(__float2half(v.x), __float2half(v.y));
        ((__half2*)dst)[off * 2 + 1] = __halves2half2(__float2half(v.z), __float2half(v.w));
    }
}

// ---------------------------------------------------------------------------
// wqt_kernel: Wqt[e, h*64+dp] = sum_d wq[e, h*64+d] * wk[dp, h*64+d]
// ---------------------------------------------------------------------------
__global__ __launch_bounds__(256) void wqt_kernel(
    const float* __restrict__ wq,
    const float* __restrict__ wk)
{
    const int idx = blockIdx.x * 256 + threadIdx.x;
    const int e  = idx >> 9;
    const int j  = idx & 511;
    const int h  = j >> 6;
    const int dp = j & 63;
    float s = 0.f;
    const float* wqp = wq + (size_t)e * 512 + h * 64;
    const float* wkp = wk + (size_t)dp * 512 + h * 64;
    #pragma unroll 8
    for (int d = 0; d < 64; d++)
        s = fmaf(wqp[d], wkp[d], s);
    g_wqt[e * 512 + j] = s;
}

// ---------------------------------------------------------------------------
// qt_kernel: qt = command @ Wqt
// ---------------------------------------------------------------------------
#define QT_WSTR 132
#define QT_SMEM ((32 * 128 + 128 * QT_WSTR) * 4)

__global__ __launch_bounds__(256) void qt_kernel(const float* __restrict__ command)
{
    extern __shared__ float qsm[];
    float* cmds = qsm;
    float* Wq   = qsm + 32 * 128;

    const int tid = threadIdx.x;
    const int bb  = blockIdx.x * 32;
    const int jt  = blockIdx.y * 128;

    #pragma unroll
    for (int rep = 0; rep < 4; rep++) {
        const int i = tid + rep * 256;
        const int row = i >> 5, c4 = i & 31;
        float4 v = *(const float4*)(command + (size_t)(bb + row) * 128 + c4 * 4);
        *(float4*)(cmds + row * 128 + c4 * 4) = v;
    }
    #pragma unroll
    for (int rep = 0; rep < 16; rep++) {
        const int i = tid + rep * 256;
        const int row = i >> 5, c4 = i & 31;
        float4 v = *(const float4*)(g_wqt + row * 512 + jt + c4 * 4);
        *(float4*)(Wq + row * QT_WSTR + c4 * 4) = v;
    }
    __syncthreads();

    const int r = tid >> 3;
    const int g = tid & 7;
    float acc[16];
    #pragma unroll
    for (int c = 0; c < 16; c++) acc[c] = 0.f;

    #pragma unroll 4
    for (int k = 0; k < 128; k++) {
        const float a = cmds[r * 128 + k];
        const float* wp = Wq + k * QT_WSTR + g * 16;
        #pragma unroll
        for (int c = 0; c < 16; c++)
            acc[c] = fmaf(a, wp[c], acc[c]);
    }

    float* dst = g_qt + (size_t)(bb + r) * 512 + jt + g * 16;
    #pragma unroll
    for (int c4 = 0; c4 < 4; c4++)
        *(float4*)(dst + c4 * 4) = make_float4(acc[c4 * 4], acc[c4 * 4 + 1],
                                               acc[c4 * 4 + 2], acc[c4 * 4 + 3]);
}

// ---------------------------------------------------------------------------
// wmma fp16 projection GEMM + GELU + LayerNorm
//   128 threads, 4 warps (2m x 2n), warp tile 64x64 (acc 4x4 frags):
//   per k-step 8 fragment loads -> 16 MMAs (ratio 2.0 vs 1.33 before).
//   3-stage cp.async pipeline; fused feature/hidden grid; fp16 Fi epilogue.
// ---------------------------------------------------------------------------
#define KC     32
#define A_STR  40
#define B_STR  136
#define C_STR  140
#define A_PLANE (128 * A_STR * 2)
#define B_PLANE (KC * B_STR * 2)
#define STAGE_B (A_PLANE + B_PLANE)               // 18944 B
#define NSTAGE 3
#define SMEM_GB 512
#define C_BYTES (128 * C_STR * 4)                 // 71680 B > 3*STAGE_B (56832)
#define PROJ_SMEM (SMEM_GB + C_BYTES)

__global__ __launch_bounds__(128, 2) void proj_wmma_kernel(
    const float* __restrict__ gamma,
    const float* __restrict__ beta)
{
    extern __shared__ char smem[];
    const int tid = threadIdx.x;
    const int wid = tid >> 5;

    const int sel = (blockIdx.y >= 32) ? 1 : 0;
    const __half* Ah_g = sel ? g_hh  : g_fh;
    const __half* Wh_g = sel ? g_whh : g_wzh;
    const int K        = sel ? 1024  : 2048;
    const int fbase    = sel ? 64    : 0;

    const int bm = blockIdx.x * 128;
    const int bn = (blockIdx.y & 31) * 128;

    if (tid < 64) {
        *(float*)(smem + tid * 4)       = gamma[tid];
        *(float*)(smem + 256 + tid * 4) = beta[tid];
    }

    const int warp_m = wid & 1;     // 0..1 -> 64-row slab
    const int warp_n = wid >> 1;    // 0..1 -> 64-col slab

    wmma::fragment<wmma::accumulator, 16, 16, 16, float> acc[4][4];
    #pragma unroll
    for (int fm = 0; fm < 4; fm++)
        #pragma unroll
        for (int fn = 0; fn < 4; fn++)
            wmma::fill_fragment(acc[fm][fn], 0.0f);

    const int nK = K / KC;

    auto load_stage = [&](int it, int buf) {
        const int kt = it * KC;
        char* stg = smem + SMEM_GB + buf * STAGE_B;
        const uint32_t stg_u = (uint32_t)__cvta_generic_to_shared(stg);
        // A: 128 rows x 4 chunks(16B) = 512; 4/thread (128 threads)
        #pragma unroll
        for (int rep = 0; rep < 4; rep++) {
            const int i = tid + rep * 128;
            const int r = i >> 2;
            const int c = i & 3;
            const __half* gp = Ah_g + (size_t)(bm + r) * K + kt + c * 8;
            cp_async16(stg_u + r * (A_STR * 2) + c * 16, gp);
        }
        // B: 32 k-rows x 16 chunks = 512; 4/thread
        #pragma unroll
        for (int rep = 0; rep < 4; rep++) {
            const int i = tid + rep * 128;
            const int kk = i >> 4;
            const int c  = i & 15;
            const __half* gp = Wh_g + (size_t)(kt + kk) * MCOLS + bn + c * 8;
            cp_async16(stg_u + A_PLANE + kk * (B_STR * 2) + c * 16, gp);
        }
        asm volatile("cp.async.commit_group;");
    };

    // prologue: fill 2 stages ahead
    load_stage(0, 0);
    if (nK > 1) load_stage(1, 1);

    for (int it = 0; it < nK; it++) {
        const int buf = it % NSTAGE;
        if (it + 2 < nK) {
            load_stage(it + 2, (it + 2) % NSTAGE);
            asm volatile("cp.async.wait_group 2;");
        } else if (it + 1 < nK) {
            asm volatile("cp.async.wait_group 1;");
        } else {
            asm volatile("cp.async.wait_group 0;");
        }
        __syncthreads();

        const char* stg = smem + SMEM_GB + buf * STAGE_B;
        const __half* As = (const __half*)(stg);
        const __half* Bs = (const __half*)(stg + A_PLANE);

        #pragma unroll
        for (int kk = 0; kk < KC; kk += 16) {
            wmma::fragment<wmma::matrix_a, 16, 16, 16, __half, wmma::row_major> af[4];
            #pragma unroll
            for (int fm = 0; fm < 4; fm++)
                wmma::load_matrix_sync(af[fm], As + (warp_m * 64 + fm * 16) * A_STR + kk, A_STR);
            #pragma unroll
            for (int fn = 0; fn < 4; fn++) {
                wmma::fragment<wmma::matrix_b, 16, 16, 16, __half, wmma::row_major> bf;
                wmma::load_matrix_sync(bf, Bs + kk * B_STR + warp_n * 64 + fn * 16, B_STR);
                #pragma unroll
                for (int fm = 0; fm < 4; fm++)
                    wmma::mma_sync(acc[fm][fn], af[fm], bf, acc[fm][fn]);
            }
        }
        __syncthreads();
    }

    // ---- Epilogue: GELU + LN, write fp16 Fi
    float* Cs = (float*)(smem + SMEM_GB);
    #pragma unroll
    for (int fm = 0; fm < 4; fm++)
        #pragma unroll
        for (int fn = 0; fn < 4; fn++)
            wmma::store_matrix_sync(Cs + (warp_m * 64 + fm * 16) * C_STR + warp_n * 64 + fn * 16,
                                    acc[fm][fn], C_STR, wmma::mem_row_major);
    __syncthreads();

    const float* gs = (const float*)(smem);
    const float* bs = (const float*)(smem + 256);
    #pragma unroll
    for (int r = 0; r < 2; r++) {
        const int item = tid + r * 128;        // 0..255
        const int row = item >> 1;
        const int grp = item & 1;
        const float* src = Cs + row * C_STR + grp * 64;

        float v[64];
        float s = 0.f, sq = 0.f;
        #pragma unroll
        for (int c = 0; c < 64; c++) {
            float x = gelu_exact(src[c]);
            v[c] = x;
            s += x; sq += x * x;
        }
        const float mu   = s * (1.f / 64.f);
        const float var  = sq * (1.f / 64.f) - mu * mu;
        const float rstd = rsqrtf(var + LN_EPS);

        const int f = fbase + (bn >> 6) + grp;
        const size_t base = ((size_t)(bm + row) * NF_ + f) * D_;
        __half2* dh = (__half2*)(g_Fih + base);
        #pragma unroll
        for (int c4 = 0; c4 < 16; c4++) {
            float ox = (v[c4 * 4 + 0] - mu) * rstd * gs[c4 * 4 + 0] + bs[c4 * 4 + 0];
            float oy = (v[c4 * 4 + 1] - mu) * rstd * gs[c4 * 4 + 1] + bs[c4 * 4 + 1];
            float oz = (v[c4 * 4 + 2] - mu) * rstd * gs[c4 * 4 + 2] + bs[c4 * 4 + 2];
            float ow = (v[c4 * 4 + 3] - mu) * rstd * gs[c4 * 4 + 3] + bs[c4 * 4 + 3];
            dh[c4 * 2 + 0] = __halves2half2(__float2half(ox), __float2half(oy));
            dh[c4 * 2 + 1] = __halves2half2(__float2half(oz), __float2half(ow));
        }
    }
}

// ---------------------------------------------------------------------------
// mv_kernel (fp16, proven shape): per b, V = Fi_b @ wv; mV = mean_d |V|.
// ---------------------------------------------------------------------------
#define MV_A_STR 72
#define MV_APL   (128 * MV_A_STR * 2)
#define MV_B_STR 136
#define MV_BPL   (64 * MV_B_STR * 2)
#define MV_C_STR 132
#define MV_SMEM  (MV_APL + 2 * MV_BPL + 128 * MV_C_STR * 4)

__global__ __launch_bounds__(256, 1) void mv_kernel()
{
    extern __shared__ char smem[];
    const int tid = threadIdx.x;
    const int wid = tid >> 5;
    const int b   = blockIdx.x;

    char* Afi = smem;
    char* Bw  = smem + MV_APL;
    float* Cs = (float*)(Bw + 2 * MV_BPL);

    const uint32_t afi_u = (uint32_t)__cvta_generic_to_shared(Afi);
    const uint32_t bw_u  = (uint32_t)__cvta_generic_to_shared(Bw);

    {
        const size_t base = (size_t)b * NF_ * D_;
        #pragma unroll
        for (int rep = 0; rep < 4; rep++) {
            const int i = tid + rep * 256;
            const int r = i >> 3;
            const int c = i & 7;
            cp_async16(afi_u + r * (MV_A_STR * 2) + c * 16, g_Fih + base + r * 64 + c * 8);
        }
    }
    auto load_b = [&](int nc, int buf) {
        #pragma unroll
        for (int rep = 0; rep < 4; rep++) {
            const int i = tid + rep * 256;
            const int kk = i >> 4;
            const int c  = i & 15;
            cp_async16(bw_u + buf * MV_BPL + kk * (MV_B_STR * 2) + c * 16,
                       g_wvh + kk * 512 + nc * 128 + c * 8);
        }
        asm volatile("cp.async.commit_group;");
    };
    load_b(0, 0);

    const int warp_m = wid & 3;
    const int warp_n = wid >> 2;

    for (int nc = 0; nc < 4; nc++) {
        const int buf = nc & 1;
        if (nc + 1 < 4) {
            load_b(nc + 1, buf ^ 1);
            asm volatile("cp.async.wait_group 1;");
        } else {
            asm volatile("cp.async.wait_group 0;");
        }
        __syncthreads();

        wmma::fragment<wmma::accumulator, 16, 16, 16, float> acc[2][4];
        #pragma unroll
        for (int fm = 0; fm < 2; fm++)
            #pragma unroll
            for (int fn = 0; fn < 4; fn++)
                wmma::fill_fragment(acc[fm][fn], 0.0f);

        const __half* As = (const __half*)Afi;
        const __half* Bs = (const __half*)(Bw + buf * MV_BPL);

        #pragma unroll
        for (int kk = 0; kk < 64; kk += 16) {
            wmma::fragment<wmma::matrix_a, 16, 16, 16, __half, wmma::row_major> af[2];
            #pragma unroll
            for (int fm = 0; fm < 2; fm++)
                wmma::load_matrix_sync(af[fm], As + (warp_m * 32 + fm * 16) * MV_A_STR + kk, MV_A_STR);
            #pragma unroll
            for (int fn = 0; fn < 4; fn++) {
                wmma::fragment<wmma::matrix_b, 16, 16, 16, __half, wmma::row_major> bf;
                wmma::load_matrix_sync(bf, Bs + kk * MV_B_STR + warp_n * 64 + fn * 16, MV_B_STR);
                #pragma unroll
                for (int fm = 0; fm < 2; fm++)
                    wmma::mma_sync(acc[fm][fn], af[fm], bf, acc[fm][fn]);
            }
        }
        #pragma unroll
        for (int fm = 0; fm < 2; fm++)
            #pragma unroll
            for (int fn = 0; fn < 4; fn++)
                wmma::store_matrix_sync(Cs + (warp_m * 32 + fm * 16) * MV_C_STR + warp_n * 64 + fn * 16,
                                        acc[fm][fn], MV_C_STR, wmma::mem_row_major);
        __syncthreads();

        {
            const int hh = tid >> 7;
            const int m  = tid & 127;
            const float* rowp = Cs + m * MV_C_STR + hh * 64;
            float s = 0.f;
            #pragma unroll 16
            for (int c = 0; c < 64; c++)
                s += fabsf(rowp[c]);
            g_mv[((size_t)b * 8 + nc * 2 + hh) * 128 + m] = s * (1.f / 64.f);
        }
        __syncthreads();
    }
}

// ---------------------------------------------------------------------------
// attn_lite (proven shape, fp16 Fi source): logits, softmax, gvec, S
// ---------------------------------------------------------------------------
#define FSTR 129
#define LITE_SMEM ((64 * FSTR + 512 + 1024 + 1024 + 512) * 4)

__global__ __launch_bounds__(256, 1) void attn_lite_kernel(
    const float* __restrict__ wv,
    float* __restrict__ out)
{
    extern __shared__ float sm[];
    float* Fst  = sm;
    float* qts  = Fst + 64 * FSTR;
    float* mvs  = qts + 512;
    float* Aw   = mvs + 1024;
    float* gv   = Aw + 1024;

    const int tid = threadIdx.x;
    const int b   = blockIdx.x;

    {
        const __half* Fi = g_Fih + (size_t)b * NF_ * D_;
        const int m = tid & 127, half = tid >> 7;
        #pragma unroll
        for (int v = 0; v < 4; v++) {
            const int c8 = half * 4 + v;
            const __half2* p = (const __half2*)(Fi + m * 64 + c8 * 8);
            #pragma unroll
            for (int e = 0; e < 4; e++) {
                float2 f = __half22float2(p[e]);
                Fst[(c8 * 8 + e * 2 + 0) * FSTR + m] = f.x;
                Fst[(c8 * 8 + e * 2 + 1) * FSTR + m] = f.y;
            }
        }
    }
    #pragma unroll
    for (int r = 0; r < 2; r++)
        qts[tid + r * 256] = g_qt[(size_t)b * 512 + tid + r * 256];
    #pragma unroll
    for (int r = 0; r < 4; r++)
        mvs[tid + r * 256] = g_mv[(size_t)b * 1024 + tid + r * 256];
    __syncthreads();

    #pragma unroll
    for (int r = 0; r < 4; r++) {
        const int idx = tid + r * 256;
        const int h = idx >> 7, m = idx & 127;
        float s = 0.f;
        #pragma unroll 8
        for (int k = 0; k < 64; k++)
            s = fmaf(Fst[k * FSTR + m], qts[h * 64 + k], s);
        Aw[idx] = mvs[idx] * s * 0.125f;
    }
    __syncthreads();

    {
        const int w = tid >> 5, lane = tid & 31;
        float v0 = Aw[w * 128 + lane];
        float v1 = Aw[w * 128 + lane + 32];
        float v2 = Aw[w * 128 + lane + 64];
        float v3 = Aw[w * 128 + lane + 96];
        float mx = fmaxf(fmaxf(v0, v1), fmaxf(v2, v3));
        #pragma unroll
        for (int off = 16; off >= 1; off >>= 1)
            mx = fmaxf(mx, __shfl_xor_sync(0xffffffffu, mx, off));
        v0 = expf(v0 - mx); v1 = expf(v1 - mx);
        v2 = expf(v2 - mx); v3 = expf(v3 - mx);
        float se = v0 + v1 + v2 + v3;
        #pragma unroll
        for (int off = 16; off >= 1; off >>= 1)
            se += __shfl_xor_sync(0xffffffffu, se, off);
        const float inv = 1.f / se;
        Aw[w * 128 + lane]      = v0 * inv;
        Aw[w * 128 + lane + 32] = v1 * inv;
        Aw[w * 128 + lane + 64] = v2 * inv;
        Aw[w * 128 + lane + 96] = v3 * inv;
    }
    __syncthreads();

    #pragma unroll
    for (int r = 0; r < 2; r++) {
        const int idx = tid + r * 256;
        const int h = idx >> 6, d = idx & 63;
        float s = 0.f;
        #pragma unroll 8
        for (int m = 0; m < 128; m++)
            s = fmaf(Aw[h * 128 + m], Fst[d * FSTR + m], s);
        gv[idx] = s;
    }
    __syncthreads();

    #pragma unroll
    for (int r = 0; r < 2; r++) {
        const int idx = tid + r * 256;
        const int h = idx >> 6, d = idx & 63;
        float s = 0.f;
        #pragma unroll 8
        for (int k = 0; k < 64; k++)
            s = fmaf(gv[h * 64 + k], wv[(size_t)k * 512 + h * 64 + d], s);
        out[(size_t)b * 512 + idx] = s;
    }
}

// ---------------------------------------------------------------------------
// Launch
// ---------------------------------------------------------------------------
extern "C" void kernel_launch(void* const* d_in, const int* in_sizes, int n_in,
                              void* d_out, int out_size)
{
    const float* feature  = (const float*)d_in[0];
    const float* hidden   = (const float*)d_in[1];
    const float* command  = (const float*)d_in[2];
    const float* wz       = (const float*)d_in[3];
    const float* wh       = (const float*)d_in[4];
    const float* wq       = (const float*)d_in[5];
    const float* wk       = (const float*)d_in[6];
    const float* wv       = (const float*)d_in[7];
    const float* ln_gamma = (const float*)d_in[8];
    const float* ln_beta  = (const float*)d_in[9];
    float* out = (float*)d_out;

    cudaFuncSetAttribute(proj_wmma_kernel, cudaFuncAttributeMaxDynamicSharedMemorySize, PROJ_SMEM);
    cudaFuncSetAttribute(mv_kernel, cudaFuncAttributeMaxDynamicSharedMemorySize, MV_SMEM);
    cudaFuncSetAttribute(attn_lite_kernel, cudaFuncAttributeMaxDynamicSharedMemorySize, LITE_SMEM);
    cudaFuncSetAttribute(qt_kernel, cudaFuncAttributeMaxDynamicSharedMemorySize, QT_SMEM);

    convert_all_kernel<<<2048, 256>>>(feature, hidden, wz, wh, wv);

    wqt_kernel<<<256, 256>>>(wq, wk);
    qt_kernel<<<dim3(32, 4), 256, QT_SMEM>>>(command);

    // fused projections: y 0-31 = feature@wz, y 32-63 = hidden@wh
    proj_wmma_kernel<<<dim3(8, 64), 128, PROJ_SMEM>>>(ln_gamma, ln_beta);

    mv_kernel<<<B_SZ, 256, MV_SMEM>>>();
    attn_lite_kernel<<<B_SZ, 256, LITE_SMEM>>>(wv, out);
}